// round 9
// baseline (speedup 1.0000x reference)
#include <cuda_runtime.h>
#include <cuda_bf16.h>
#include <math.h>

// Problem constants: B=32, N=128, D=256, H=8, DK=32
typedef unsigned int u32;
typedef __nv_bfloat16 bf16;

// ---------------- scratch (static device globals; no allocation) -------------
__device__ __align__(16) float g_fA[1024 * 256];
__device__ __align__(16) float g_fB[1024 * 256];
__device__ __align__(16) float g_conn[8 * 128 * 128];
__device__ __align__(16) float g_cb[3 * 256];            // composed QKV biases
__device__ __align__(16) bf16 g_wphi[8 * 65536];         // fcA,fcB,w1,ow,w2,wq,wk,wv
__device__ __align__(16) bf16 g_wplo[8 * 65536];
__device__ __align__(16) bf16 g_cwhi[3 * 65536];         // composed W2@W{q,k,v}
__device__ __align__(16) bf16 g_cwlo[3 * 65536];
__device__ __align__(16) bf16 g_fthi[1024 * 256];        // feats planes
__device__ __align__(16) bf16 g_ftlo[1024 * 256];
__device__ __align__(16) bf16 g_xhi[4096 * 256];         // x planes
__device__ __align__(16) bf16 g_xlo[4096 * 256];
__device__ __align__(16) bf16 g_h1hi[4096 * 256];
__device__ __align__(16) bf16 g_h1lo[4096 * 256];
__device__ __align__(16) bf16 g_qkvhi[3 * 1048576];      // [op][B,H,N,DK] planes
__device__ __align__(16) bf16 g_qkvlo[3 * 1048576];
__device__ __align__(16) bf16 g_aohi[4096 * 256];
__device__ __align__(16) bf16 g_aolo[4096 * 256];

__device__ __forceinline__ float gelu_tanh(float x) {
    float x3 = x * x * x;
    float t = tanhf(0.7978845608028654f * (x + 0.044715f * x3));
    return 0.5f * x * (1.0f + t);
}

__device__ __forceinline__ void split_bf16(float v, bf16& h, bf16& l) {
    h = __float2bfloat16_rn(v);
    l = __float2bfloat16_rn(v - __bfloat162float(h));
}

__device__ __forceinline__ void cvt4(float4 v, uint2& hi, uint2& lo) {
    bf16 h0, l0, h1, l1, h2, l2, h3, l3;
    split_bf16(v.x, h0, l0); split_bf16(v.y, h1, l1);
    split_bf16(v.z, h2, l2); split_bf16(v.w, h3, l3);
    __nv_bfloat162 a, b, c, d;
    a.x = h0; a.y = h1; b.x = h2; b.y = h3;
    c.x = l0; c.y = l1; d.x = l2; d.y = l3;
    hi.x = *(u32*)&a; hi.y = *(u32*)&b;
    lo.x = *(u32*)&c; lo.y = *(u32*)&d;
}

__device__ __forceinline__ void packP(float x, float y, u32& hi, u32& lo) {
    bf16 hx, lx, hy, ly;
    split_bf16(x, hx, lx);
    split_bf16(y, hy, ly);
    __nv_bfloat162 H; H.x = hx; H.y = hy;
    __nv_bfloat162 L; L.x = lx; L.y = ly;
    hi = *(u32*)&H; lo = *(u32*)&L;
}

#define LDSM4(r, addr)                                                        \
    asm volatile("ldmatrix.sync.aligned.m8n8.x4.shared.b16 {%0,%1,%2,%3}, [%4];" \
                 : "=r"(r[0]), "=r"(r[1]), "=r"(r[2]), "=r"(r[3]) : "r"(addr))

#define LDSM4T(r, addr)                                                       \
    asm volatile("ldmatrix.sync.aligned.m8n8.x4.trans.shared.b16 {%0,%1,%2,%3}, [%4];" \
                 : "=r"(r[0]), "=r"(r[1]), "=r"(r[2]), "=r"(r[3]) : "r"(addr))

#define MMA16816(d, a, b)                                                     \
    asm volatile("mma.sync.aligned.m16n8k16.row.col.f32.bf16.bf16.f32 "       \
                 "{%0,%1,%2,%3}, {%4,%5,%6,%7}, {%8,%9}, {%0,%1,%2,%3};"      \
                 : "+f"(d[0]), "+f"(d[1]), "+f"(d[2]), "+f"(d[3])             \
                 : "r"(a[0]), "r"(a[1]), "r"(a[2]), "r"(a[3]),                \
                   "r"(b[0]), "r"(b[1]))

// ---------------- L0: convert weights / feats / x to bf16 hi/lo planes -------
struct CvtParams {
    const float* src[8];
    const float* mw;
    const float* x;
};

__global__ void __launch_bounds__(256)
k_cvt(CvtParams P)
{
    int bid = blockIdx.x, t = threadIdx.x;
    const float* s;
    bf16 *hi, *lo;
    if (bid < 256) {
        int task = bid >> 5;
        int base = (bid & 31) * 2048 + t * 8;
        s = P.src[task] + base;
        hi = g_wphi + task * 65536 + base;
        lo = g_wplo + task * 65536 + base;
    } else if (bid < 384) {
        int e = (bid - 256) * 2048 + t * 8;
        int row = e >> 8, d = e & 255;
        int h = row >> 7, n = row & 127;
        s = P.mw + n * 2048 + h * 256 + d;
        hi = g_fthi + e; lo = g_ftlo + e;
    } else {
        int e = (bid - 384) * 2048 + t * 8;
        s = P.x + e;
        hi = g_xhi + e; lo = g_xlo + e;
    }
    float4 a = *(const float4*)s;
    float4 b = *(const float4*)(s + 4);
    uint2 h0, l0, h1, l1;
    cvt4(a, h0, l0); cvt4(b, h1, l1);
    *(uint2*)hi = h0; *(uint2*)(hi + 4) = h1;
    *(uint2*)lo = l0; *(uint2*)(lo + 4) = l1;
}

// ---------------- multi-job GEMM-32: BM=32, BN=64, BK=32 ---------------------
struct Job6 {
    const bf16 *Ahi[6], *Alo[6], *Whi[6], *Wlo[6];
    const float* bias[6];
    float* Cf[6];
    bf16 *Chi[6], *Clo[6];
    float scale[6];
    int act[6];
    int storeMode[6];  // 0 fp32, 1 bf16 planes row*256+col, 2 QKV per-head planes
    int end[6];        // cumulative tile counts
    int totTiles, nconn;
};

struct ConnArgs {
    const float *fcb, *fccw, *fccb, *gu;
    const float *b2, *wq, *wk, *wv, *bq, *bk, *bv;
};

__device__ void connJob(int cid, ConnArgs CA, char* smemRaw);

__device__ void biasJob(int z, ConnArgs CA) {
    int c = threadIdx.x;
    const float* wz = (z == 0) ? CA.wq : (z == 1) ? CA.wk : CA.wv;
    const float* bz = (z == 0) ? CA.bq : (z == 1) ? CA.bk : CA.bv;
    float acc = bz[c];
    for (int d = 0; d < 256; d++)
        acc = fmaf(CA.b2[d], wz[d * 256 + c], acc);
    g_cb[z * 256 + c] = acc;
}

__global__ void __launch_bounds__(256)
k_gemm32(Job6 J, ConnArgs CA)
{
    __shared__ __align__(16) char smemRaw[28672];

    int jid = blockIdx.x;
    if (jid >= J.totTiles) {
        int e = jid - J.totTiles;
        if (e < J.nconn) connJob(e, CA, smemRaw);
        else biasJob(e - J.nconn, CA);
        return;
    }
    int ji = 0;
    #pragma unroll
    for (int k = 0; k < 5; k++) if (jid >= J.end[k]) ji = k + 1;
    int tile = jid - (ji ? J.end[ji - 1] : 0);

    const bf16 *Ahi = J.Ahi[ji], *Alo = J.Alo[ji];
    const bf16 *Whi = J.Whi[ji], *Wlo = J.Wlo[ji];

    bf16* sAhi = (bf16*)smemRaw;            // [2][32*40]
    bf16* sAlo = sAhi + 2 * 1280;
    bf16* sWhi = sAlo + 2 * 1280;           // [2][32*72]
    bf16* sWlo = sWhi + 2 * 2304;

    int rowBase = (tile >> 2) * 32;
    int colBase = (tile & 3) * 64;

    int t = threadIdx.x;
    int warp = t >> 5, lane = t & 31;
    int wm = warp >> 2, wn = warp & 3;
    int g = lane >> 3, r = lane & 7;

    u32 sAhiB = (u32)__cvta_generic_to_shared(sAhi);
    u32 sAloB = (u32)__cvta_generic_to_shared(sAlo);
    u32 sWhiB = (u32)__cvta_generic_to_shared(sWhi);
    u32 sWloB = (u32)__cvta_generic_to_shared(sWlo);

    int pl = t >> 7, ps = t & 127;
    int prow = ps >> 2, pseg = ps & 3;   // A: 32 rows x 4 uint4
    int wr = ps >> 3, wsg = ps & 7;      // W: rows wr, wr+16

    uint4 pa, pw0, pw1;

    auto loadTile = [&](int kt) {
        const bf16* asrc = pl ? Alo : Ahi;
        pa = *(const uint4*)&asrc[(rowBase + prow) * 256 + kt + pseg * 8];
        const bf16* wsrc = pl ? Wlo : Whi;
        pw0 = *(const uint4*)&wsrc[(kt + wr) * 256 + colBase + wsg * 8];
        pw1 = *(const uint4*)&wsrc[(kt + wr + 16) * 256 + colBase + wsg * 8];
    };

    auto storeTile = [&](int bb) {
        bf16* ad = pl ? sAlo : sAhi;
        *(uint4*)&ad[bb * 1280 + prow * 40 + pseg * 8] = pa;
        bf16* wd = pl ? sWlo : sWhi;
        *(uint4*)&wd[bb * 2304 + wr * 72 + wsg * 8] = pw0;
        *(uint4*)&wd[bb * 2304 + (wr + 16) * 72 + wsg * 8] = pw1;
    };

    float acc[2][4];
    #pragma unroll
    for (int nt = 0; nt < 2; nt++)
        #pragma unroll
        for (int i = 0; i < 4; i++) acc[nt][i] = 0.0f;

    loadTile(0);
    storeTile(0);
    __syncthreads();

    #pragma unroll
    for (int it = 0; it < 8; it++) {
        int bb = it & 1;
        if (it < 7) loadTile((it + 1) * 32);

        #pragma unroll
        for (int ks = 0; ks < 32; ks += 16) {
            u32 ah[4], al[4], bh[4], bl[4];
            {
                int rowA = wm * 16 + r + ((g & 1) << 3);
                int kcol = ks + ((g >> 1) << 3);
                u32 off = (u32)(bb * 1280 + rowA * 40 + kcol) * 2;
                LDSM4(ah, sAhiB + off);
                LDSM4(al, sAloB + off);
            }
            {
                int krow = ks + r + ((g & 1) << 3);
                int ncol = wn * 16 + ((g >> 1) << 3);
                u32 off = (u32)(bb * 2304 + krow * 72 + ncol) * 2;
                LDSM4T(bh, sWhiB + off);
                LDSM4T(bl, sWloB + off);
            }
            #pragma unroll
            for (int nt = 0; nt < 2; nt++) {
                MMA16816(acc[nt], ah, (&bh[nt * 2]));
                MMA16816(acc[nt], ah, (&bl[nt * 2]));
                MMA16816(acc[nt], al, (&bh[nt * 2]));
            }
        }
        if (it < 7) {
            storeTile(1 - bb);   // other buffer: no hazard with this iter's readers
            __syncthreads();
        }
    }

    const float* bias = J.bias[ji];
    float scl = J.scale[ji];
    int sMode = J.storeMode[ji], act = J.act[ji];

    #pragma unroll
    for (int nt = 0; nt < 2; nt++) {
        int row0 = rowBase + wm * 16 + (lane >> 2);
        int col0 = colBase + wn * 16 + nt * 8 + (lane & 3) * 2;
        float bv0 = bias ? bias[col0] : 0.0f;
        float bv1 = bias ? bias[col0 + 1] : 0.0f;
        #pragma unroll
        for (int half = 0; half < 2; half++) {
            int row = row0 + half * 8;
            float v0 = (acc[nt][half * 2 + 0] + bv0) * scl;
            float v1 = (acc[nt][half * 2 + 1] + bv1) * scl;
            if (act) { v0 = gelu_tanh(v0); v1 = gelu_tanh(v1); }
            if (sMode == 0) {
                *(float2*)&J.Cf[ji][row * 256 + col0] = make_float2(v0, v1);
            } else if (sMode == 1) {
                u32 hi, lo;
                packP(v0, v1, hi, lo);
                *(u32*)&J.Chi[ji][row * 256 + col0] = hi;
                *(u32*)&J.Clo[ji][row * 256 + col0] = lo;
            } else {
                int b = row >> 7, n = row & 127;
                int h = col0 >> 5, dk = col0 & 31;
                int idx = (((b * 8 + h) * 128 + n) * 32) + dk;
                u32 hi, lo;
                packP(v0, v1, hi, lo);
                *(u32*)&J.Chi[ji][idx] = hi;
                *(u32*)&J.Clo[ji][idx] = lo;
            }
        }
    }
}

// ---------------- conn job: 32i x 32j, 256 threads ---------------------------
__device__ void connJob(int cid, ConnArgs CA, char* smemRaw)
{
    float (*Aj)[33] = (float(*)[33])smemRaw;
    float (*Bi)[33] = (float(*)[33])(smemRaw + 32 * 33 * 4);
    float* Cs0 = (float*)(smemRaw + 2 * 32 * 33 * 4);
    float* Cs1 = Cs0 + 256;

    int h = cid >> 4;
    int ibase = ((cid >> 2) & 3) * 32;
    int jbase = (cid & 3) * 32;
    int t = threadIdx.x;
    int tx = t & 15, ty = t >> 4;

    Cs0[t] = CA.fccw[2 * t];
    Cs1[t] = CA.fccw[2 * t + 1];

    float l0[2][2] = {{0.f, 0.f}, {0.f, 0.f}};
    float l1[2][2] = {{0.f, 0.f}, {0.f, 0.f}};

    for (int d0 = 0; d0 < 256; d0 += 32) {
        if (d0) __syncthreads();
        int jr = t >> 3, c = (t & 7) * 4;
        float4 va = *(const float4*)&g_fA[(h * 128 + jbase + jr) * 256 + d0 + c];
        Aj[jr][c] = va.x; Aj[jr][c + 1] = va.y; Aj[jr][c + 2] = va.z; Aj[jr][c + 3] = va.w;
        float4 vb = *(const float4*)&g_fB[(h * 128 + ibase + jr) * 256 + d0 + c];
        float4 o = *(const float4*)&CA.fcb[d0 + c];
        Bi[jr][c] = vb.x + o.x; Bi[jr][c + 1] = vb.y + o.y;
        Bi[jr][c + 2] = vb.z + o.z; Bi[jr][c + 3] = vb.w + o.w;
        __syncthreads();

        #pragma unroll
        for (int dd = 0; dd < 32; dd++) {
            float a0 = Aj[tx * 2][dd], a1 = Aj[tx * 2 + 1][dd];
            float b0 = Bi[ty * 2][dd], b1 = Bi[ty * 2 + 1][dd];
            float c0v = Cs0[d0 + dd], c1v = Cs1[d0 + dd];
            float r00 = fmaxf(a0 + b0, 0.f), r10 = fmaxf(a1 + b0, 0.f);
            float r01 = fmaxf(a0 + b1, 0.f), r11 = fmaxf(a1 + b1, 0.f);
            l0[0][0] = fmaf(r00, c0v, l0[0][0]); l1[0][0] = fmaf(r00, c1v, l1[0][0]);
            l0[0][1] = fmaf(r10, c0v, l0[0][1]); l1[0][1] = fmaf(r10, c1v, l1[0][1]);
            l0[1][0] = fmaf(r01, c0v, l0[1][0]); l1[1][0] = fmaf(r01, c1v, l1[1][0]);
            l0[1][1] = fmaf(r11, c0v, l0[1][1]); l1[1][1] = fmaf(r11, c1v, l1[1][1]);
        }
    }

    float cb0 = CA.fccb[0], cb1 = CA.fccb[1];
    #pragma unroll
    for (int ii = 0; ii < 2; ii++) {
        int i = ibase + ty * 2 + ii;
        #pragma unroll
        for (int jj = 0; jj < 2; jj++) {
            int j = jbase + tx * 2 + jj;
            int idx = (h * 128 + i) * 128 + j;
            float2 u2 = *(const float2*)&CA.gu[idx * 2];
            float gg0 = -logf(-logf(u2.x + 1e-10f) + 1e-10f);
            float gg1 = -logf(-logf(u2.y + 1e-10f) + 1e-10f);
            g_conn[idx] = ((l1[ii][jj] + cb1 + gg1) > (l0[ii][jj] + cb0 + gg0)) ? 1.0f : 0.0f;
        }
    }
}

// ---------------- attention-only kernel: one CTA per (b,h), 256 threads ------
// Q/K/V planes from gmem -> smem; S=QK^T MMA; mask; softmax; O=PV MMA -> ao.
#define ATTN_SMEM (61440 + 2048)

__global__ void __launch_bounds__(256)
k_attn()
{
    extern __shared__ char sm[];
    u32 smB = (u32)__cvta_generic_to_shared(sm);
    bf16* planes = (bf16*)sm;                // 6 x [128*40]
    u32* cmask = (u32*)(sm + 61440);
    u32 sQhiB = smB, sQloB = smB + 10240;
    u32 sKhiB = smB + 20480, sKloB = smB + 30720;
    u32 sVhiB = smB + 40960, sVloB = smB + 51200;

    int bid = blockIdx.x;
    int b = bid >> 3, h = bid & 7;
    int t = threadIdx.x;
    int warp = t >> 5, lane = t & 31;
    int g = lane >> 3, r = lane & 7;

    // conn bitmask
    {
        const float* cr = g_conn + h * 16384;
        for (int i0b = 0; i0b < 128; i0b += 2) {
            int i0 = i0b + (warp >> 2);
            float c = cr[i0 * 128 + (warp & 3) * 32 + lane];
            u32 bal = __ballot_sync(0xffffffffu, c > 0.5f);
            if (lane == 0) cmask[i0 * 4 + (warp & 3)] = bal;
        }
    }

    // stage Q/K/V planes: 6 planes x 512 uint4 chunks
    {
        int gbase = bid * 4096;
        #pragma unroll
        for (int u = 0; u < 12; u++) {
            int c = t + u * 256;          // 0..3071
            int plane = c >> 9;            // 0..5
            int i = c & 511;
            int row = i >> 2, seg = i & 3;
            int op = plane >> 1;
            const bf16* src = (plane & 1) ? (g_qkvlo + op * 1048576)
                                          : (g_qkvhi + op * 1048576);
            // smem plane order: Qhi,Qlo,Khi,Klo,Vhi,Vlo ; plane p at offset p*5120
            int pidx = op * 2 + (plane & 1);
            *(uint4*)&planes[pidx * 5120 + row * 40 + seg * 8] =
                *(const uint4*)&src[gbase + row * 32 + seg * 8];
        }
    }
    __syncthreads();

    // Q frags (k=32 -> 2 k-tiles)
    u32 aQh[2][4], aQl[2][4];
    #pragma unroll
    for (int kt = 0; kt < 2; kt++) {
        int rowA = warp * 16 + r + ((g & 1) << 3);
        int kcol = kt * 16 + ((g >> 1) << 3);
        u32 off = (u32)(rowA * 40 + kcol) * 2;
        LDSM4(aQh[kt], sQhiB + off);
        LDSM4(aQl[kt], sQloB + off);
    }

    float accS[16][4];
    #pragma unroll
    for (int nt = 0; nt < 16; nt++)
        #pragma unroll
        for (int i = 0; i < 4; i++) accS[nt][i] = 0.0f;

    #pragma unroll
    for (int kt = 0; kt < 2; kt++) {
        #pragma unroll
        for (int ng = 0; ng < 8; ng++) {
            u32 kbh[4], kbl[4];
            int nrow = ng * 16 + r + ((g & 1) << 3);
            int kcol = kt * 16 + ((g >> 1) << 3);
            u32 off = (u32)(nrow * 40 + kcol) * 2;
            LDSM4(kbh, sKhiB + off);
            LDSM4(kbl, sKloB + off);
            u32 b0h[2] = {kbh[0], kbh[2]}, b1h[2] = {kbh[1], kbh[3]};
            u32 b0l[2] = {kbl[0], kbl[2]}, b1l[2] = {kbl[1], kbl[3]};
            MMA16816(accS[ng * 2], aQh[kt], b0h);
            MMA16816(accS[ng * 2], aQh[kt], b0l);
            MMA16816(accS[ng * 2], aQl[kt], b0h);
            MMA16816(accS[ng * 2 + 1], aQh[kt], b1h);
            MMA16816(accS[ng * 2 + 1], aQh[kt], b1l);
            MMA16816(accS[ng * 2 + 1], aQl[kt], b1h);
        }
    }

    int rA = warp * 16 + (lane >> 2);
    int rB = rA + 8;
    u32 mA[4], mB[4];
    #pragma unroll
    for (int w2 = 0; w2 < 4; w2++) { mA[w2] = cmask[rA * 4 + w2]; mB[w2] = cmask[rB * 4 + w2]; }
    #pragma unroll
    for (int nt = 0; nt < 16; nt++) {
        int c0 = nt * 8 + (lane & 3) * 2;
        int w2 = c0 >> 5, bit = c0 & 31;
        if (!((mA[w2] >> bit) & 1u))       accS[nt][0] = -INFINITY;
        if (!((mA[w2] >> (bit + 1)) & 1u)) accS[nt][1] = -INFINITY;
        if (!((mB[w2] >> bit) & 1u))       accS[nt][2] = -INFINITY;
        if (!((mB[w2] >> (bit + 1)) & 1u)) accS[nt][3] = -INFINITY;
    }

    float mxA = -INFINITY, mxB = -INFINITY;
    #pragma unroll
    for (int nt = 0; nt < 16; nt++) {
        mxA = fmaxf(mxA, fmaxf(accS[nt][0], accS[nt][1]));
        mxB = fmaxf(mxB, fmaxf(accS[nt][2], accS[nt][3]));
    }
    mxA = fmaxf(mxA, __shfl_xor_sync(0xffffffffu, mxA, 1));
    mxA = fmaxf(mxA, __shfl_xor_sync(0xffffffffu, mxA, 2));
    mxB = fmaxf(mxB, __shfl_xor_sync(0xffffffffu, mxB, 1));
    mxB = fmaxf(mxB, __shfl_xor_sync(0xffffffffu, mxB, 2));

    float sA = 0.0f, sB = 0.0f;
    #pragma unroll
    for (int nt = 0; nt < 16; nt++) {
        accS[nt][0] = expf(accS[nt][0] - mxA);
        accS[nt][1] = expf(accS[nt][1] - mxA);
        accS[nt][2] = expf(accS[nt][2] - mxB);
        accS[nt][3] = expf(accS[nt][3] - mxB);
        sA += accS[nt][0] + accS[nt][1];
        sB += accS[nt][2] + accS[nt][3];
    }
    sA += __shfl_xor_sync(0xffffffffu, sA, 1);
    sA += __shfl_xor_sync(0xffffffffu, sA, 2);
    sB += __shfl_xor_sync(0xffffffffu, sB, 1);
    sB += __shfl_xor_sync(0xffffffffu, sB, 2);
    float invA = 1.0f / sA, invB = 1.0f / sB;

    float accO[4][4];
    #pragma unroll
    for (int nt = 0; nt < 4; nt++)
        #pragma unroll
        for (int i = 0; i < 4; i++) accO[nt][i] = 0.0f;

    #pragma unroll
    for (int kt = 0; kt < 8; kt++) {
        u32 ph[4], plo[4];
        packP(accS[2 * kt][0],     accS[2 * kt][1],     ph[0], plo[0]);
        packP(accS[2 * kt][2],     accS[2 * kt][3],     ph[1], plo[1]);
        packP(accS[2 * kt + 1][0], accS[2 * kt + 1][1], ph[2], plo[2]);
        packP(accS[2 * kt + 1][2], accS[2 * kt + 1][3], ph[3], plo[3]);
        #pragma unroll
        for (int n16 = 0; n16 < 2; n16++) {
            u32 vbh[4], vbl[4];
            int krow = kt * 16 + r + ((g & 1) << 3);
            int ncol = n16 * 16 + ((g >> 1) << 3);
            u32 off = (u32)(krow * 40 + ncol) * 2;
            LDSM4T(vbh, sVhiB + off);
            LDSM4T(vbl, sVloB + off);
            MMA16816(accO[n16 * 2], ph, (&vbh[0]));
            MMA16816(accO[n16 * 2], ph, (&vbl[0]));
            MMA16816(accO[n16 * 2], plo, (&vbh[0]));
            MMA16816(accO[n16 * 2 + 1], ph, (&vbh[2]));
            MMA16816(accO[n16 * 2 + 1], ph, (&vbl[2]));
            MMA16816(accO[n16 * 2 + 1], plo, (&vbh[2]));
        }
    }

    #pragma unroll
    for (int nt = 0; nt < 4; nt++) {
        int c0 = nt * 8 + (lane & 3) * 2;
        int oA = (b * 128 + rA) * 256 + h * 32 + c0;
        int oB = (b * 128 + rB) * 256 + h * 32 + c0;
        u32 hi, lo;
        packP(accO[nt][0] * invA, accO[nt][1] * invA, hi, lo);
        *(u32*)&g_aohi[oA] = hi; *(u32*)&g_aolo[oA] = lo;
        packP(accO[nt][2] * invB, accO[nt][3] * invB, hi, lo);
        *(u32*)&g_aohi[oB] = hi; *(u32*)&g_aolo[oB] = lo;
    }
}

// ---------------- launch ------------------------------------------------------
extern "C" void kernel_launch(void* const* d_in, const int* in_sizes, int n_in,
                              void* d_out, int out_size)
{
    const float* x        = (const float*)d_in[0];
    const float* gumbel_u = (const float*)d_in[1];
    const float* memory_w = (const float*)d_in[2];
    const float* fc_out_w = (const float*)d_in[3];
    const float* fc_out_b = (const float*)d_in[4];
    const float* fc_cat_w = (const float*)d_in[5];
    const float* fc_cat_b = (const float*)d_in[6];
    const float* wq       = (const float*)d_in[7];
    const float* bq       = (const float*)d_in[8];
    const float* wk       = (const float*)d_in[9];
    const float* bk       = (const float*)d_in[10];
    const float* wv       = (const float*)d_in[11];
    const float* bv       = (const float*)d_in[12];
    const float* out_w    = (const float*)d_in[13];
    const float* out_b    = (const float*)d_in[14];
    const float* mlp_w1   = (const float*)d_in[15];
    const float* mlp_b1   = (const float*)d_in[16];
    const float* mlp_w2   = (const float*)d_in[17];
    const float* mlp_b2   = (const float*)d_in[18];

    float *fA, *fB, *cb;
    cudaGetSymbolAddress((void**)&fA, g_fA);
    cudaGetSymbolAddress((void**)&fB, g_fB);
    cudaGetSymbolAddress((void**)&cb, g_cb);
    bf16 *wphi, *wplo, *fthi, *ftlo, *xhi, *xlo, *cwhi, *cwlo;
    bf16 *h1hi, *h1lo, *qkvhi, *qkvlo, *aohi, *aolo;
    cudaGetSymbolAddress((void**)&wphi, g_wphi);
    cudaGetSymbolAddress((void**)&wplo, g_wplo);
    cudaGetSymbolAddress((void**)&fthi, g_fthi);
    cudaGetSymbolAddress((void**)&ftlo, g_ftlo);
    cudaGetSymbolAddress((void**)&xhi, g_xhi);
    cudaGetSymbolAddress((void**)&xlo, g_xlo);
    cudaGetSymbolAddress((void**)&cwhi, g_cwhi);
    cudaGetSymbolAddress((void**)&cwlo, g_cwlo);
    cudaGetSymbolAddress((void**)&h1hi, g_h1hi);
    cudaGetSymbolAddress((void**)&h1lo, g_h1lo);
    cudaGetSymbolAddress((void**)&qkvhi, g_qkvhi);
    cudaGetSymbolAddress((void**)&qkvlo, g_qkvlo);
    cudaGetSymbolAddress((void**)&aohi, g_aohi);
    cudaGetSymbolAddress((void**)&aolo, g_aolo);

    static bool attrSet = false;
    if (!attrSet) {
        cudaFuncSetAttribute(k_attn, cudaFuncAttributeMaxDynamicSharedMemorySize, ATTN_SMEM);
        attrSet = true;
    }

    ConnArgs CA = { fc_out_b, fc_cat_w, fc_cat_b, gumbel_u,
                    mlp_b2, wq, wk, wv, bq, bk, bv };

    // A: convert weights / feats / x to planes (896 blocks)
    {
        CvtParams CP;
        CP.src[0] = fc_out_w;          CP.src[1] = fc_out_w + 65536;
        CP.src[2] = mlp_w1;            CP.src[3] = out_w;
        CP.src[4] = mlp_w2;            CP.src[5] = wq;
        CP.src[6] = wk;                CP.src[7] = wv;
        CP.mw = memory_w;              CP.x = x;
        k_cvt<<<896, 256>>>(CP);
    }

    // B: fA(128) + fB(128) + mlp1(512) + composeQ/K/V(32 each) + bias(3) = 867
    {
        Job6 J = {};
        // job 0: fA
        J.Ahi[0] = fthi; J.Alo[0] = ftlo; J.Whi[0] = wphi; J.Wlo[0] = wplo;
        J.Cf[0] = fA; J.scale[0] = 1.0f; J.end[0] = 128;
        // job 1: fB
        J.Ahi[1] = fthi; J.Alo[1] = ftlo;
        J.Whi[1] = wphi + 65536; J.Wlo[1] = wplo + 65536;
        J.Cf[1] = fB; J.scale[1] = 1.0f; J.end[1] = 256;
        // job 2: mlp1 (gelu, planes)
        J.Ahi[2] = xhi; J.Alo[2] = xlo;
        J.Whi[2] = wphi + 2 * 65536; J.Wlo[2] = wplo + 2 * 65536;
        J.bias[2] = mlp_b1; J.Chi[2] = h1hi; J.Clo[2] = h1lo;
        J.scale[2] = 1.0f; J.act[2] = 1; J.storeMode[2] = 1; J.end[2] = 768;
        // jobs 3-5: compose W2@W{q,k,v} (planes out)
        for (int z = 0; z < 3; z++) {
            int ji = 3 + z;
            J.Ahi[ji] = wphi + 4 * 65536; J.Alo[ji] = wplo + 4 * 65536;
            J.Whi[ji] = wphi + (5 + z) * 65536; J.Wlo[ji] = wplo + (5 + z) * 65536;
            J.Chi[ji] = cwhi + z * 65536; J.Clo[ji] = cwlo + z * 65536;
            J.scale[ji] = 1.0f; J.storeMode[ji] = 1; J.end[ji] = 768 + (z + 1) * 32;
        }
        J.totTiles = 864; J.nconn = 0;   // 3 bias blocks after tiles
        k_gemm32<<<867, 256>>>(J, CA);
    }

    // C: QKV gemms (3 x 512, per-head plane store) + conn(128) = 1664
    {
        Job6 J = {};
        const float scale = 0.17677669529663687f;  // 1/sqrt(32)
        for (int z = 0; z < 3; z++) {
            J.Ahi[z] = h1hi; J.Alo[z] = h1lo;
            J.Whi[z] = cwhi + z * 65536; J.Wlo[z] = cwlo + z * 65536;
            J.bias[z] = cb + z * 256;
            J.Chi[z] = qkvhi + z * 1048576; J.Clo[z] = qkvlo + z * 1048576;
            J.scale[z] = (z == 0) ? scale : 1.0f;
            J.storeMode[z] = 2;
            J.end[z] = (z + 1) * 512;
        }
        J.end[3] = J.end[4] = J.end[5] = 1536;
        J.totTiles = 1536; J.nconn = 128;
        k_gemm32<<<1664, 256>>>(J, CA);
    }

    // D: attention (256 CTAs, one per (b,h))
    k_attn<<<256, 256, ATTN_SMEM>>>();

    // E: output projection -> d_out (512)
    {
        Job6 J = {};
        J.Ahi[0] = aohi; J.Alo[0] = aolo;
        J.Whi[0] = wphi + 3 * 65536; J.Wlo[0] = wplo + 3 * 65536;
        J.bias[0] = out_b; J.Cf[0] = (float*)d_out;
        J.scale[0] = 1.0f; J.end[0] = 512;
        J.end[1] = J.end[2] = J.end[3] = J.end[4] = J.end[5] = 512;
        J.totTiles = 512; J.nconn = 0;
        k_gemm32<<<512, 256>>>(J, CA);
    }
}

// round 10
// speedup vs baseline: 1.0282x; 1.0282x over previous
#include <cuda_runtime.h>
#include <cuda_bf16.h>
#include <math.h>

// Problem constants: B=32, N=128, D=256, H=8, DK=32
typedef unsigned int u32;
typedef __nv_bfloat16 bf16;

// ---------------- scratch (static device globals; no allocation) -------------
__device__ __align__(16) float g_fA[1024 * 256];
__device__ __align__(16) float g_fB[1024 * 256];
__device__ __align__(16) float g_conn[8 * 128 * 128];
__device__ __align__(16) float g_cb[3 * 256];            // composed QKV biases
__device__ __align__(16) bf16 g_cwhi[3 * 65536];         // composed W2@W{q,k,v}
__device__ __align__(16) bf16 g_cwlo[3 * 65536];
__device__ __align__(16) bf16 g_h1hi[4096 * 256];
__device__ __align__(16) bf16 g_h1lo[4096 * 256];
__device__ __align__(16) bf16 g_qkvhi[3 * 1048576];      // [op][B,H,N,DK] planes
__device__ __align__(16) bf16 g_qkvlo[3 * 1048576];
__device__ __align__(16) bf16 g_aohi[4096 * 256];
__device__ __align__(16) bf16 g_aolo[4096 * 256];

__device__ __forceinline__ float gelu_tanh(float x) {
    float x3 = x * x * x;
    float t = tanhf(0.7978845608028654f * (x + 0.044715f * x3));
    return 0.5f * x * (1.0f + t);
}

__device__ __forceinline__ void split_bf16(float v, bf16& h, bf16& l) {
    h = __float2bfloat16_rn(v);
    l = __float2bfloat16_rn(v - __bfloat162float(h));
}

__device__ __forceinline__ void cvt4(float4 v, uint2& hi, uint2& lo) {
    bf16 h0, l0, h1, l1, h2, l2, h3, l3;
    split_bf16(v.x, h0, l0); split_bf16(v.y, h1, l1);
    split_bf16(v.z, h2, l2); split_bf16(v.w, h3, l3);
    __nv_bfloat162 a, b, c, d;
    a.x = h0; a.y = h1; b.x = h2; b.y = h3;
    c.x = l0; c.y = l1; d.x = l2; d.y = l3;
    hi.x = *(u32*)&a; hi.y = *(u32*)&b;
    lo.x = *(u32*)&c; lo.y = *(u32*)&d;
}

__device__ __forceinline__ void packP(float x, float y, u32& hi, u32& lo) {
    bf16 hx, lx, hy, ly;
    split_bf16(x, hx, lx);
    split_bf16(y, hy, ly);
    __nv_bfloat162 H; H.x = hx; H.y = hy;
    __nv_bfloat162 L; L.x = lx; L.y = ly;
    hi = *(u32*)&H; lo = *(u32*)&L;
}

#define LDSM4(r, addr)                                                        \
    asm volatile("ldmatrix.sync.aligned.m8n8.x4.shared.b16 {%0,%1,%2,%3}, [%4];" \
                 : "=r"(r[0]), "=r"(r[1]), "=r"(r[2]), "=r"(r[3]) : "r"(addr))

#define LDSM4T(r, addr)                                                       \
    asm volatile("ldmatrix.sync.aligned.m8n8.x4.trans.shared.b16 {%0,%1,%2,%3}, [%4];" \
                 : "=r"(r[0]), "=r"(r[1]), "=r"(r[2]), "=r"(r[3]) : "r"(addr))

#define MMA16816(d, a, b)                                                     \
    asm volatile("mma.sync.aligned.m16n8k16.row.col.f32.bf16.bf16.f32 "       \
                 "{%0,%1,%2,%3}, {%4,%5,%6,%7}, {%8,%9}, {%0,%1,%2,%3};"      \
                 : "+f"(d[0]), "+f"(d[1]), "+f"(d[2]), "+f"(d[3])             \
                 : "r"(a[0]), "r"(a[1]), "r"(a[2]), "r"(a[3]),                \
                   "r"(b[0]), "r"(b[1]))

// ---------------- multi-job GEMM-32: BM=32, BN=64, BK=32 ---------------------
// aMode: 0 fp32 row-major, 1 fp32 memory_w gather, 2 bf16 planes
// wMode: 0 fp32 (inline split), 1 bf16 planes
// storeMode: 0 fp32, 1 bf16 planes row*256+col, 2 QKV per-head planes
struct Job6 {
    const float* Af[6];
    const bf16 *Ahi[6], *Alo[6];
    const float* Wf[6];
    const bf16 *Whi[6], *Wlo[6];
    const float* bias[6];
    float* Cf[6];
    bf16 *Chi[6], *Clo[6];
    float scale[6];
    int aMode[6], wMode[6], act[6], storeMode[6];
    int end[6];        // cumulative tile counts
    int totTiles, nconn;
};

struct ConnArgs {
    const float *fcb, *fccw, *fccb, *gu;
    const float *b2, *wq, *wk, *wv, *bq, *bk, *bv;
};

__device__ void connJob(int cid, ConnArgs CA, char* smemRaw);

__device__ void biasJob(int z, ConnArgs CA) {
    int c = threadIdx.x;
    const float* wz = (z == 0) ? CA.wq : (z == 1) ? CA.wk : CA.wv;
    const float* bz = (z == 0) ? CA.bq : (z == 1) ? CA.bk : CA.bv;
    float acc = bz[c];
    for (int d = 0; d < 256; d++)
        acc = fmaf(CA.b2[d], wz[d * 256 + c], acc);
    g_cb[z * 256 + c] = acc;
}

__global__ void __launch_bounds__(256)
k_gemm32(Job6 J, ConnArgs CA)
{
    __shared__ __align__(16) char smemRaw[28672];

    int jid = blockIdx.x;
    if (jid >= J.totTiles) {
        int e = jid - J.totTiles;
        if (e < J.nconn) connJob(e, CA, smemRaw);
        else biasJob(e - J.nconn, CA);
        return;
    }
    int ji = 0;
    #pragma unroll
    for (int k = 0; k < 5; k++) if (jid >= J.end[k]) ji = k + 1;
    int tile = jid - (ji ? J.end[ji - 1] : 0);

    int aMode = J.aMode[ji], wMode = J.wMode[ji];

    bf16* sAhi = (bf16*)smemRaw;            // [2][32*40]
    bf16* sAlo = sAhi + 2 * 1280;
    bf16* sWhi = sAlo + 2 * 1280;           // [2][32*72]
    bf16* sWlo = sWhi + 2 * 2304;

    int rowBase = (tile >> 2) * 32;
    int colBase = (tile & 3) * 64;

    int t = threadIdx.x;
    int warp = t >> 5, lane = t & 31;
    int wm = warp >> 2, wn = warp & 3;
    int g = lane >> 3, r = lane & 7;

    u32 sAhiB = (u32)__cvta_generic_to_shared(sAhi);
    u32 sAloB = (u32)__cvta_generic_to_shared(sAlo);
    u32 sWhiB = (u32)__cvta_generic_to_shared(sWhi);
    u32 sWloB = (u32)__cvta_generic_to_shared(sWlo);

    // staging indices
    int pl = t >> 7, ps = t & 127;
    int prow = ps >> 2, pseg = ps & 3;     // A planes: 32 rows x 4 uint4
    int wr = ps >> 3, wsg = ps & 7;        // W planes: rows wr, wr+16
    int arow = t >> 3, aseg = t & 7;       // A fp32: 1 float4/thread
    int wrow0 = t >> 4, wseg0 = t & 15;    // W fp32: 2 float4/thread
    int wrow1 = (t + 256) >> 4, wseg1 = (t + 256) & 15;

    uint4 pa, pw0, pw1;
    float4 fa, fw0, fw1;

    auto loadTile = [&](int kt) {
        if (aMode == 2) {
            const bf16* asrc = pl ? J.Alo[ji] : J.Ahi[ji];
            pa = *(const uint4*)&asrc[(rowBase + prow) * 256 + kt + pseg * 8];
        } else if (aMode == 0) {
            fa = *(const float4*)&J.Af[ji][(rowBase + arow) * 256 + kt + aseg * 4];
        } else {
            int rr = rowBase + arow;
            int h = rr >> 7, n = rr & 127;
            fa = *(const float4*)&J.Af[ji][n * 2048 + h * 256 + kt + aseg * 4];
        }
        if (wMode == 1) {
            const bf16* wsrc = pl ? J.Wlo[ji] : J.Whi[ji];
            pw0 = *(const uint4*)&wsrc[(kt + wr) * 256 + colBase + wsg * 8];
            pw1 = *(const uint4*)&wsrc[(kt + wr + 16) * 256 + colBase + wsg * 8];
        } else {
            fw0 = *(const float4*)&J.Wf[ji][(kt + wrow0) * 256 + colBase + wseg0 * 4];
            fw1 = *(const float4*)&J.Wf[ji][(kt + wrow1) * 256 + colBase + wseg1 * 4];
        }
    };

    auto storeTile = [&](int bb) {
        if (aMode == 2) {
            bf16* ad = pl ? sAlo : sAhi;
            *(uint4*)&ad[bb * 1280 + prow * 40 + pseg * 8] = pa;
        } else {
            uint2 hi, lo;
            cvt4(fa, hi, lo);
            *(uint2*)&sAhi[bb * 1280 + arow * 40 + aseg * 4] = hi;
            *(uint2*)&sAlo[bb * 1280 + arow * 40 + aseg * 4] = lo;
        }
        if (wMode == 1) {
            bf16* wd = pl ? sWlo : sWhi;
            *(uint4*)&wd[bb * 2304 + wr * 72 + wsg * 8] = pw0;
            *(uint4*)&wd[bb * 2304 + (wr + 16) * 72 + wsg * 8] = pw1;
        } else {
            uint2 hi, lo;
            cvt4(fw0, hi, lo);
            *(uint2*)&sWhi[bb * 2304 + wrow0 * 72 + wseg0 * 4] = hi;
            *(uint2*)&sWlo[bb * 2304 + wrow0 * 72 + wseg0 * 4] = lo;
            cvt4(fw1, hi, lo);
            *(uint2*)&sWhi[bb * 2304 + wrow1 * 72 + wseg1 * 4] = hi;
            *(uint2*)&sWlo[bb * 2304 + wrow1 * 72 + wseg1 * 4] = lo;
        }
    };

    float acc[2][4];
    #pragma unroll
    for (int nt = 0; nt < 2; nt++)
        #pragma unroll
        for (int i = 0; i < 4; i++) acc[nt][i] = 0.0f;

    loadTile(0);
    storeTile(0);
    __syncthreads();

    #pragma unroll
    for (int it = 0; it < 8; it++) {
        int bb = it & 1;
        if (it < 7) loadTile((it + 1) * 32);

        #pragma unroll
        for (int ks = 0; ks < 32; ks += 16) {
            u32 ah[4], al[4], bh[4], bl[4];
            {
                int rowA = wm * 16 + r + ((g & 1) << 3);
                int kcol = ks + ((g >> 1) << 3);
                u32 off = (u32)(bb * 1280 + rowA * 40 + kcol) * 2;
                LDSM4(ah, sAhiB + off);
                LDSM4(al, sAloB + off);
            }
            {
                int krow = ks + r + ((g & 1) << 3);
                int ncol = wn * 16 + ((g >> 1) << 3);
                u32 off = (u32)(bb * 2304 + krow * 72 + ncol) * 2;
                LDSM4T(bh, sWhiB + off);
                LDSM4T(bl, sWloB + off);
            }
            #pragma unroll
            for (int nt = 0; nt < 2; nt++) {
                MMA16816(acc[nt], ah, (&bh[nt * 2]));
                MMA16816(acc[nt], ah, (&bl[nt * 2]));
                MMA16816(acc[nt], al, (&bh[nt * 2]));
            }
        }
        if (it < 7) {
            storeTile(1 - bb);   // other buffer: no hazard with this iter's readers
            __syncthreads();
        }
    }

    const float* bias = J.bias[ji];
    float scl = J.scale[ji];
    int sMode = J.storeMode[ji], act = J.act[ji];

    #pragma unroll
    for (int nt = 0; nt < 2; nt++) {
        int row0 = rowBase + wm * 16 + (lane >> 2);
        int col0 = colBase + wn * 16 + nt * 8 + (lane & 3) * 2;
        float bv0 = bias ? bias[col0] : 0.0f;
        float bv1 = bias ? bias[col0 + 1] : 0.0f;
        #pragma unroll
        for (int half = 0; half < 2; half++) {
            int row = row0 + half * 8;
            float v0 = (acc[nt][half * 2 + 0] + bv0) * scl;
            float v1 = (acc[nt][half * 2 + 1] + bv1) * scl;
            if (act) { v0 = gelu_tanh(v0); v1 = gelu_tanh(v1); }
            if (sMode == 0) {
                *(float2*)&J.Cf[ji][row * 256 + col0] = make_float2(v0, v1);
            } else if (sMode == 1) {
                u32 hi, lo;
                packP(v0, v1, hi, lo);
                *(u32*)&J.Chi[ji][row * 256 + col0] = hi;
                *(u32*)&J.Clo[ji][row * 256 + col0] = lo;
            } else {
                int b = row >> 7, n = row & 127;
                int h = col0 >> 5, dk = col0 & 31;
                int idx = (((b * 8 + h) * 128 + n) * 32) + dk;
                u32 hi, lo;
                packP(v0, v1, hi, lo);
                *(u32*)&J.Chi[ji][idx] = hi;
                *(u32*)&J.Clo[ji][idx] = lo;
            }
        }
    }
}

// ---------------- conn job: 32i x 32j, 256 threads ---------------------------
__device__ void connJob(int cid, ConnArgs CA, char* smemRaw)
{
    float (*Aj)[33] = (float(*)[33])smemRaw;
    float (*Bi)[33] = (float(*)[33])(smemRaw + 32 * 33 * 4);
    float* Cs0 = (float*)(smemRaw + 2 * 32 * 33 * 4);
    float* Cs1 = Cs0 + 256;

    int h = cid >> 4;
    int ibase = ((cid >> 2) & 3) * 32;
    int jbase = (cid & 3) * 32;
    int t = threadIdx.x;
    int tx = t & 15, ty = t >> 4;

    Cs0[t] = CA.fccw[2 * t];
    Cs1[t] = CA.fccw[2 * t + 1];

    float l0[2][2] = {{0.f, 0.f}, {0.f, 0.f}};
    float l1[2][2] = {{0.f, 0.f}, {0.f, 0.f}};

    for (int d0 = 0; d0 < 256; d0 += 32) {
        if (d0) __syncthreads();
        int jr = t >> 3, c = (t & 7) * 4;
        float4 va = *(const float4*)&g_fA[(h * 128 + jbase + jr) * 256 + d0 + c];
        Aj[jr][c] = va.x; Aj[jr][c + 1] = va.y; Aj[jr][c + 2] = va.z; Aj[jr][c + 3] = va.w;
        float4 vb = *(const float4*)&g_fB[(h * 128 + ibase + jr) * 256 + d0 + c];
        float4 o = *(const float4*)&CA.fcb[d0 + c];
        Bi[jr][c] = vb.x + o.x; Bi[jr][c + 1] = vb.y + o.y;
        Bi[jr][c + 2] = vb.z + o.z; Bi[jr][c + 3] = vb.w + o.w;
        __syncthreads();

        #pragma unroll
        for (int dd = 0; dd < 32; dd++) {
            float a0 = Aj[tx * 2][dd], a1 = Aj[tx * 2 + 1][dd];
            float b0 = Bi[ty * 2][dd], b1 = Bi[ty * 2 + 1][dd];
            float c0v = Cs0[d0 + dd], c1v = Cs1[d0 + dd];
            float r00 = fmaxf(a0 + b0, 0.f), r10 = fmaxf(a1 + b0, 0.f);
            float r01 = fmaxf(a0 + b1, 0.f), r11 = fmaxf(a1 + b1, 0.f);
            l0[0][0] = fmaf(r00, c0v, l0[0][0]); l1[0][0] = fmaf(r00, c1v, l1[0][0]);
            l0[0][1] = fmaf(r10, c0v, l0[0][1]); l1[0][1] = fmaf(r10, c1v, l1[0][1]);
            l0[1][0] = fmaf(r01, c0v, l0[1][0]); l1[1][0] = fmaf(r01, c1v, l1[1][0]);
            l0[1][1] = fmaf(r11, c0v, l0[1][1]); l1[1][1] = fmaf(r11, c1v, l1[1][1]);
        }
    }

    float cb0 = CA.fccb[0], cb1 = CA.fccb[1];
    #pragma unroll
    for (int ii = 0; ii < 2; ii++) {
        int i = ibase + ty * 2 + ii;
        #pragma unroll
        for (int jj = 0; jj < 2; jj++) {
            int j = jbase + tx * 2 + jj;
            int idx = (h * 128 + i) * 128 + j;
            float2 u2 = *(const float2*)&CA.gu[idx * 2];
            float gg0 = -logf(-logf(u2.x + 1e-10f) + 1e-10f);
            float gg1 = -logf(-logf(u2.y + 1e-10f) + 1e-10f);
            g_conn[idx] = ((l1[ii][jj] + cb1 + gg1) > (l0[ii][jj] + cb0 + gg0)) ? 1.0f : 0.0f;
        }
    }
}

// ---------------- attention-only kernel: one CTA per (b,h), 256 threads ------
#define ATTN_SMEM (61440 + 2048)

__global__ void __launch_bounds__(256)
k_attn()
{
    extern __shared__ char sm[];
    u32 smB = (u32)__cvta_generic_to_shared(sm);
    bf16* planes = (bf16*)sm;                // 6 x [128*40]
    u32* cmask = (u32*)(sm + 61440);
    u32 sQhiB = smB, sQloB = smB + 10240;
    u32 sKhiB = smB + 20480, sKloB = smB + 30720;
    u32 sVhiB = smB + 40960, sVloB = smB + 51200;

    int bid = blockIdx.x;
    int b = bid >> 3, h = bid & 7;
    int t = threadIdx.x;
    int warp = t >> 5, lane = t & 31;
    int g = lane >> 3, r = lane & 7;

    // conn bitmask
    {
        const float* cr = g_conn + h * 16384;
        for (int i0b = 0; i0b < 128; i0b += 2) {
            int i0 = i0b + (warp >> 2);
            float c = cr[i0 * 128 + (warp & 3) * 32 + lane];
            u32 bal = __ballot_sync(0xffffffffu, c > 0.5f);
            if (lane == 0) cmask[i0 * 4 + (warp & 3)] = bal;
        }
    }

    // stage Q/K/V planes
    {
        int gbase = bid * 4096;
        #pragma unroll
        for (int u = 0; u < 12; u++) {
            int c = t + u * 256;
            int plane = c >> 9;
            int i = c & 511;
            int row = i >> 2, seg = i & 3;
            int op = plane >> 1;
            const bf16* src = (plane & 1) ? (g_qkvlo + op * 1048576)
                                          : (g_qkvhi + op * 1048576);
            int pidx = op * 2 + (plane & 1);
            *(uint4*)&planes[pidx * 5120 + row * 40 + seg * 8] =
                *(const uint4*)&src[gbase + row * 32 + seg * 8];
        }
    }
    __syncthreads();

    u32 aQh[2][4], aQl[2][4];
    #pragma unroll
    for (int kt = 0; kt < 2; kt++) {
        int rowA = warp * 16 + r + ((g & 1) << 3);
        int kcol = kt * 16 + ((g >> 1) << 3);
        u32 off = (u32)(rowA * 40 + kcol) * 2;
        LDSM4(aQh[kt], sQhiB + off);
        LDSM4(aQl[kt], sQloB + off);
    }

    float accS[16][4];
    #pragma unroll
    for (int nt = 0; nt < 16; nt++)
        #pragma unroll
        for (int i = 0; i < 4; i++) accS[nt][i] = 0.0f;

    #pragma unroll
    for (int kt = 0; kt < 2; kt++) {
        #pragma unroll
        for (int ng = 0; ng < 8; ng++) {
            u32 kbh[4], kbl[4];
            int nrow = ng * 16 + r + ((g & 1) << 3);
            int kcol = kt * 16 + ((g >> 1) << 3);
            u32 off = (u32)(nrow * 40 + kcol) * 2;
            LDSM4(kbh, sKhiB + off);
            LDSM4(kbl, sKloB + off);
            u32 b0h[2] = {kbh[0], kbh[2]}, b1h[2] = {kbh[1], kbh[3]};
            u32 b0l[2] = {kbl[0], kbl[2]}, b1l[2] = {kbl[1], kbl[3]};
            MMA16816(accS[ng * 2], aQh[kt], b0h);
            MMA16816(accS[ng * 2], aQh[kt], b0l);
            MMA16816(accS[ng * 2], aQl[kt], b0h);
            MMA16816(accS[ng * 2 + 1], aQh[kt], b1h);
            MMA16816(accS[ng * 2 + 1], aQh[kt], b1l);
            MMA16816(accS[ng * 2 + 1], aQl[kt], b1h);
        }
    }

    int rA = warp * 16 + (lane >> 2);
    int rB = rA + 8;
    u32 mA[4], mB[4];
    #pragma unroll
    for (int w2 = 0; w2 < 4; w2++) { mA[w2] = cmask[rA * 4 + w2]; mB[w2] = cmask[rB * 4 + w2]; }
    #pragma unroll
    for (int nt = 0; nt < 16; nt++) {
        int c0 = nt * 8 + (lane & 3) * 2;
        int w2 = c0 >> 5, bit = c0 & 31;
        if (!((mA[w2] >> bit) & 1u))       accS[nt][0] = -INFINITY;
        if (!((mA[w2] >> (bit + 1)) & 1u)) accS[nt][1] = -INFINITY;
        if (!((mB[w2] >> bit) & 1u))       accS[nt][2] = -INFINITY;
        if (!((mB[w2] >> (bit + 1)) & 1u)) accS[nt][3] = -INFINITY;
    }

    float mxA = -INFINITY, mxB = -INFINITY;
    #pragma unroll
    for (int nt = 0; nt < 16; nt++) {
        mxA = fmaxf(mxA, fmaxf(accS[nt][0], accS[nt][1]));
        mxB = fmaxf(mxB, fmaxf(accS[nt][2], accS[nt][3]));
    }
    mxA = fmaxf(mxA, __shfl_xor_sync(0xffffffffu, mxA, 1));
    mxA = fmaxf(mxA, __shfl_xor_sync(0xffffffffu, mxA, 2));
    mxB = fmaxf(mxB, __shfl_xor_sync(0xffffffffu, mxB, 1));
    mxB = fmaxf(mxB, __shfl_xor_sync(0xffffffffu, mxB, 2));

    float sA = 0.0f, sB = 0.0f;
    #pragma unroll
    for (int nt = 0; nt < 16; nt++) {
        accS[nt][0] = expf(accS[nt][0] - mxA);
        accS[nt][1] = expf(accS[nt][1] - mxA);
        accS[nt][2] = expf(accS[nt][2] - mxB);
        accS[nt][3] = expf(accS[nt][3] - mxB);
        sA += accS[nt][0] + accS[nt][1];
        sB += accS[nt][2] + accS[nt][3];
    }
    sA += __shfl_xor_sync(0xffffffffu, sA, 1);
    sA += __shfl_xor_sync(0xffffffffu, sA, 2);
    sB += __shfl_xor_sync(0xffffffffu, sB, 1);
    sB += __shfl_xor_sync(0xffffffffu, sB, 2);
    float invA = 1.0f / sA, invB = 1.0f / sB;

    float accO[4][4];
    #pragma unroll
    for (int nt = 0; nt < 4; nt++)
        #pragma unroll
        for (int i = 0; i < 4; i++) accO[nt][i] = 0.0f;

    #pragma unroll
    for (int kt = 0; kt < 8; kt++) {
        u32 ph[4], plo[4];
        packP(accS[2 * kt][0],     accS[2 * kt][1],     ph[0], plo[0]);
        packP(accS[2 * kt][2],     accS[2 * kt][3],     ph[1], plo[1]);
        packP(accS[2 * kt + 1][0], accS[2 * kt + 1][1], ph[2], plo[2]);
        packP(accS[2 * kt + 1][2], accS[2 * kt + 1][3], ph[3], plo[3]);
        #pragma unroll
        for (int n16 = 0; n16 < 2; n16++) {
            u32 vbh[4], vbl[4];
            int krow = kt * 16 + r + ((g & 1) << 3);
            int ncol = n16 * 16 + ((g >> 1) << 3);
            u32 off = (u32)(krow * 40 + ncol) * 2;
            LDSM4T(vbh, sVhiB + off);
            LDSM4T(vbl, sVloB + off);
            MMA16816(accO[n16 * 2], ph, (&vbh[0]));
            MMA16816(accO[n16 * 2], ph, (&vbl[0]));
            MMA16816(accO[n16 * 2], plo, (&vbh[0]));
            MMA16816(accO[n16 * 2 + 1], ph, (&vbh[2]));
            MMA16816(accO[n16 * 2 + 1], ph, (&vbl[2]));
            MMA16816(accO[n16 * 2 + 1], plo, (&vbh[2]));
        }
    }

    #pragma unroll
    for (int nt = 0; nt < 4; nt++) {
        int c0 = nt * 8 + (lane & 3) * 2;
        int oA = (b * 128 + rA) * 256 + h * 32 + c0;
        int oB = (b * 128 + rB) * 256 + h * 32 + c0;
        u32 hi, lo;
        packP(accO[nt][0] * invA, accO[nt][1] * invA, hi, lo);
        *(u32*)&g_aohi[oA] = hi; *(u32*)&g_aolo[oA] = lo;
        packP(accO[nt][2] * invB, accO[nt][3] * invB, hi, lo);
        *(u32*)&g_aohi[oB] = hi; *(u32*)&g_aolo[oB] = lo;
    }
}

// ---------------- launch ------------------------------------------------------
extern "C" void kernel_launch(void* const* d_in, const int* in_sizes, int n_in,
                              void* d_out, int out_size)
{
    const float* x        = (const float*)d_in[0];
    const float* gumbel_u = (const float*)d_in[1];
    const float* memory_w = (const float*)d_in[2];
    const float* fc_out_w = (const float*)d_in[3];
    const float* fc_out_b = (const float*)d_in[4];
    const float* fc_cat_w = (const float*)d_in[5];
    const float* fc_cat_b = (const float*)d_in[6];
    const float* wq       = (const float*)d_in[7];
    const float* bq       = (const float*)d_in[8];
    const float* wk       = (const float*)d_in[9];
    const float* bk       = (const float*)d_in[10];
    const float* wv       = (const float*)d_in[11];
    const float* bv       = (const float*)d_in[12];
    const float* out_w    = (const float*)d_in[13];
    const float* out_b    = (const float*)d_in[14];
    const float* mlp_w1   = (const float*)d_in[15];
    const float* mlp_b1   = (const float*)d_in[16];
    const float* mlp_w2   = (const float*)d_in[17];
    const float* mlp_b2   = (const float*)d_in[18];

    float *fA, *fB, *cb;
    cudaGetSymbolAddress((void**)&fA, g_fA);
    cudaGetSymbolAddress((void**)&fB, g_fB);
    cudaGetSymbolAddress((void**)&cb, g_cb);
    bf16 *cwhi, *cwlo, *h1hi, *h1lo, *qkvhi, *qkvlo, *aohi, *aolo;
    cudaGetSymbolAddress((void**)&cwhi, g_cwhi);
    cudaGetSymbolAddress((void**)&cwlo, g_cwlo);
    cudaGetSymbolAddress((void**)&h1hi, g_h1hi);
    cudaGetSymbolAddress((void**)&h1lo, g_h1lo);
    cudaGetSymbolAddress((void**)&qkvhi, g_qkvhi);
    cudaGetSymbolAddress((void**)&qkvlo, g_qkvlo);
    cudaGetSymbolAddress((void**)&aohi, g_aohi);
    cudaGetSymbolAddress((void**)&aolo, g_aolo);

    static bool attrSet = false;
    if (!attrSet) {
        cudaFuncSetAttribute(k_attn, cudaFuncAttributeMaxDynamicSharedMemorySize, ATTN_SMEM);
        attrSet = true;
    }

    ConnArgs CA = { fc_out_b, fc_cat_w, fc_cat_b, gumbel_u,
                    mlp_b2, wq, wk, wv, bq, bk, bv };

    // L1: fA(128) + fB(128) + mlp1(512) + compose W2@W{q,k,v}(3x32) + bias(3) = 867
    {
        Job6 J = {};
        // job 0: fA (feats gather, fp32 W)
        J.Af[0] = memory_w; J.Wf[0] = fc_out_w;
        J.Cf[0] = fA; J.scale[0] = 1.0f; J.aMode[0] = 1; J.end[0] = 128;
        // job 1: fB
        J.Af[1] = memory_w; J.Wf[1] = fc_out_w + 65536;
        J.Cf[1] = fB; J.scale[1] = 1.0f; J.aMode[1] = 1; J.end[1] = 256;
        // job 2: mlp1 (fp32 x, fp32 W, gelu, planes out)
        J.Af[2] = x; J.Wf[2] = mlp_w1; J.bias[2] = mlp_b1;
        J.Chi[2] = h1hi; J.Clo[2] = h1lo;
        J.scale[2] = 1.0f; J.act[2] = 1; J.storeMode[2] = 1; J.end[2] = 768;
        // jobs 3-5: compose W2@W{q,k,v} (fp32 A = mlp_w2, fp32 W, planes out)
        const float* wz[3] = { wq, wk, wv };
        for (int z = 0; z < 3; z++) {
            int ji = 3 + z;
            J.Af[ji] = mlp_w2; J.Wf[ji] = wz[z];
            J.Chi[ji] = cwhi + z * 65536; J.Clo[ji] = cwlo + z * 65536;
            J.scale[ji] = 1.0f; J.storeMode[ji] = 1; J.end[ji] = 768 + (z + 1) * 32;
        }
        J.totTiles = 864; J.nconn = 0;   // +3 bias blocks
        k_gemm32<<<867, 256>>>(J, CA);
    }

    // L2: QKV (3x512, per-head plane store) + conn(128) = 1664
    {
        Job6 J = {};
        const float scale = 0.17677669529663687f;  // 1/sqrt(32)
        for (int z = 0; z < 3; z++) {
            J.Ahi[z] = h1hi; J.Alo[z] = h1lo;
            J.Whi[z] = cwhi + z * 65536; J.Wlo[z] = cwlo + z * 65536;
            J.bias[z] = cb + z * 256;
            J.Chi[z] = qkvhi + z * 1048576; J.Clo[z] = qkvlo + z * 1048576;
            J.scale[z] = (z == 0) ? scale : 1.0f;
            J.aMode[z] = 2; J.wMode[z] = 1; J.storeMode[z] = 2;
            J.end[z] = (z + 1) * 512;
        }
        J.end[3] = J.end[4] = J.end[5] = 1536;
        J.totTiles = 1536; J.nconn = 128;
        k_gemm32<<<1664, 256>>>(J, CA);
    }

    // L3: attention (256 CTAs, one per (b,h))
    k_attn<<<256, 256, ATTN_SMEM>>>();

    // L4: output projection -> d_out (512; A = ao planes, W = out_w fp32 inline)
    {
        Job6 J = {};
        J.Ahi[0] = aohi; J.Alo[0] = aolo; J.Wf[0] = out_w;
        J.bias[0] = out_b; J.Cf[0] = (float*)d_out;
        J.scale[0] = 1.0f; J.aMode[0] = 2; J.end[0] = 512;
        J.end[1] = J.end[2] = J.end[3] = J.end[4] = J.end[5] = 512;
        J.totTiles = 512; J.nconn = 0;
        k_gemm32<<<512, 256>>>(J, CA);
    }
}

// round 11
// speedup vs baseline: 1.0915x; 1.0616x over previous
#include <cuda_runtime.h>
#include <cuda_bf16.h>
#include <math.h>

// Problem constants: B=32, N=128, D=256, H=8, DK=32
typedef unsigned int u32;
typedef __nv_bfloat16 bf16;

// ---------------- scratch (static device globals; no allocation) -------------
__device__ __align__(16) float g_fA[1024 * 256];
__device__ __align__(16) float g_fB[1024 * 256];
__device__ __align__(16) float g_conn[8 * 128 * 128];
__device__ __align__(16) float g_cb[3 * 256];            // composed QKV biases
__device__ __align__(16) bf16 g_cwhi[3 * 65536];         // composed W2@W{q,k,v}
__device__ __align__(16) bf16 g_cwlo[3 * 65536];
__device__ __align__(16) bf16 g_h1hi[4096 * 256];
__device__ __align__(16) bf16 g_h1lo[4096 * 256];
__device__ __align__(16) bf16 g_qkvhi[3 * 1048576];      // [op][B,H,N,DK] planes
__device__ __align__(16) bf16 g_qkvlo[3 * 1048576];
__device__ __align__(16) bf16 g_aohi[4096 * 256];
__device__ __align__(16) bf16 g_aolo[4096 * 256];

__device__ __forceinline__ float gelu_tanh(float x) {
    float x3 = x * x * x;
    float t = tanhf(0.7978845608028654f * (x + 0.044715f * x3));
    return 0.5f * x * (1.0f + t);
}

__device__ __forceinline__ void split_bf16(float v, bf16& h, bf16& l) {
    h = __float2bfloat16_rn(v);
    l = __float2bfloat16_rn(v - __bfloat162float(h));
}

__device__ __forceinline__ void cvt4(float4 v, uint2& hi, uint2& lo) {
    bf16 h0, l0, h1, l1, h2, l2, h3, l3;
    split_bf16(v.x, h0, l0); split_bf16(v.y, h1, l1);
    split_bf16(v.z, h2, l2); split_bf16(v.w, h3, l3);
    __nv_bfloat162 a, b, c, d;
    a.x = h0; a.y = h1; b.x = h2; b.y = h3;
    c.x = l0; c.y = l1; d.x = l2; d.y = l3;
    hi.x = *(u32*)&a; hi.y = *(u32*)&b;
    lo.x = *(u32*)&c; lo.y = *(u32*)&d;
}

__device__ __forceinline__ void packP(float x, float y, u32& hi, u32& lo) {
    bf16 hx, lx, hy, ly;
    split_bf16(x, hx, lx);
    split_bf16(y, hy, ly);
    __nv_bfloat162 H; H.x = hx; H.y = hy;
    __nv_bfloat162 L; L.x = lx; L.y = ly;
    hi = *(u32*)&H; lo = *(u32*)&L;
}

#define LDSM4(r, addr)                                                        \
    asm volatile("ldmatrix.sync.aligned.m8n8.x4.shared.b16 {%0,%1,%2,%3}, [%4];" \
                 : "=r"(r[0]), "=r"(r[1]), "=r"(r[2]), "=r"(r[3]) : "r"(addr))

#define LDSM4T(r, addr)                                                       \
    asm volatile("ldmatrix.sync.aligned.m8n8.x4.trans.shared.b16 {%0,%1,%2,%3}, [%4];" \
                 : "=r"(r[0]), "=r"(r[1]), "=r"(r[2]), "=r"(r[3]) : "r"(addr))

#define MMA16816(d, a, b)                                                     \
    asm volatile("mma.sync.aligned.m16n8k16.row.col.f32.bf16.bf16.f32 "       \
                 "{%0,%1,%2,%3}, {%4,%5,%6,%7}, {%8,%9}, {%0,%1,%2,%3};"      \
                 : "+f"(d[0]), "+f"(d[1]), "+f"(d[2]), "+f"(d[3])             \
                 : "r"(a[0]), "r"(a[1]), "r"(a[2]), "r"(a[3]),                \
                   "r"(b[0]), "r"(b[1]))

// ---------------- multi-job GEMM-32: BM=32, BN=64, BK=32 ---------------------
struct Job6 {
    const float* Af[6];
    const bf16 *Ahi[6], *Alo[6];
    const float* Wf[6];
    const bf16 *Whi[6], *Wlo[6];
    const float* bias[6];
    float* Cf[6];
    bf16 *Chi[6], *Clo[6];
    float scale[6];
    int gather[6], act[6], storeMode[6];   // storeMode: 0 fp32, 1 planes, 2 QKV
    int end[6];
    int totTiles, nconn;
};

struct ConnArgs {
    const float *fcb, *fccw, *fccb, *gu;
    const float *b2, *wq, *wk, *wv, *bq, *bk, *bv;
};

__device__ void connJob(int cid, ConnArgs CA, char* smemRaw);

__device__ void biasJob(int z, ConnArgs CA) {
    int c = threadIdx.x;
    const float* wz = (z == 0) ? CA.wq : (z == 1) ? CA.wk : CA.wv;
    const float* bz = (z == 0) ? CA.bq : (z == 1) ? CA.bk : CA.bv;
    float acc = bz[c];
    for (int d = 0; d < 256; d++)
        acc = fmaf(CA.b2[d], wz[d * 256 + c], acc);
    g_cb[z * 256 + c] = acc;
}

// AFP32: A in fp32 (with per-job gather flag) vs bf16 planes.
// WFP32: W in fp32 (inline split) vs bf16 planes.
template <bool AFP32, bool WFP32>
__device__ __forceinline__ void gemmBody(const Job6& J, const ConnArgs& CA, char* smemRaw)
{
    int jid = blockIdx.x;
    if (jid >= J.totTiles) {
        int e = jid - J.totTiles;
        if (e < J.nconn) connJob(e, CA, smemRaw);
        else biasJob(e - J.nconn, CA);
        return;
    }
    int ji = 0;
    #pragma unroll
    for (int k = 0; k < 5; k++) if (jid >= J.end[k]) ji = k + 1;
    int tile = jid - (ji ? J.end[ji - 1] : 0);

    bf16* sAhi = (bf16*)smemRaw;            // [2][32*40]
    bf16* sAlo = sAhi + 2 * 1280;
    bf16* sWhi = sAlo + 2 * 1280;           // [2][32*72]
    bf16* sWlo = sWhi + 2 * 2304;

    int rowBase = (tile >> 2) * 32;
    int colBase = (tile & 3) * 64;

    int t = threadIdx.x;
    int warp = t >> 5, lane = t & 31;
    int wm = warp >> 2, wn = warp & 3;
    int g = lane >> 3, r = lane & 7;

    u32 sAhiB = (u32)__cvta_generic_to_shared(sAhi);
    u32 sAloB = (u32)__cvta_generic_to_shared(sAlo);
    u32 sWhiB = (u32)__cvta_generic_to_shared(sWhi);
    u32 sWloB = (u32)__cvta_generic_to_shared(sWlo);

    // staging indices
    int pl = t >> 7, ps = t & 127;
    int prow = ps >> 2, pseg = ps & 3;     // A planes
    int wr = ps >> 3, wsg = ps & 7;        // W planes
    int arow = t >> 3, aseg = t & 7;       // A fp32
    int wrow0 = t >> 4, wseg0 = t & 15;    // W fp32
    int wrow1 = (t + 256) >> 4, wseg1 = (t + 256) & 15;

    // A fp32 row address (gather handled once, outside the loop)
    const float* aRowPtr = nullptr;
    if (AFP32) {
        int rr = rowBase + arow;
        if (J.gather[ji]) {
            int h = rr >> 7, n = rr & 127;
            aRowPtr = J.Af[ji] + n * 2048 + h * 256;
        } else {
            aRowPtr = J.Af[ji] + rr * 256;
        }
    }

    uint4 pa, pw0, pw1;
    float4 fa, fw0, fw1;

    auto loadTile = [&](int kt) {
        if (AFP32) {
            fa = *(const float4*)&aRowPtr[kt + aseg * 4];
        } else {
            const bf16* asrc = pl ? J.Alo[ji] : J.Ahi[ji];
            pa = *(const uint4*)&asrc[(rowBase + prow) * 256 + kt + pseg * 8];
        }
        if (WFP32) {
            fw0 = *(const float4*)&J.Wf[ji][(kt + wrow0) * 256 + colBase + wseg0 * 4];
            fw1 = *(const float4*)&J.Wf[ji][(kt + wrow1) * 256 + colBase + wseg1 * 4];
        } else {
            const bf16* wsrc = pl ? J.Wlo[ji] : J.Whi[ji];
            pw0 = *(const uint4*)&wsrc[(kt + wr) * 256 + colBase + wsg * 8];
            pw1 = *(const uint4*)&wsrc[(kt + wr + 16) * 256 + colBase + wsg * 8];
        }
    };

    auto storeTile = [&](int bb) {
        if (AFP32) {
            uint2 hi, lo;
            cvt4(fa, hi, lo);
            *(uint2*)&sAhi[bb * 1280 + arow * 40 + aseg * 4] = hi;
            *(uint2*)&sAlo[bb * 1280 + arow * 40 + aseg * 4] = lo;
        } else {
            bf16* ad = pl ? sAlo : sAhi;
            *(uint4*)&ad[bb * 1280 + prow * 40 + pseg * 8] = pa;
        }
        if (WFP32) {
            uint2 hi, lo;
            cvt4(fw0, hi, lo);
            *(uint2*)&sWhi[bb * 2304 + wrow0 * 72 + wseg0 * 4] = hi;
            *(uint2*)&sWlo[bb * 2304 + wrow0 * 72 + wseg0 * 4] = lo;
            cvt4(fw1, hi, lo);
            *(uint2*)&sWhi[bb * 2304 + wrow1 * 72 + wseg1 * 4] = hi;
            *(uint2*)&sWlo[bb * 2304 + wrow1 * 72 + wseg1 * 4] = lo;
        } else {
            bf16* wd = pl ? sWlo : sWhi;
            *(uint4*)&wd[bb * 2304 + wr * 72 + wsg * 8] = pw0;
            *(uint4*)&wd[bb * 2304 + (wr + 16) * 72 + wsg * 8] = pw1;
        }
    };

    float acc[2][4];
    #pragma unroll
    for (int nt = 0; nt < 2; nt++)
        #pragma unroll
        for (int i = 0; i < 4; i++) acc[nt][i] = 0.0f;

    loadTile(0);
    storeTile(0);
    __syncthreads();

    #pragma unroll
    for (int it = 0; it < 8; it++) {
        int bb = it & 1;
        if (it < 7) loadTile((it + 1) * 32);

        #pragma unroll
        for (int ks = 0; ks < 32; ks += 16) {
            u32 ah[4], al[4], bh[4], bl[4];
            {
                int rowA = wm * 16 + r + ((g & 1) << 3);
                int kcol = ks + ((g >> 1) << 3);
                u32 off = (u32)(bb * 1280 + rowA * 40 + kcol) * 2;
                LDSM4(ah, sAhiB + off);
                LDSM4(al, sAloB + off);
            }
            {
                int krow = ks + r + ((g & 1) << 3);
                int ncol = wn * 16 + ((g >> 1) << 3);
                u32 off = (u32)(bb * 2304 + krow * 72 + ncol) * 2;
                LDSM4T(bh, sWhiB + off);
                LDSM4T(bl, sWloB + off);
            }
            #pragma unroll
            for (int nt = 0; nt < 2; nt++) {
                MMA16816(acc[nt], ah, (&bh[nt * 2]));
                MMA16816(acc[nt], ah, (&bl[nt * 2]));
                MMA16816(acc[nt], al, (&bh[nt * 2]));
            }
        }
        if (it < 7) {
            storeTile(1 - bb);
            __syncthreads();
        }
    }

    const float* bias = J.bias[ji];
    float scl = J.scale[ji];
    int sMode = J.storeMode[ji], act = J.act[ji];

    #pragma unroll
    for (int nt = 0; nt < 2; nt++) {
        int row0 = rowBase + wm * 16 + (lane >> 2);
        int col0 = colBase + wn * 16 + nt * 8 + (lane & 3) * 2;
        float bv0 = bias ? bias[col0] : 0.0f;
        float bv1 = bias ? bias[col0 + 1] : 0.0f;
        #pragma unroll
        for (int half = 0; half < 2; half++) {
            int row = row0 + half * 8;
            float v0 = (acc[nt][half * 2 + 0] + bv0) * scl;
            float v1 = (acc[nt][half * 2 + 1] + bv1) * scl;
            if (act) { v0 = gelu_tanh(v0); v1 = gelu_tanh(v1); }
            if (sMode == 0) {
                *(float2*)&J.Cf[ji][row * 256 + col0] = make_float2(v0, v1);
            } else if (sMode == 1) {
                u32 hi, lo;
                packP(v0, v1, hi, lo);
                *(u32*)&J.Chi[ji][row * 256 + col0] = hi;
                *(u32*)&J.Clo[ji][row * 256 + col0] = lo;
            } else {
                int b = row >> 7, n = row & 127;
                int h = col0 >> 5, dk = col0 & 31;
                int idx = (((b * 8 + h) * 128 + n) * 32) + dk;
                u32 hi, lo;
                packP(v0, v1, hi, lo);
                *(u32*)&J.Chi[ji][idx] = hi;
                *(u32*)&J.Clo[ji][idx] = lo;
            }
        }
    }
}

__global__ void __launch_bounds__(256) k_gemm_ff(Job6 J, ConnArgs CA) {
    __shared__ __align__(16) char smemRaw[28672];
    gemmBody<true, true>(J, CA, smemRaw);
}
__global__ void __launch_bounds__(256) k_gemm_pp(Job6 J, ConnArgs CA) {
    __shared__ __align__(16) char smemRaw[28672];
    gemmBody<false, false>(J, CA, smemRaw);
}
__global__ void __launch_bounds__(256) k_gemm_pf(Job6 J, ConnArgs CA) {
    __shared__ __align__(16) char smemRaw[28672];
    gemmBody<false, true>(J, CA, smemRaw);
}

// ---------------- conn job: 32i x 32j, 256 threads ---------------------------
__device__ void connJob(int cid, ConnArgs CA, char* smemRaw)
{
    float (*Aj)[33] = (float(*)[33])smemRaw;
    float (*Bi)[33] = (float(*)[33])(smemRaw + 32 * 33 * 4);
    float* Cs0 = (float*)(smemRaw + 2 * 32 * 33 * 4);
    float* Cs1 = Cs0 + 256;

    int h = cid >> 4;
    int ibase = ((cid >> 2) & 3) * 32;
    int jbase = (cid & 3) * 32;
    int t = threadIdx.x;
    int tx = t & 15, ty = t >> 4;

    Cs0[t] = CA.fccw[2 * t];
    Cs1[t] = CA.fccw[2 * t + 1];

    float l0[2][2] = {{0.f, 0.f}, {0.f, 0.f}};
    float l1[2][2] = {{0.f, 0.f}, {0.f, 0.f}};

    for (int d0 = 0; d0 < 256; d0 += 32) {
        if (d0) __syncthreads();
        int jr = t >> 3, c = (t & 7) * 4;
        float4 va = *(const float4*)&g_fA[(h * 128 + jbase + jr) * 256 + d0 + c];
        Aj[jr][c] = va.x; Aj[jr][c + 1] = va.y; Aj[jr][c + 2] = va.z; Aj[jr][c + 3] = va.w;
        float4 vb = *(const float4*)&g_fB[(h * 128 + ibase + jr) * 256 + d0 + c];
        float4 o = *(const float4*)&CA.fcb[d0 + c];
        Bi[jr][c] = vb.x + o.x; Bi[jr][c + 1] = vb.y + o.y;
        Bi[jr][c + 2] = vb.z + o.z; Bi[jr][c + 3] = vb.w + o.w;
        __syncthreads();

        #pragma unroll
        for (int dd = 0; dd < 32; dd++) {
            float a0 = Aj[tx * 2][dd], a1 = Aj[tx * 2 + 1][dd];
            float b0 = Bi[ty * 2][dd], b1 = Bi[ty * 2 + 1][dd];
            float c0v = Cs0[d0 + dd], c1v = Cs1[d0 + dd];
            float r00 = fmaxf(a0 + b0, 0.f), r10 = fmaxf(a1 + b0, 0.f);
            float r01 = fmaxf(a0 + b1, 0.f), r11 = fmaxf(a1 + b1, 0.f);
            l0[0][0] = fmaf(r00, c0v, l0[0][0]); l1[0][0] = fmaf(r00, c1v, l1[0][0]);
            l0[0][1] = fmaf(r10, c0v, l0[0][1]); l1[0][1] = fmaf(r10, c1v, l1[0][1]);
            l0[1][0] = fmaf(r01, c0v, l0[1][0]); l1[1][0] = fmaf(r01, c1v, l1[1][0]);
            l0[1][1] = fmaf(r11, c0v, l0[1][1]); l1[1][1] = fmaf(r11, c1v, l1[1][1]);
        }
    }

    float cb0 = CA.fccb[0], cb1 = CA.fccb[1];
    #pragma unroll
    for (int ii = 0; ii < 2; ii++) {
        int i = ibase + ty * 2 + ii;
        #pragma unroll
        for (int jj = 0; jj < 2; jj++) {
            int j = jbase + tx * 2 + jj;
            int idx = (h * 128 + i) * 128 + j;
            float2 u2 = *(const float2*)&CA.gu[idx * 2];
            float gg0 = -logf(-logf(u2.x + 1e-10f) + 1e-10f);
            float gg1 = -logf(-logf(u2.y + 1e-10f) + 1e-10f);
            g_conn[idx] = ((l1[ii][jj] + cb1 + gg1) > (l0[ii][jj] + cb0 + gg0)) ? 1.0f : 0.0f;
        }
    }
}

// ---------------- attention-only kernel: one CTA per (b,h), 256 threads ------
#define ATTN_SMEM (61440 + 2048)

__global__ void __launch_bounds__(256)
k_attn()
{
    extern __shared__ char sm[];
    u32 smB = (u32)__cvta_generic_to_shared(sm);
    bf16* planes = (bf16*)sm;                // 6 x [128*40]
    u32* cmask = (u32*)(sm + 61440);
    u32 sQhiB = smB, sQloB = smB + 10240;
    u32 sKhiB = smB + 20480, sKloB = smB + 30720;
    u32 sVhiB = smB + 40960, sVloB = smB + 51200;

    int bid = blockIdx.x;
    int b = bid >> 3, h = bid & 7;
    int t = threadIdx.x;
    int warp = t >> 5, lane = t & 31;
    int g = lane >> 3, r = lane & 7;

    // conn bitmask
    {
        const float* cr = g_conn + h * 16384;
        for (int i0b = 0; i0b < 128; i0b += 2) {
            int i0 = i0b + (warp >> 2);
            float c = cr[i0 * 128 + (warp & 3) * 32 + lane];
            u32 bal = __ballot_sync(0xffffffffu, c > 0.5f);
            if (lane == 0) cmask[i0 * 4 + (warp & 3)] = bal;
        }
    }

    // stage Q/K/V planes
    {
        int gbase = bid * 4096;
        #pragma unroll
        for (int u = 0; u < 12; u++) {
            int c = t + u * 256;
            int plane = c >> 9;
            int i = c & 511;
            int row = i >> 2, seg = i & 3;
            int op = plane >> 1;
            const bf16* src = (plane & 1) ? (g_qkvlo + op * 1048576)
                                          : (g_qkvhi + op * 1048576);
            int pidx = op * 2 + (plane & 1);
            *(uint4*)&planes[pidx * 5120 + row * 40 + seg * 8] =
                *(const uint4*)&src[gbase + row * 32 + seg * 8];
        }
    }
    __syncthreads();

    u32 aQh[2][4], aQl[2][4];
    #pragma unroll
    for (int kt = 0; kt < 2; kt++) {
        int rowA = warp * 16 + r + ((g & 1) << 3);
        int kcol = kt * 16 + ((g >> 1) << 3);
        u32 off = (u32)(rowA * 40 + kcol) * 2;
        LDSM4(aQh[kt], sQhiB + off);
        LDSM4(aQl[kt], sQloB + off);
    }

    float accS[16][4];
    #pragma unroll
    for (int nt = 0; nt < 16; nt++)
        #pragma unroll
        for (int i = 0; i < 4; i++) accS[nt][i] = 0.0f;

    #pragma unroll
    for (int kt = 0; kt < 2; kt++) {
        #pragma unroll
        for (int ng = 0; ng < 8; ng++) {
            u32 kbh[4], kbl[4];
            int nrow = ng * 16 + r + ((g & 1) << 3);
            int kcol = kt * 16 + ((g >> 1) << 3);
            u32 off = (u32)(nrow * 40 + kcol) * 2;
            LDSM4(kbh, sKhiB + off);
            LDSM4(kbl, sKloB + off);
            u32 b0h[2] = {kbh[0], kbh[2]}, b1h[2] = {kbh[1], kbh[3]};
            u32 b0l[2] = {kbl[0], kbl[2]}, b1l[2] = {kbl[1], kbl[3]};
            MMA16816(accS[ng * 2], aQh[kt], b0h);
            MMA16816(accS[ng * 2], aQh[kt], b0l);
            MMA16816(accS[ng * 2], aQl[kt], b0h);
            MMA16816(accS[ng * 2 + 1], aQh[kt], b1h);
            MMA16816(accS[ng * 2 + 1], aQh[kt], b1l);
            MMA16816(accS[ng * 2 + 1], aQl[kt], b1h);
        }
    }

    int rA = warp * 16 + (lane >> 2);
    int rB = rA + 8;
    u32 mA[4], mB[4];
    #pragma unroll
    for (int w2 = 0; w2 < 4; w2++) { mA[w2] = cmask[rA * 4 + w2]; mB[w2] = cmask[rB * 4 + w2]; }
    #pragma unroll
    for (int nt = 0; nt < 16; nt++) {
        int c0 = nt * 8 + (lane & 3) * 2;
        int w2 = c0 >> 5, bit = c0 & 31;
        if (!((mA[w2] >> bit) & 1u))       accS[nt][0] = -INFINITY;
        if (!((mA[w2] >> (bit + 1)) & 1u)) accS[nt][1] = -INFINITY;
        if (!((mB[w2] >> bit) & 1u))       accS[nt][2] = -INFINITY;
        if (!((mB[w2] >> (bit + 1)) & 1u)) accS[nt][3] = -INFINITY;
    }

    float mxA = -INFINITY, mxB = -INFINITY;
    #pragma unroll
    for (int nt = 0; nt < 16; nt++) {
        mxA = fmaxf(mxA, fmaxf(accS[nt][0], accS[nt][1]));
        mxB = fmaxf(mxB, fmaxf(accS[nt][2], accS[nt][3]));
    }
    mxA = fmaxf(mxA, __shfl_xor_sync(0xffffffffu, mxA, 1));
    mxA = fmaxf(mxA, __shfl_xor_sync(0xffffffffu, mxA, 2));
    mxB = fmaxf(mxB, __shfl_xor_sync(0xffffffffu, mxB, 1));
    mxB = fmaxf(mxB, __shfl_xor_sync(0xffffffffu, mxB, 2));

    float sA = 0.0f, sB = 0.0f;
    #pragma unroll
    for (int nt = 0; nt < 16; nt++) {
        accS[nt][0] = expf(accS[nt][0] - mxA);
        accS[nt][1] = expf(accS[nt][1] - mxA);
        accS[nt][2] = expf(accS[nt][2] - mxB);
        accS[nt][3] = expf(accS[nt][3] - mxB);
        sA += accS[nt][0] + accS[nt][1];
        sB += accS[nt][2] + accS[nt][3];
    }
    sA += __shfl_xor_sync(0xffffffffu, sA, 1);
    sA += __shfl_xor_sync(0xffffffffu, sA, 2);
    sB += __shfl_xor_sync(0xffffffffu, sB, 1);
    sB += __shfl_xor_sync(0xffffffffu, sB, 2);
    float invA = 1.0f / sA, invB = 1.0f / sB;

    float accO[4][4];
    #pragma unroll
    for (int nt = 0; nt < 4; nt++)
        #pragma unroll
        for (int i = 0; i < 4; i++) accO[nt][i] = 0.0f;

    #pragma unroll
    for (int kt = 0; kt < 8; kt++) {
        u32 ph[4], plo[4];
        packP(accS[2 * kt][0],     accS[2 * kt][1],     ph[0], plo[0]);
        packP(accS[2 * kt][2],     accS[2 * kt][3],     ph[1], plo[1]);
        packP(accS[2 * kt + 1][0], accS[2 * kt + 1][1], ph[2], plo[2]);
        packP(accS[2 * kt + 1][2], accS[2 * kt + 1][3], ph[3], plo[3]);
        #pragma unroll
        for (int n16 = 0; n16 < 2; n16++) {
            u32 vbh[4], vbl[4];
            int krow = kt * 16 + r + ((g & 1) << 3);
            int ncol = n16 * 16 + ((g >> 1) << 3);
            u32 off = (u32)(krow * 40 + ncol) * 2;
            LDSM4T(vbh, sVhiB + off);
            LDSM4T(vbl, sVloB + off);
            MMA16816(accO[n16 * 2], ph, (&vbh[0]));
            MMA16816(accO[n16 * 2], ph, (&vbl[0]));
            MMA16816(accO[n16 * 2], plo, (&vbh[0]));
            MMA16816(accO[n16 * 2 + 1], ph, (&vbh[2]));
            MMA16816(accO[n16 * 2 + 1], ph, (&vbl[2]));
            MMA16816(accO[n16 * 2 + 1], plo, (&vbh[2]));
        }
    }

    #pragma unroll
    for (int nt = 0; nt < 4; nt++) {
        int c0 = nt * 8 + (lane & 3) * 2;
        int oA = (b * 128 + rA) * 256 + h * 32 + c0;
        int oB = (b * 128 + rB) * 256 + h * 32 + c0;
        u32 hi, lo;
        packP(accO[nt][0] * invA, accO[nt][1] * invA, hi, lo);
        *(u32*)&g_aohi[oA] = hi; *(u32*)&g_aolo[oA] = lo;
        packP(accO[nt][2] * invB, accO[nt][3] * invB, hi, lo);
        *(u32*)&g_aohi[oB] = hi; *(u32*)&g_aolo[oB] = lo;
    }
}

// ---------------- launch ------------------------------------------------------
extern "C" void kernel_launch(void* const* d_in, const int* in_sizes, int n_in,
                              void* d_out, int out_size)
{
    const float* x        = (const float*)d_in[0];
    const float* gumbel_u = (const float*)d_in[1];
    const float* memory_w = (const float*)d_in[2];
    const float* fc_out_w = (const float*)d_in[3];
    const float* fc_out_b = (const float*)d_in[4];
    const float* fc_cat_w = (const float*)d_in[5];
    const float* fc_cat_b = (const float*)d_in[6];
    const float* wq       = (const float*)d_in[7];
    const float* bq       = (const float*)d_in[8];
    const float* wk       = (const float*)d_in[9];
    const float* bk       = (const float*)d_in[10];
    const float* wv       = (const float*)d_in[11];
    const float* bv       = (const float*)d_in[12];
    const float* out_w    = (const float*)d_in[13];
    const float* out_b    = (const float*)d_in[14];
    const float* mlp_w1   = (const float*)d_in[15];
    const float* mlp_b1   = (const float*)d_in[16];
    const float* mlp_w2   = (const float*)d_in[17];
    const float* mlp_b2   = (const float*)d_in[18];

    float *fA, *fB, *cb;
    cudaGetSymbolAddress((void**)&fA, g_fA);
    cudaGetSymbolAddress((void**)&fB, g_fB);
    cudaGetSymbolAddress((void**)&cb, g_cb);
    bf16 *cwhi, *cwlo, *h1hi, *h1lo, *qkvhi, *qkvlo, *aohi, *aolo;
    cudaGetSymbolAddress((void**)&cwhi, g_cwhi);
    cudaGetSymbolAddress((void**)&cwlo, g_cwlo);
    cudaGetSymbolAddress((void**)&h1hi, g_h1hi);
    cudaGetSymbolAddress((void**)&h1lo, g_h1lo);
    cudaGetSymbolAddress((void**)&qkvhi, g_qkvhi);
    cudaGetSymbolAddress((void**)&qkvlo, g_qkvlo);
    cudaGetSymbolAddress((void**)&aohi, g_aohi);
    cudaGetSymbolAddress((void**)&aolo, g_aolo);

    static bool attrSet = false;
    if (!attrSet) {
        cudaFuncSetAttribute(k_attn, cudaFuncAttributeMaxDynamicSharedMemorySize, ATTN_SMEM);
        attrSet = true;
    }

    ConnArgs CA = { fc_out_b, fc_cat_w, fc_cat_b, gumbel_u,
                    mlp_b2, wq, wk, wv, bq, bk, bv };

    // L1: fA(128) + fB(128) + mlp1(512) + compose(3x32) + bias(3) = 867
    {
        Job6 J = {};
        J.Af[0] = memory_w; J.Wf[0] = fc_out_w;
        J.Cf[0] = fA; J.scale[0] = 1.0f; J.gather[0] = 1; J.end[0] = 128;
        J.Af[1] = memory_w; J.Wf[1] = fc_out_w + 65536;
        J.Cf[1] = fB; J.scale[1] = 1.0f; J.gather[1] = 1; J.end[1] = 256;
        J.Af[2] = x; J.Wf[2] = mlp_w1; J.bias[2] = mlp_b1;
        J.Chi[2] = h1hi; J.Clo[2] = h1lo;
        J.scale[2] = 1.0f; J.act[2] = 1; J.storeMode[2] = 1; J.end[2] = 768;
        const float* wz[3] = { wq, wk, wv };
        for (int z = 0; z < 3; z++) {
            int ji = 3 + z;
            J.Af[ji] = mlp_w2; J.Wf[ji] = wz[z];
            J.Chi[ji] = cwhi + z * 65536; J.Clo[ji] = cwlo + z * 65536;
            J.scale[ji] = 1.0f; J.storeMode[ji] = 1; J.end[ji] = 768 + (z + 1) * 32;
        }
        J.totTiles = 864; J.nconn = 0;
        k_gemm_ff<<<867, 256>>>(J, CA);
    }

    // L2: QKV (3x512, per-head plane store) + conn(128) = 1664
    {
        Job6 J = {};
        const float scale = 0.17677669529663687f;  // 1/sqrt(32)
        for (int z = 0; z < 3; z++) {
            J.Ahi[z] = h1hi; J.Alo[z] = h1lo;
            J.Whi[z] = cwhi + z * 65536; J.Wlo[z] = cwlo + z * 65536;
            J.bias[z] = cb + z * 256;
            J.Chi[z] = qkvhi + z * 1048576; J.Clo[z] = qkvlo + z * 1048576;
            J.scale[z] = (z == 0) ? scale : 1.0f;
            J.storeMode[z] = 2;
            J.end[z] = (z + 1) * 512;
        }
        J.end[3] = J.end[4] = J.end[5] = 1536;
        J.totTiles = 1536; J.nconn = 128;
        k_gemm_pp<<<1664, 256>>>(J, CA);
    }

    // L3: attention (256 CTAs, one per (b,h))
    k_attn<<<256, 256, ATTN_SMEM>>>();

    // L4: output projection -> d_out (512; A = ao planes, W = out_w fp32)
    {
        Job6 J = {};
        J.Ahi[0] = aohi; J.Alo[0] = aolo; J.Wf[0] = out_w;
        J.bias[0] = out_b; J.Cf[0] = (float*)d_out;
        J.scale[0] = 1.0f; J.end[0] = 512;
        J.end[1] = J.end[2] = J.end[3] = J.end[4] = J.end[5] = 512;
        J.totTiles = 512; J.nconn = 0;
        k_gemm_pf<<<512, 256>>>(J, CA);
    }
}

// round 12
// speedup vs baseline: 1.1168x; 1.0232x over previous
#include <cuda_runtime.h>
#include <cuda_bf16.h>
#include <math.h>

// Problem constants: B=32, N=128, D=256, H=8, DK=32
typedef unsigned int u32;
typedef __nv_bfloat16 bf16;

// ---------------- scratch (static device globals; no allocation) -------------
__device__ __align__(16) float g_fA[1024 * 256];
__device__ __align__(16) float g_fB[1024 * 256];
__device__ __align__(16) float g_conn[8 * 128 * 128];
__device__ __align__(16) float g_cb[3 * 256];            // composed QKV biases
__device__ __align__(16) bf16 g_cwhi[3 * 65536];         // composed W2@W{q,k,v}
__device__ __align__(16) bf16 g_cwlo[3 * 65536];
__device__ __align__(16) bf16 g_h1hi[4096 * 256];
__device__ __align__(16) bf16 g_h1lo[4096 * 256];
__device__ __align__(16) bf16 g_qkvhi[3 * 1048576];      // [op][B,H,N,DK] planes
__device__ __align__(16) bf16 g_qkvlo[3 * 1048576];
__device__ __align__(16) bf16 g_aohi[4096 * 256];
__device__ __align__(16) bf16 g_aolo[4096 * 256];

#define GEMM_SMEM 55296   // 2buf x (A 2 planes 32x72 + W 2 planes 64x72) bf16

__device__ __forceinline__ float gelu_tanh(float x) {
    float x3 = x * x * x;
    float t = tanhf(0.7978845608028654f * (x + 0.044715f * x3));
    return 0.5f * x * (1.0f + t);
}

__device__ __forceinline__ void split_bf16(float v, bf16& h, bf16& l) {
    h = __float2bfloat16_rn(v);
    l = __float2bfloat16_rn(v - __bfloat162float(h));
}

__device__ __forceinline__ void cvt4(float4 v, uint2& hi, uint2& lo) {
    bf16 h0, l0, h1, l1, h2, l2, h3, l3;
    split_bf16(v.x, h0, l0); split_bf16(v.y, h1, l1);
    split_bf16(v.z, h2, l2); split_bf16(v.w, h3, l3);
    __nv_bfloat162 a, b, c, d;
    a.x = h0; a.y = h1; b.x = h2; b.y = h3;
    c.x = l0; c.y = l1; d.x = l2; d.y = l3;
    hi.x = *(u32*)&a; hi.y = *(u32*)&b;
    lo.x = *(u32*)&c; lo.y = *(u32*)&d;
}

__device__ __forceinline__ void packP(float x, float y, u32& hi, u32& lo) {
    bf16 hx, lx, hy, ly;
    split_bf16(x, hx, lx);
    split_bf16(y, hy, ly);
    __nv_bfloat162 H; H.x = hx; H.y = hy;
    __nv_bfloat162 L; L.x = lx; L.y = ly;
    hi = *(u32*)&H; lo = *(u32*)&L;
}

#define LDSM4(r, addr)                                                        \
    asm volatile("ldmatrix.sync.aligned.m8n8.x4.shared.b16 {%0,%1,%2,%3}, [%4];" \
                 : "=r"(r[0]), "=r"(r[1]), "=r"(r[2]), "=r"(r[3]) : "r"(addr))

#define LDSM4T(r, addr)                                                       \
    asm volatile("ldmatrix.sync.aligned.m8n8.x4.trans.shared.b16 {%0,%1,%2,%3}, [%4];" \
                 : "=r"(r[0]), "=r"(r[1]), "=r"(r[2]), "=r"(r[3]) : "r"(addr))

#define MMA16816(d, a, b)                                                     \
    asm volatile("mma.sync.aligned.m16n8k16.row.col.f32.bf16.bf16.f32 "       \
                 "{%0,%1,%2,%3}, {%4,%5,%6,%7}, {%8,%9}, {%0,%1,%2,%3};"      \
                 : "+f"(d[0]), "+f"(d[1]), "+f"(d[2]), "+f"(d[3])             \
                 : "r"(a[0]), "r"(a[1]), "r"(a[2]), "r"(a[3]),                \
                   "r"(b[0]), "r"(b[1]))

// ---------------- multi-job GEMM: BM=32, BN=64, BK=64, 4 k-iterations --------
struct Job6 {
    const float* Af[6];
    const bf16 *Ahi[6], *Alo[6];
    const float* Wf[6];
    const bf16 *Whi[6], *Wlo[6];
    const float* bias[6];
    float* Cf[6];
    bf16 *Chi[6], *Clo[6];
    float scale[6];
    int gather[6], act[6], storeMode[6];   // storeMode: 0 fp32, 1 planes, 2 QKV
    int end[6];
    int totTiles, nconn;
};

struct ConnArgs {
    const float *fcb, *fccw, *fccb, *gu;
    const float *b2, *wq, *wk, *wv, *bq, *bk, *bv;
};

__device__ void connJob(int cid, ConnArgs CA, char* smemRaw);

__device__ void biasJob(int z, ConnArgs CA) {
    int c = threadIdx.x;
    const float* wz = (z == 0) ? CA.wq : (z == 1) ? CA.wk : CA.wv;
    const float* bz = (z == 0) ? CA.bq : (z == 1) ? CA.bk : CA.bv;
    float acc = bz[c];
    for (int d = 0; d < 256; d++)
        acc = fmaf(CA.b2[d], wz[d * 256 + c], acc);
    g_cb[z * 256 + c] = acc;
}

// AFP32: A in fp32 (with per-job gather flag) vs bf16 planes.
// WFP32: W in fp32 (inline split) vs bf16 planes.
template <bool AFP32, bool WFP32>
__device__ __forceinline__ void gemmBody(const Job6& J, const ConnArgs& CA, char* smemRaw)
{
    int jid = blockIdx.x;
    if (jid >= J.totTiles) {
        int e = jid - J.totTiles;
        if (e < J.nconn) connJob(e, CA, smemRaw);
        else biasJob(e - J.nconn, CA);
        return;
    }
    int ji = 0;
    #pragma unroll
    for (int k = 0; k < 5; k++) if (jid >= J.end[k]) ji = k + 1;
    int tile = jid - (ji ? J.end[ji - 1] : 0);

    // smem (bf16 units): A planes 2 bufs x 32x72; W planes 2 bufs x 64x72
    bf16* sAhi = (bf16*)smemRaw;             // [2][2304]
    bf16* sAlo = sAhi + 2 * 2304;
    bf16* sWhi = sAlo + 2 * 2304;            // [2][4608]
    bf16* sWlo = sWhi + 2 * 4608;

    int rowBase = (tile >> 2) * 32;
    int colBase = (tile & 3) * 64;

    int t = threadIdx.x;
    int warp = t >> 5, lane = t & 31;
    int wm = warp >> 2, wn = warp & 3;
    int g = lane >> 3, r = lane & 7;

    u32 sAhiB = (u32)__cvta_generic_to_shared(sAhi);
    u32 sAloB = (u32)__cvta_generic_to_shared(sAlo);
    u32 sWhiB = (u32)__cvta_generic_to_shared(sWhi);
    u32 sWloB = (u32)__cvta_generic_to_shared(sWlo);

    int pl = t >> 7, ps = t & 127;

    // fp32-A row pointers (2 chunks: rows t>>4 and (t>>4)+16)
    const float* aRow0 = nullptr;
    const float* aRow1 = nullptr;
    if (AFP32) {
        int r0 = rowBase + (t >> 4);
        int r1 = r0 + 16;
        if (J.gather[ji]) {
            aRow0 = J.Af[ji] + (r0 & 127) * 2048 + (r0 >> 7) * 256;
            aRow1 = J.Af[ji] + (r1 & 127) * 2048 + (r1 >> 7) * 256;
        } else {
            aRow0 = J.Af[ji] + r0 * 256;
            aRow1 = J.Af[ji] + r1 * 256;
        }
    }

    uint4 pa[2], pw[4];
    float4 fa[2], fw[4];

    auto loadTile = [&](int kt) {
        if (AFP32) {
            int seg = t & 15;
            fa[0] = *(const float4*)&aRow0[kt + seg * 4];
            fa[1] = *(const float4*)&aRow1[kt + seg * 4];
        } else {
            const bf16* asrc = pl ? J.Alo[ji] : J.Ahi[ji];
            #pragma unroll
            for (int u = 0; u < 2; u++) {
                int c = ps + 128 * u;
                pa[u] = *(const uint4*)&asrc[(rowBase + (c >> 3)) * 256 + kt + (c & 7) * 8];
            }
        }
        if (WFP32) {
            #pragma unroll
            for (int u = 0; u < 4; u++) {
                int c = t + 256 * u;
                fw[u] = *(const float4*)&J.Wf[ji][(kt + (c >> 4)) * 256 + colBase + (c & 15) * 4];
            }
        } else {
            const bf16* wsrc = pl ? J.Wlo[ji] : J.Whi[ji];
            #pragma unroll
            for (int u = 0; u < 4; u++) {
                int c = ps + 128 * u;
                pw[u] = *(const uint4*)&wsrc[(kt + (c >> 3)) * 256 + colBase + (c & 7) * 8];
            }
        }
    };

    auto storeTile = [&](int bb) {
        if (AFP32) {
            uint2 hi, lo;
            int row = t >> 4, seg = t & 15;
            cvt4(fa[0], hi, lo);
            int off0 = bb * 2304 + row * 72 + seg * 4;
            *(uint2*)&sAhi[off0] = hi; *(uint2*)&sAlo[off0] = lo;
            cvt4(fa[1], hi, lo);
            int off1 = bb * 2304 + (row + 16) * 72 + seg * 4;
            *(uint2*)&sAhi[off1] = hi; *(uint2*)&sAlo[off1] = lo;
        } else {
            bf16* ad = pl ? sAlo : sAhi;
            #pragma unroll
            for (int u = 0; u < 2; u++) {
                int c = ps + 128 * u;
                *(uint4*)&ad[bb * 2304 + (c >> 3) * 72 + (c & 7) * 8] = pa[u];
            }
        }
        if (WFP32) {
            #pragma unroll
            for (int u = 0; u < 4; u++) {
                uint2 hi, lo;
                cvt4(fw[u], hi, lo);
                int c = t + 256 * u;
                int off = bb * 4608 + (c >> 4) * 72 + (c & 15) * 4;
                *(uint2*)&sWhi[off] = hi; *(uint2*)&sWlo[off] = lo;
            }
        } else {
            bf16* wd = pl ? sWlo : sWhi;
            #pragma unroll
            for (int u = 0; u < 4; u++) {
                int c = ps + 128 * u;
                *(uint4*)&wd[bb * 4608 + (c >> 3) * 72 + (c & 7) * 8] = pw[u];
            }
        }
    };

    // split accumulators: accH = Ah*Wh chain, accM = Ah*Wl + Al*Wh chain
    float accH[2][4], accM[2][4];
    #pragma unroll
    for (int nt = 0; nt < 2; nt++)
        #pragma unroll
        for (int i = 0; i < 4; i++) { accH[nt][i] = 0.0f; accM[nt][i] = 0.0f; }

    loadTile(0);
    storeTile(0);
    __syncthreads();

    #pragma unroll
    for (int it = 0; it < 4; it++) {
        int bb = it & 1;
        if (it < 3) loadTile((it + 1) * 64);

        #pragma unroll
        for (int ks = 0; ks < 64; ks += 16) {
            u32 ah[4], al[4], bh[4], bl[4];
            {
                int rowA = wm * 16 + r + ((g & 1) << 3);
                int kcol = ks + ((g >> 1) << 3);
                u32 off = (u32)(bb * 2304 + rowA * 72 + kcol) * 2;
                LDSM4(ah, sAhiB + off);
                LDSM4(al, sAloB + off);
            }
            {
                int krow = ks + r + ((g & 1) << 3);
                int ncol = wn * 16 + ((g >> 1) << 3);
                u32 off = (u32)(bb * 4608 + krow * 72 + ncol) * 2;
                LDSM4T(bh, sWhiB + off);
                LDSM4T(bl, sWloB + off);
            }
            #pragma unroll
            for (int nt = 0; nt < 2; nt++) {
                MMA16816(accH[nt], ah, (&bh[nt * 2]));
                MMA16816(accM[nt], ah, (&bl[nt * 2]));
                MMA16816(accM[nt], al, (&bh[nt * 2]));
            }
        }
        if (it < 3) {
            storeTile(1 - bb);
            __syncthreads();
        }
    }

    const float* bias = J.bias[ji];
    float scl = J.scale[ji];
    int sMode = J.storeMode[ji], act = J.act[ji];

    #pragma unroll
    for (int nt = 0; nt < 2; nt++) {
        int row0 = rowBase + wm * 16 + (lane >> 2);
        int col0 = colBase + wn * 16 + nt * 8 + (lane & 3) * 2;
        float bv0 = bias ? bias[col0] : 0.0f;
        float bv1 = bias ? bias[col0 + 1] : 0.0f;
        #pragma unroll
        for (int half = 0; half < 2; half++) {
            int row = row0 + half * 8;
            float v0 = (accH[nt][half * 2 + 0] + accM[nt][half * 2 + 0] + bv0) * scl;
            float v1 = (accH[nt][half * 2 + 1] + accM[nt][half * 2 + 1] + bv1) * scl;
            if (act) { v0 = gelu_tanh(v0); v1 = gelu_tanh(v1); }
            if (sMode == 0) {
                *(float2*)&J.Cf[ji][row * 256 + col0] = make_float2(v0, v1);
            } else if (sMode == 1) {
                u32 hi, lo;
                packP(v0, v1, hi, lo);
                *(u32*)&J.Chi[ji][row * 256 + col0] = hi;
                *(u32*)&J.Clo[ji][row * 256 + col0] = lo;
            } else {
                int b = row >> 7, n = row & 127;
                int h = col0 >> 5, dk = col0 & 31;
                int idx = (((b * 8 + h) * 128 + n) * 32) + dk;
                u32 hi, lo;
                packP(v0, v1, hi, lo);
                *(u32*)&J.Chi[ji][idx] = hi;
                *(u32*)&J.Clo[ji][idx] = lo;
            }
        }
    }
}

__global__ void __launch_bounds__(256) k_gemm_ff(Job6 J, ConnArgs CA) {
    extern __shared__ char smemRaw[];
    gemmBody<true, true>(J, CA, smemRaw);
}
__global__ void __launch_bounds__(256) k_gemm_pp(Job6 J, ConnArgs CA) {
    extern __shared__ char smemRaw[];
    gemmBody<false, false>(J, CA, smemRaw);
}
__global__ void __launch_bounds__(256) k_gemm_pf(Job6 J, ConnArgs CA) {
    extern __shared__ char smemRaw[];
    gemmBody<false, true>(J, CA, smemRaw);
}

// ---------------- conn job: 32i x 32j, 256 threads ---------------------------
__device__ void connJob(int cid, ConnArgs CA, char* smemRaw)
{
    float (*Aj)[33] = (float(*)[33])smemRaw;
    float (*Bi)[33] = (float(*)[33])(smemRaw + 32 * 33 * 4);
    float* Cs0 = (float*)(smemRaw + 2 * 32 * 33 * 4);
    float* Cs1 = Cs0 + 256;

    int h = cid >> 4;
    int ibase = ((cid >> 2) & 3) * 32;
    int jbase = (cid & 3) * 32;
    int t = threadIdx.x;
    int tx = t & 15, ty = t >> 4;

    Cs0[t] = CA.fccw[2 * t];
    Cs1[t] = CA.fccw[2 * t + 1];

    float l0[2][2] = {{0.f, 0.f}, {0.f, 0.f}};
    float l1[2][2] = {{0.f, 0.f}, {0.f, 0.f}};

    for (int d0 = 0; d0 < 256; d0 += 32) {
        if (d0) __syncthreads();
        int jr = t >> 3, c = (t & 7) * 4;
        float4 va = *(const float4*)&g_fA[(h * 128 + jbase + jr) * 256 + d0 + c];
        Aj[jr][c] = va.x; Aj[jr][c + 1] = va.y; Aj[jr][c + 2] = va.z; Aj[jr][c + 3] = va.w;
        float4 vb = *(const float4*)&g_fB[(h * 128 + ibase + jr) * 256 + d0 + c];
        float4 o = *(const float4*)&CA.fcb[d0 + c];
        Bi[jr][c] = vb.x + o.x; Bi[jr][c + 1] = vb.y + o.y;
        Bi[jr][c + 2] = vb.z + o.z; Bi[jr][c + 3] = vb.w + o.w;
        __syncthreads();

        #pragma unroll
        for (int dd = 0; dd < 32; dd++) {
            float a0 = Aj[tx * 2][dd], a1 = Aj[tx * 2 + 1][dd];
            float b0 = Bi[ty * 2][dd], b1 = Bi[ty * 2 + 1][dd];
            float c0v = Cs0[d0 + dd], c1v = Cs1[d0 + dd];
            float r00 = fmaxf(a0 + b0, 0.f), r10 = fmaxf(a1 + b0, 0.f);
            float r01 = fmaxf(a0 + b1, 0.f), r11 = fmaxf(a1 + b1, 0.f);
            l0[0][0] = fmaf(r00, c0v, l0[0][0]); l1[0][0] = fmaf(r00, c1v, l1[0][0]);
            l0[0][1] = fmaf(r10, c0v, l0[0][1]); l1[0][1] = fmaf(r10, c1v, l1[0][1]);
            l0[1][0] = fmaf(r01, c0v, l0[1][0]); l1[1][0] = fmaf(r01, c1v, l1[1][0]);
            l0[1][1] = fmaf(r11, c0v, l0[1][1]); l1[1][1] = fmaf(r11, c1v, l1[1][1]);
        }
    }

    float cb0 = CA.fccb[0], cb1 = CA.fccb[1];
    #pragma unroll
    for (int ii = 0; ii < 2; ii++) {
        int i = ibase + ty * 2 + ii;
        #pragma unroll
        for (int jj = 0; jj < 2; jj++) {
            int j = jbase + tx * 2 + jj;
            int idx = (h * 128 + i) * 128 + j;
            float2 u2 = *(const float2*)&CA.gu[idx * 2];
            float gg0 = -logf(-logf(u2.x + 1e-10f) + 1e-10f);
            float gg1 = -logf(-logf(u2.y + 1e-10f) + 1e-10f);
            g_conn[idx] = ((l1[ii][jj] + cb1 + gg1) > (l0[ii][jj] + cb0 + gg0)) ? 1.0f : 0.0f;
        }
    }
}

// ---------------- attention-only kernel: one CTA per (b,h), 256 threads ------
#define ATTN_SMEM (61440 + 2048)

__global__ void __launch_bounds__(256)
k_attn()
{
    extern __shared__ char sm[];
    u32 smB = (u32)__cvta_generic_to_shared(sm);
    bf16* planes = (bf16*)sm;                // 6 x [128*40]
    u32* cmask = (u32*)(sm + 61440);
    u32 sQhiB = smB, sQloB = smB + 10240;
    u32 sKhiB = smB + 20480, sKloB = smB + 30720;
    u32 sVhiB = smB + 40960, sVloB = smB + 51200;

    int bid = blockIdx.x;
    int b = bid >> 3, h = bid & 7;
    int t = threadIdx.x;
    int warp = t >> 5, lane = t & 31;
    int g = lane >> 3, r = lane & 7;

    // conn bitmask
    {
        const float* cr = g_conn + h * 16384;
        for (int i0b = 0; i0b < 128; i0b += 2) {
            int i0 = i0b + (warp >> 2);
            float c = cr[i0 * 128 + (warp & 3) * 32 + lane];
            u32 bal = __ballot_sync(0xffffffffu, c > 0.5f);
            if (lane == 0) cmask[i0 * 4 + (warp & 3)] = bal;
        }
    }

    // stage Q/K/V planes
    {
        int gbase = bid * 4096;
        #pragma unroll
        for (int u = 0; u < 12; u++) {
            int c = t + u * 256;
            int plane = c >> 9;
            int i = c & 511;
            int row = i >> 2, seg = i & 3;
            int op = plane >> 1;
            const bf16* src = (plane & 1) ? (g_qkvlo + op * 1048576)
                                          : (g_qkvhi + op * 1048576);
            int pidx = op * 2 + (plane & 1);
            *(uint4*)&planes[pidx * 5120 + row * 40 + seg * 8] =
                *(const uint4*)&src[gbase + row * 32 + seg * 8];
        }
    }
    __syncthreads();

    u32 aQh[2][4], aQl[2][4];
    #pragma unroll
    for (int kt = 0; kt < 2; kt++) {
        int rowA = warp * 16 + r + ((g & 1) << 3);
        int kcol = kt * 16 + ((g >> 1) << 3);
        u32 off = (u32)(rowA * 40 + kcol) * 2;
        LDSM4(aQh[kt], sQhiB + off);
        LDSM4(aQl[kt], sQloB + off);
    }

    float accS[16][4];
    #pragma unroll
    for (int nt = 0; nt < 16; nt++)
        #pragma unroll
        for (int i = 0; i < 4; i++) accS[nt][i] = 0.0f;

    #pragma unroll
    for (int kt = 0; kt < 2; kt++) {
        #pragma unroll
        for (int ng = 0; ng < 8; ng++) {
            u32 kbh[4], kbl[4];
            int nrow = ng * 16 + r + ((g & 1) << 3);
            int kcol = kt * 16 + ((g >> 1) << 3);
            u32 off = (u32)(nrow * 40 + kcol) * 2;
            LDSM4(kbh, sKhiB + off);
            LDSM4(kbl, sKloB + off);
            u32 b0h[2] = {kbh[0], kbh[2]}, b1h[2] = {kbh[1], kbh[3]};
            u32 b0l[2] = {kbl[0], kbl[2]}, b1l[2] = {kbl[1], kbl[3]};
            MMA16816(accS[ng * 2], aQh[kt], b0h);
            MMA16816(accS[ng * 2], aQh[kt], b0l);
            MMA16816(accS[ng * 2], aQl[kt], b0h);
            MMA16816(accS[ng * 2 + 1], aQh[kt], b1h);
            MMA16816(accS[ng * 2 + 1], aQh[kt], b1l);
            MMA16816(accS[ng * 2 + 1], aQl[kt], b1h);
        }
    }

    int rA = warp * 16 + (lane >> 2);
    int rB = rA + 8;
    u32 mA[4], mB[4];
    #pragma unroll
    for (int w2 = 0; w2 < 4; w2++) { mA[w2] = cmask[rA * 4 + w2]; mB[w2] = cmask[rB * 4 + w2]; }
    #pragma unroll
    for (int nt = 0; nt < 16; nt++) {
        int c0 = nt * 8 + (lane & 3) * 2;
        int w2 = c0 >> 5, bit = c0 & 31;
        if (!((mA[w2] >> bit) & 1u))       accS[nt][0] = -INFINITY;
        if (!((mA[w2] >> (bit + 1)) & 1u)) accS[nt][1] = -INFINITY;
        if (!((mB[w2] >> bit) & 1u))       accS[nt][2] = -INFINITY;
        if (!((mB[w2] >> (bit + 1)) & 1u)) accS[nt][3] = -INFINITY;
    }

    float mxA = -INFINITY, mxB = -INFINITY;
    #pragma unroll
    for (int nt = 0; nt < 16; nt++) {
        mxA = fmaxf(mxA, fmaxf(accS[nt][0], accS[nt][1]));
        mxB = fmaxf(mxB, fmaxf(accS[nt][2], accS[nt][3]));
    }
    mxA = fmaxf(mxA, __shfl_xor_sync(0xffffffffu, mxA, 1));
    mxA = fmaxf(mxA, __shfl_xor_sync(0xffffffffu, mxA, 2));
    mxB = fmaxf(mxB, __shfl_xor_sync(0xffffffffu, mxB, 1));
    mxB = fmaxf(mxB, __shfl_xor_sync(0xffffffffu, mxB, 2));

    float sA = 0.0f, sB = 0.0f;
    #pragma unroll
    for (int nt = 0; nt < 16; nt++) {
        accS[nt][0] = expf(accS[nt][0] - mxA);
        accS[nt][1] = expf(accS[nt][1] - mxA);
        accS[nt][2] = expf(accS[nt][2] - mxB);
        accS[nt][3] = expf(accS[nt][3] - mxB);
        sA += accS[nt][0] + accS[nt][1];
        sB += accS[nt][2] + accS[nt][3];
    }
    sA += __shfl_xor_sync(0xffffffffu, sA, 1);
    sA += __shfl_xor_sync(0xffffffffu, sA, 2);
    sB += __shfl_xor_sync(0xffffffffu, sB, 1);
    sB += __shfl_xor_sync(0xffffffffu, sB, 2);
    float invA = 1.0f / sA, invB = 1.0f / sB;

    float accO[4][4];
    #pragma unroll
    for (int nt = 0; nt < 4; nt++)
        #pragma unroll
        for (int i = 0; i < 4; i++) accO[nt][i] = 0.0f;

    #pragma unroll
    for (int kt = 0; kt < 8; kt++) {
        u32 ph[4], plo[4];
        packP(accS[2 * kt][0],     accS[2 * kt][1],     ph[0], plo[0]);
        packP(accS[2 * kt][2],     accS[2 * kt][3],     ph[1], plo[1]);
        packP(accS[2 * kt + 1][0], accS[2 * kt + 1][1], ph[2], plo[2]);
        packP(accS[2 * kt + 1][2], accS[2 * kt + 1][3], ph[3], plo[3]);
        #pragma unroll
        for (int n16 = 0; n16 < 2; n16++) {
            u32 vbh[4], vbl[4];
            int krow = kt * 16 + r + ((g & 1) << 3);
            int ncol = n16 * 16 + ((g >> 1) << 3);
            u32 off = (u32)(krow * 40 + ncol) * 2;
            LDSM4T(vbh, sVhiB + off);
            LDSM4T(vbl, sVloB + off);
            MMA16816(accO[n16 * 2], ph, (&vbh[0]));
            MMA16816(accO[n16 * 2], ph, (&vbl[0]));
            MMA16816(accO[n16 * 2], plo, (&vbh[0]));
            MMA16816(accO[n16 * 2 + 1], ph, (&vbh[2]));
            MMA16816(accO[n16 * 2 + 1], ph, (&vbl[2]));
            MMA16816(accO[n16 * 2 + 1], plo, (&vbh[2]));
        }
    }

    #pragma unroll
    for (int nt = 0; nt < 4; nt++) {
        int c0 = nt * 8 + (lane & 3) * 2;
        int oA = (b * 128 + rA) * 256 + h * 32 + c0;
        int oB = (b * 128 + rB) * 256 + h * 32 + c0;
        u32 hi, lo;
        packP(accO[nt][0] * invA, accO[nt][1] * invA, hi, lo);
        *(u32*)&g_aohi[oA] = hi; *(u32*)&g_aolo[oA] = lo;
        packP(accO[nt][2] * invB, accO[nt][3] * invB, hi, lo);
        *(u32*)&g_aohi[oB] = hi; *(u32*)&g_aolo[oB] = lo;
    }
}

// ---------------- launch ------------------------------------------------------
extern "C" void kernel_launch(void* const* d_in, const int* in_sizes, int n_in,
                              void* d_out, int out_size)
{
    const float* x        = (const float*)d_in[0];
    const float* gumbel_u = (const float*)d_in[1];
    const float* memory_w = (const float*)d_in[2];
    const float* fc_out_w = (const float*)d_in[3];
    const float* fc_out_b = (const float*)d_in[4];
    const float* fc_cat_w = (const float*)d_in[5];
    const float* fc_cat_b = (const float*)d_in[6];
    const float* wq       = (const float*)d_in[7];
    const float* bq       = (const float*)d_in[8];
    const float* wk       = (const float*)d_in[9];
    const float* bk       = (const float*)d_in[10];
    const float* wv       = (const float*)d_in[11];
    const float* bv       = (const float*)d_in[12];
    const float* out_w    = (const float*)d_in[13];
    const float* out_b    = (const float*)d_in[14];
    const float* mlp_w1   = (const float*)d_in[15];
    const float* mlp_b1   = (const float*)d_in[16];
    const float* mlp_w2   = (const float*)d_in[17];
    const float* mlp_b2   = (const float*)d_in[18];

    float *fA, *fB, *cb;
    cudaGetSymbolAddress((void**)&fA, g_fA);
    cudaGetSymbolAddress((void**)&fB, g_fB);
    cudaGetSymbolAddress((void**)&cb, g_cb);
    bf16 *cwhi, *cwlo, *h1hi, *h1lo, *qkvhi, *qkvlo, *aohi, *aolo;
    cudaGetSymbolAddress((void**)&cwhi, g_cwhi);
    cudaGetSymbolAddress((void**)&cwlo, g_cwlo);
    cudaGetSymbolAddress((void**)&h1hi, g_h1hi);
    cudaGetSymbolAddress((void**)&h1lo, g_h1lo);
    cudaGetSymbolAddress((void**)&qkvhi, g_qkvhi);
    cudaGetSymbolAddress((void**)&qkvlo, g_qkvlo);
    cudaGetSymbolAddress((void**)&aohi, g_aohi);
    cudaGetSymbolAddress((void**)&aolo, g_aolo);

    static bool attrSet = false;
    if (!attrSet) {
        cudaFuncSetAttribute(k_attn, cudaFuncAttributeMaxDynamicSharedMemorySize, ATTN_SMEM);
        cudaFuncSetAttribute(k_gemm_ff, cudaFuncAttributeMaxDynamicSharedMemorySize, GEMM_SMEM);
        cudaFuncSetAttribute(k_gemm_pp, cudaFuncAttributeMaxDynamicSharedMemorySize, GEMM_SMEM);
        cudaFuncSetAttribute(k_gemm_pf, cudaFuncAttributeMaxDynamicSharedMemorySize, GEMM_SMEM);
        attrSet = true;
    }

    ConnArgs CA = { fc_out_b, fc_cat_w, fc_cat_b, gumbel_u,
                    mlp_b2, wq, wk, wv, bq, bk, bv };

    // L1: fA(128) + fB(128) + mlp1(512) + compose(3x32) + bias(3) = 867
    {
        Job6 J = {};
        J.Af[0] = memory_w; J.Wf[0] = fc_out_w;
        J.Cf[0] = fA; J.scale[0] = 1.0f; J.gather[0] = 1; J.end[0] = 128;
        J.Af[1] = memory_w; J.Wf[1] = fc_out_w + 65536;
        J.Cf[1] = fB; J.scale[1] = 1.0f; J.gather[1] = 1; J.end[1] = 256;
        J.Af[2] = x; J.Wf[2] = mlp_w1; J.bias[2] = mlp_b1;
        J.Chi[2] = h1hi; J.Clo[2] = h1lo;
        J.scale[2] = 1.0f; J.act[2] = 1; J.storeMode[2] = 1; J.end[2] = 768;
        const float* wz[3] = { wq, wk, wv };
        for (int z = 0; z < 3; z++) {
            int ji = 3 + z;
            J.Af[ji] = mlp_w2; J.Wf[ji] = wz[z];
            J.Chi[ji] = cwhi + z * 65536; J.Clo[ji] = cwlo + z * 65536;
            J.scale[ji] = 1.0f; J.storeMode[ji] = 1; J.end[ji] = 768 + (z + 1) * 32;
        }
        J.totTiles = 864; J.nconn = 0;
        k_gemm_ff<<<867, 256, GEMM_SMEM>>>(J, CA);
    }

    // L2: QKV (3x512, per-head plane store) + conn(128) = 1664
    {
        Job6 J = {};
        const float scale = 0.17677669529663687f;  // 1/sqrt(32)
        for (int z = 0; z < 3; z++) {
            J.Ahi[z] = h1hi; J.Alo[z] = h1lo;
            J.Whi[z] = cwhi + z * 65536; J.Wlo[z] = cwlo + z * 65536;
            J.bias[z] = cb + z * 256;
            J.Chi[z] = qkvhi + z * 1048576; J.Clo[z] = qkvlo + z * 1048576;
            J.scale[z] = (z == 0) ? scale : 1.0f;
            J.storeMode[z] = 2;
            J.end[z] = (z + 1) * 512;
        }
        J.end[3] = J.end[4] = J.end[5] = 1536;
        J.totTiles = 1536; J.nconn = 128;
        k_gemm_pp<<<1664, 256, GEMM_SMEM>>>(J, CA);
    }

    // L3: attention (256 CTAs, one per (b,h))
    k_attn<<<256, 256, ATTN_SMEM>>>();

    // L4: output projection -> d_out (512; A = ao planes, W = out_w fp32)
    {
        Job6 J = {};
        J.Ahi[0] = aohi; J.Alo[0] = aolo; J.Wf[0] = out_w;
        J.bias[0] = out_b; J.Cf[0] = (float*)d_out;
        J.scale[0] = 1.0f; J.end[0] = 512;
        J.end[1] = J.end[2] = J.end[3] = J.end[4] = J.end[5] = 512;
        J.totTiles = 512; J.nconn = 0;
        k_gemm_pf<<<512, 256, GEMM_SMEM>>>(J, CA);
    }
}

// round 13
// speedup vs baseline: 1.2388x; 1.1092x over previous
#include <cuda_runtime.h>
#include <cuda_bf16.h>
#include <math.h>

// Problem constants: B=32, N=128, D=256, H=8, DK=32
typedef unsigned int u32;
typedef __nv_bfloat16 bf16;

// ---------------- scratch (static device globals; no allocation) -------------
__device__ __align__(16) float g_fA[1024 * 256];
__device__ __align__(16) float g_fB[1024 * 256];
__device__ __align__(16) u32 g_cmask[8 * 128 * 4];       // conn bitmask [h][i][4 words]
__device__ __align__(16) float g_cb[3 * 256];            // composed QKV biases
__device__ __align__(16) bf16 g_cwhi[3 * 65536];         // composed W2@W{q,k,v}
__device__ __align__(16) bf16 g_cwlo[3 * 65536];
__device__ __align__(16) bf16 g_h1hi[4096 * 256];
__device__ __align__(16) bf16 g_h1lo[4096 * 256];
__device__ __align__(16) bf16 g_qkvhi[3 * 1048576];      // [op][B,H,N,DK] planes
__device__ __align__(16) bf16 g_qkvlo[3 * 1048576];
__device__ __align__(16) bf16 g_aohi[4096 * 256];
__device__ __align__(16) bf16 g_aolo[4096 * 256];

#define GEMM_SMEM 55296     // BM32/BK64 variant
#define GEMM64_SMEM 73728   // BM64/BN64/BK64 variant: 4 arrays x 2buf x 4608 bf16
#define ATTN_SMEM 61440

__device__ __forceinline__ float gelu_tanh(float x) {
    float x3 = x * x * x;
    float t = tanhf(0.7978845608028654f * (x + 0.044715f * x3));
    return 0.5f * x * (1.0f + t);
}

__device__ __forceinline__ void split_bf16(float v, bf16& h, bf16& l) {
    h = __float2bfloat16_rn(v);
    l = __float2bfloat16_rn(v - __bfloat162float(h));
}

__device__ __forceinline__ void cvt4(float4 v, uint2& hi, uint2& lo) {
    bf16 h0, l0, h1, l1, h2, l2, h3, l3;
    split_bf16(v.x, h0, l0); split_bf16(v.y, h1, l1);
    split_bf16(v.z, h2, l2); split_bf16(v.w, h3, l3);
    __nv_bfloat162 a, b, c, d;
    a.x = h0; a.y = h1; b.x = h2; b.y = h3;
    c.x = l0; c.y = l1; d.x = l2; d.y = l3;
    hi.x = *(u32*)&a; hi.y = *(u32*)&b;
    lo.x = *(u32*)&c; lo.y = *(u32*)&d;
}

__device__ __forceinline__ void packP(float x, float y, u32& hi, u32& lo) {
    bf16 hx, lx, hy, ly;
    split_bf16(x, hx, lx);
    split_bf16(y, hy, ly);
    __nv_bfloat162 H; H.x = hx; H.y = hy;
    __nv_bfloat162 L; L.x = lx; L.y = ly;
    hi = *(u32*)&H; lo = *(u32*)&L;
}

#define LDSM4(r, addr)                                                        \
    asm volatile("ldmatrix.sync.aligned.m8n8.x4.shared.b16 {%0,%1,%2,%3}, [%4];" \
                 : "=r"(r[0]), "=r"(r[1]), "=r"(r[2]), "=r"(r[3]) : "r"(addr))

#define LDSM4T(r, addr)                                                       \
    asm volatile("ldmatrix.sync.aligned.m8n8.x4.trans.shared.b16 {%0,%1,%2,%3}, [%4];" \
                 : "=r"(r[0]), "=r"(r[1]), "=r"(r[2]), "=r"(r[3]) : "r"(addr))

#define MMA16816(d, a, b)                                                     \
    asm volatile("mma.sync.aligned.m16n8k16.row.col.f32.bf16.bf16.f32 "       \
                 "{%0,%1,%2,%3}, {%4,%5,%6,%7}, {%8,%9}, {%0,%1,%2,%3};"      \
                 : "+f"(d[0]), "+f"(d[1]), "+f"(d[2]), "+f"(d[3])             \
                 : "r"(a[0]), "r"(a[1]), "r"(a[2]), "r"(a[3]),                \
                   "r"(b[0]), "r"(b[1]))

// ---------------- job table --------------------------------------------------
struct Job6 {
    const float* Af[6];
    const bf16 *Ahi[6], *Alo[6];
    const float* Wf[6];
    const bf16 *Whi[6], *Wlo[6];
    const float* bias[6];
    float* Cf[6];
    bf16 *Chi[6], *Clo[6];
    float scale[6];
    int gather[6], act[6], storeMode[6];   // storeMode: 0 fp32, 1 planes, 2 QKV
    int end[6];
    int totTiles, nconn;
};

struct ConnArgs {
    const float *fcb, *fccw, *fccb, *gu;
    const float *b2, *wq, *wk, *wv, *bq, *bk, *bv;
};

__device__ void connJob(int cid, ConnArgs CA, char* smemRaw);

__device__ void biasJob(int z, ConnArgs CA) {
    int c = threadIdx.x;
    const float* wz = (z == 0) ? CA.wq : (z == 1) ? CA.wk : CA.wv;
    const float* bz = (z == 0) ? CA.bq : (z == 1) ? CA.bk : CA.bv;
    float acc = bz[c];
    for (int d = 0; d < 256; d++)
        acc = fmaf(CA.b2[d], wz[d * 256 + c], acc);
    g_cb[z * 256 + c] = acc;
}

// ---------------- GEMM-32: BM=32, BN=64, BK=64 (fp32/plane variants) ---------
template <bool AFP32, bool WFP32>
__device__ __forceinline__ void gemmBody(const Job6& J, const ConnArgs& CA, char* smemRaw)
{
    int jid = blockIdx.x;
    if (jid >= J.totTiles) {
        int e = jid - J.totTiles;
        if (e < J.nconn) connJob(e, CA, smemRaw);
        else biasJob(e - J.nconn, CA);
        return;
    }
    int ji = 0;
    #pragma unroll
    for (int k = 0; k < 5; k++) if (jid >= J.end[k]) ji = k + 1;
    int tile = jid - (ji ? J.end[ji - 1] : 0);

    bf16* sAhi = (bf16*)smemRaw;             // [2][2304]
    bf16* sAlo = sAhi + 2 * 2304;
    bf16* sWhi = sAlo + 2 * 2304;            // [2][4608]
    bf16* sWlo = sWhi + 2 * 4608;

    int rowBase = (tile >> 2) * 32;
    int colBase = (tile & 3) * 64;

    int t = threadIdx.x;
    int warp = t >> 5, lane = t & 31;
    int wm = warp >> 2, wn = warp & 3;
    int g = lane >> 3, r = lane & 7;

    u32 sAhiB = (u32)__cvta_generic_to_shared(sAhi);
    u32 sAloB = (u32)__cvta_generic_to_shared(sAlo);
    u32 sWhiB = (u32)__cvta_generic_to_shared(sWhi);
    u32 sWloB = (u32)__cvta_generic_to_shared(sWlo);

    int pl = t >> 7, ps = t & 127;

    const float* aRow0 = nullptr;
    const float* aRow1 = nullptr;
    if (AFP32) {
        int r0 = rowBase + (t >> 4);
        int r1 = r0 + 16;
        if (J.gather[ji]) {
            aRow0 = J.Af[ji] + (r0 & 127) * 2048 + (r0 >> 7) * 256;
            aRow1 = J.Af[ji] + (r1 & 127) * 2048 + (r1 >> 7) * 256;
        } else {
            aRow0 = J.Af[ji] + r0 * 256;
            aRow1 = J.Af[ji] + r1 * 256;
        }
    }

    uint4 pa[2], pw[4];
    float4 fa[2], fw[4];

    auto loadTile = [&](int kt) {
        if (AFP32) {
            int seg = t & 15;
            fa[0] = *(const float4*)&aRow0[kt + seg * 4];
            fa[1] = *(const float4*)&aRow1[kt + seg * 4];
        } else {
            const bf16* asrc = pl ? J.Alo[ji] : J.Ahi[ji];
            #pragma unroll
            for (int u = 0; u < 2; u++) {
                int c = ps + 128 * u;
                pa[u] = *(const uint4*)&asrc[(rowBase + (c >> 3)) * 256 + kt + (c & 7) * 8];
            }
        }
        if (WFP32) {
            #pragma unroll
            for (int u = 0; u < 4; u++) {
                int c = t + 256 * u;
                fw[u] = *(const float4*)&J.Wf[ji][(kt + (c >> 4)) * 256 + colBase + (c & 15) * 4];
            }
        } else {
            const bf16* wsrc = pl ? J.Wlo[ji] : J.Whi[ji];
            #pragma unroll
            for (int u = 0; u < 4; u++) {
                int c = ps + 128 * u;
                pw[u] = *(const uint4*)&wsrc[(kt + (c >> 3)) * 256 + colBase + (c & 7) * 8];
            }
        }
    };

    auto storeTile = [&](int bb) {
        if (AFP32) {
            uint2 hi, lo;
            int row = t >> 4, seg = t & 15;
            cvt4(fa[0], hi, lo);
            int off0 = bb * 2304 + row * 72 + seg * 4;
            *(uint2*)&sAhi[off0] = hi; *(uint2*)&sAlo[off0] = lo;
            cvt4(fa[1], hi, lo);
            int off1 = bb * 2304 + (row + 16) * 72 + seg * 4;
            *(uint2*)&sAhi[off1] = hi; *(uint2*)&sAlo[off1] = lo;
        } else {
            bf16* ad = pl ? sAlo : sAhi;
            #pragma unroll
            for (int u = 0; u < 2; u++) {
                int c = ps + 128 * u;
                *(uint4*)&ad[bb * 2304 + (c >> 3) * 72 + (c & 7) * 8] = pa[u];
            }
        }
        if (WFP32) {
            #pragma unroll
            for (int u = 0; u < 4; u++) {
                uint2 hi, lo;
                cvt4(fw[u], hi, lo);
                int c = t + 256 * u;
                int off = bb * 4608 + (c >> 4) * 72 + (c & 15) * 4;
                *(uint2*)&sWhi[off] = hi; *(uint2*)&sWlo[off] = lo;
            }
        } else {
            bf16* wd = pl ? sWlo : sWhi;
            #pragma unroll
            for (int u = 0; u < 4; u++) {
                int c = ps + 128 * u;
                *(uint4*)&wd[bb * 4608 + (c >> 3) * 72 + (c & 7) * 8] = pw[u];
            }
        }
    };

    float accH[2][4], accM[2][4];
    #pragma unroll
    for (int nt = 0; nt < 2; nt++)
        #pragma unroll
        for (int i = 0; i < 4; i++) { accH[nt][i] = 0.0f; accM[nt][i] = 0.0f; }

    loadTile(0);
    storeTile(0);
    __syncthreads();

    #pragma unroll
    for (int it = 0; it < 4; it++) {
        int bb = it & 1;
        if (it < 3) loadTile((it + 1) * 64);

        #pragma unroll
        for (int ks = 0; ks < 64; ks += 16) {
            u32 ah[4], al[4], bh[4], bl[4];
            {
                int rowA = wm * 16 + r + ((g & 1) << 3);
                int kcol = ks + ((g >> 1) << 3);
                u32 off = (u32)(bb * 2304 + rowA * 72 + kcol) * 2;
                LDSM4(ah, sAhiB + off);
                LDSM4(al, sAloB + off);
            }
            {
                int krow = ks + r + ((g & 1) << 3);
                int ncol = wn * 16 + ((g >> 1) << 3);
                u32 off = (u32)(bb * 4608 + krow * 72 + ncol) * 2;
                LDSM4T(bh, sWhiB + off);
                LDSM4T(bl, sWloB + off);
            }
            #pragma unroll
            for (int nt = 0; nt < 2; nt++) {
                MMA16816(accH[nt], ah, (&bh[nt * 2]));
                MMA16816(accM[nt], ah, (&bl[nt * 2]));
                MMA16816(accM[nt], al, (&bh[nt * 2]));
            }
        }
        if (it < 3) {
            storeTile(1 - bb);
            __syncthreads();
        }
    }

    const float* bias = J.bias[ji];
    float scl = J.scale[ji];
    int sMode = J.storeMode[ji], act = J.act[ji];

    #pragma unroll
    for (int nt = 0; nt < 2; nt++) {
        int row0 = rowBase + wm * 16 + (lane >> 2);
        int col0 = colBase + wn * 16 + nt * 8 + (lane & 3) * 2;
        float bv0 = bias ? bias[col0] : 0.0f;
        float bv1 = bias ? bias[col0 + 1] : 0.0f;
        #pragma unroll
        for (int half = 0; half < 2; half++) {
            int row = row0 + half * 8;
            float v0 = (accH[nt][half * 2 + 0] + accM[nt][half * 2 + 0] + bv0) * scl;
            float v1 = (accH[nt][half * 2 + 1] + accM[nt][half * 2 + 1] + bv1) * scl;
            if (act) { v0 = gelu_tanh(v0); v1 = gelu_tanh(v1); }
            if (sMode == 0) {
                *(float2*)&J.Cf[ji][row * 256 + col0] = make_float2(v0, v1);
            } else if (sMode == 1) {
                u32 hi, lo;
                packP(v0, v1, hi, lo);
                *(u32*)&J.Chi[ji][row * 256 + col0] = hi;
                *(u32*)&J.Clo[ji][row * 256 + col0] = lo;
            } else {
                int b = row >> 7, n = row & 127;
                int h = col0 >> 5, dk = col0 & 31;
                int idx = (((b * 8 + h) * 128 + n) * 32) + dk;
                u32 hi, lo;
                packP(v0, v1, hi, lo);
                *(u32*)&J.Chi[ji][idx] = hi;
                *(u32*)&J.Clo[ji][idx] = lo;
            }
        }
    }
}

__global__ void __launch_bounds__(256) k_gemm_ff(Job6 J, ConnArgs CA) {
    extern __shared__ char smemRaw[];
    gemmBody<true, true>(J, CA, smemRaw);
}
__global__ void __launch_bounds__(256) k_gemm_pf(Job6 J, ConnArgs CA) {
    extern __shared__ char smemRaw[];
    gemmBody<false, true>(J, CA, smemRaw);
}

// ---------------- GEMM-64: BM=64, BN=64, BK=64, planes x planes --------------
// 8 warps as 4(m) x 2(n); warp tile 16x32.
__global__ void __launch_bounds__(256)
k_gemm64(Job6 J, ConnArgs CA)
{
    extern __shared__ char smemRaw[];
    int jid = blockIdx.x;
    if (jid >= J.totTiles) { connJob(jid - J.totTiles, CA, smemRaw); return; }

    int ji = 0;
    #pragma unroll
    for (int k = 0; k < 5; k++) if (jid >= J.end[k]) ji = k + 1;
    int tile = jid - (ji ? J.end[ji - 1] : 0);

    bf16* sAhi = (bf16*)smemRaw;             // [2][4608] each
    bf16* sAlo = sAhi + 2 * 4608;
    bf16* sWhi = sAlo + 2 * 4608;
    bf16* sWlo = sWhi + 2 * 4608;

    int rowBase = (tile >> 2) * 64;
    int colBase = (tile & 3) * 64;

    int t = threadIdx.x;
    int warp = t >> 5, lane = t & 31;
    int wm = warp >> 1, wn = warp & 1;
    int g = lane >> 3, r = lane & 7;

    u32 sAhiB = (u32)__cvta_generic_to_shared(sAhi);
    u32 sAloB = (u32)__cvta_generic_to_shared(sAlo);
    u32 sWhiB = (u32)__cvta_generic_to_shared(sWhi);
    u32 sWloB = (u32)__cvta_generic_to_shared(sWlo);

    int pl = t >> 7, ps = t & 127;

    uint4 pa[4], pw[4];

    auto loadTile = [&](int kt) {
        const bf16* asrc = pl ? J.Alo[ji] : J.Ahi[ji];
        const bf16* wsrc = pl ? J.Wlo[ji] : J.Whi[ji];
        #pragma unroll
        for (int u = 0; u < 4; u++) {
            int c = ps + 128 * u;           // 0..511
            int row = c >> 3, seg = c & 7;
            pa[u] = *(const uint4*)&asrc[(rowBase + row) * 256 + kt + seg * 8];
            pw[u] = *(const uint4*)&wsrc[(kt + row) * 256 + colBase + seg * 8];
        }
    };

    auto storeTile = [&](int bb) {
        bf16* ad = pl ? sAlo : sAhi;
        bf16* wd = pl ? sWlo : sWhi;
        #pragma unroll
        for (int u = 0; u < 4; u++) {
            int c = ps + 128 * u;
            int off = bb * 4608 + (c >> 3) * 72 + (c & 7) * 8;
            *(uint4*)&ad[off] = pa[u];
            *(uint4*)&wd[off] = pw[u];
        }
    };

    float accH[4][4], accM[4][4];
    #pragma unroll
    for (int nt = 0; nt < 4; nt++)
        #pragma unroll
        for (int i = 0; i < 4; i++) { accH[nt][i] = 0.0f; accM[nt][i] = 0.0f; }

    loadTile(0);
    storeTile(0);
    __syncthreads();

    #pragma unroll
    for (int it = 0; it < 4; it++) {
        int bb = it & 1;
        if (it < 3) loadTile((it + 1) * 64);

        #pragma unroll
        for (int ks = 0; ks < 64; ks += 16) {
            u32 ah[4], al[4];
            {
                int rowA = wm * 16 + r + ((g & 1) << 3);
                int kcol = ks + ((g >> 1) << 3);
                u32 off = (u32)(bb * 4608 + rowA * 72 + kcol) * 2;
                LDSM4(ah, sAhiB + off);
                LDSM4(al, sAloB + off);
            }
            #pragma unroll
            for (int n16 = 0; n16 < 2; n16++) {
                u32 bh[4], bl[4];
                int krow = ks + r + ((g & 1) << 3);
                int ncol = wn * 32 + n16 * 16 + ((g >> 1) << 3);
                u32 off = (u32)(bb * 4608 + krow * 72 + ncol) * 2;
                LDSM4T(bh, sWhiB + off);
                LDSM4T(bl, sWloB + off);
                MMA16816(accH[n16 * 2], ah, (&bh[0]));
                MMA16816(accM[n16 * 2], ah, (&bl[0]));
                MMA16816(accM[n16 * 2], al, (&bh[0]));
                MMA16816(accH[n16 * 2 + 1], ah, (&bh[2]));
                MMA16816(accM[n16 * 2 + 1], ah, (&bl[2]));
                MMA16816(accM[n16 * 2 + 1], al, (&bh[2]));
            }
        }
        if (it < 3) {
            storeTile(1 - bb);
            __syncthreads();
        }
    }

    const float* bias = J.bias[ji];
    float scl = J.scale[ji];
    int sMode = J.storeMode[ji];

    #pragma unroll
    for (int nt = 0; nt < 4; nt++) {
        int row0 = rowBase + wm * 16 + (lane >> 2);
        int col0 = colBase + wn * 32 + nt * 8 + (lane & 3) * 2;
        float bv0 = bias ? bias[col0] : 0.0f;
        float bv1 = bias ? bias[col0 + 1] : 0.0f;
        #pragma unroll
        for (int half = 0; half < 2; half++) {
            int row = row0 + half * 8;
            float v0 = (accH[nt][half * 2 + 0] + accM[nt][half * 2 + 0] + bv0) * scl;
            float v1 = (accH[nt][half * 2 + 1] + accM[nt][half * 2 + 1] + bv1) * scl;
            u32 hi, lo;
            packP(v0, v1, hi, lo);
            if (sMode == 1) {
                *(u32*)&J.Chi[ji][row * 256 + col0] = hi;
                *(u32*)&J.Clo[ji][row * 256 + col0] = lo;
            } else {
                int b = row >> 7, n = row & 127;
                int h = col0 >> 5, dk = col0 & 31;
                int idx = (((b * 8 + h) * 128 + n) * 32) + dk;
                *(u32*)&J.Chi[ji][idx] = hi;
                *(u32*)&J.Clo[ji][idx] = lo;
            }
        }
    }
}

// ---------------- conn job: 32i x 32j, 256 threads; emits bitmask ------------
__device__ void connJob(int cid, ConnArgs CA, char* smemRaw)
{
    float (*Aj)[33] = (float(*)[33])smemRaw;
    float (*Bi)[33] = (float(*)[33])(smemRaw + 32 * 33 * 4);
    float* Cs0 = (float*)(smemRaw + 2 * 32 * 33 * 4);
    float* Cs1 = Cs0 + 256;

    int h = cid >> 4;
    int ibase = ((cid >> 2) & 3) * 32;
    int jbase = (cid & 3) * 32;
    int t = threadIdx.x;
    int tx = t & 15, ty = t >> 4;

    Cs0[t] = CA.fccw[2 * t];
    Cs1[t] = CA.fccw[2 * t + 1];

    float l0[2][2] = {{0.f, 0.f}, {0.f, 0.f}};
    float l1[2][2] = {{0.f, 0.f}, {0.f, 0.f}};

    for (int d0 = 0; d0 < 256; d0 += 32) {
        if (d0) __syncthreads();
        int jr = t >> 3, c = (t & 7) * 4;
        float4 va = *(const float4*)&g_fA[(h * 128 + jbase + jr) * 256 + d0 + c];
        Aj[jr][c] = va.x; Aj[jr][c + 1] = va.y; Aj[jr][c + 2] = va.z; Aj[jr][c + 3] = va.w;
        float4 vb = *(const float4*)&g_fB[(h * 128 + ibase + jr) * 256 + d0 + c];
        float4 o = *(const float4*)&CA.fcb[d0 + c];
        Bi[jr][c] = vb.x + o.x; Bi[jr][c + 1] = vb.y + o.y;
        Bi[jr][c + 2] = vb.z + o.z; Bi[jr][c + 3] = vb.w + o.w;
        __syncthreads();

        #pragma unroll
        for (int dd = 0; dd < 32; dd++) {
            float a0 = Aj[tx * 2][dd], a1 = Aj[tx * 2 + 1][dd];
            float b0 = Bi[ty * 2][dd], b1 = Bi[ty * 2 + 1][dd];
            float c0v = Cs0[d0 + dd], c1v = Cs1[d0 + dd];
            float r00 = fmaxf(a0 + b0, 0.f), r10 = fmaxf(a1 + b0, 0.f);
            float r01 = fmaxf(a0 + b1, 0.f), r11 = fmaxf(a1 + b1, 0.f);
            l0[0][0] = fmaf(r00, c0v, l0[0][0]); l1[0][0] = fmaf(r00, c1v, l1[0][0]);
            l0[0][1] = fmaf(r10, c0v, l0[0][1]); l1[0][1] = fmaf(r10, c1v, l1[0][1]);
            l0[1][0] = fmaf(r01, c0v, l0[1][0]); l1[1][0] = fmaf(r01, c1v, l1[1][0]);
            l0[1][1] = fmaf(r11, c0v, l0[1][1]); l1[1][1] = fmaf(r11, c1v, l1[1][1]);
        }
    }

    // emit bitmask: word jw = jbase>>5 of row i; bit (tx*2+jj)
    float cb0 = CA.fccb[0], cb1 = CA.fccb[1];
    int lane = t & 31;
    u32 hmask = (lane < 16) ? 0x0000FFFFu : 0xFFFF0000u;
    int jw = jbase >> 5;
    #pragma unroll
    for (int ii = 0; ii < 2; ii++) {
        int i = ibase + ty * 2 + ii;
        u32 v = 0;
        #pragma unroll
        for (int jj = 0; jj < 2; jj++) {
            int j = jbase + tx * 2 + jj;
            int idx = (h * 128 + i) * 128 + j;
            float2 u2 = *(const float2*)&CA.gu[idx * 2];
            float gg0 = -logf(-logf(u2.x + 1e-10f) + 1e-10f);
            float gg1 = -logf(-logf(u2.y + 1e-10f) + 1e-10f);
            // note l0/l1 indexed [jj-of-a][ii-of-b] per original layout:
            // a0/a1 are j pair (tx*2, tx*2+1) -> first index; b0/b1 are i pair -> second
            if ((l1[ii][jj] + cb1 + gg1) > (l0[ii][jj] + cb0 + gg0))
                v |= (1u << (tx * 2 + jj));
        }
        u32 word = __reduce_or_sync(hmask, v);
        if (tx == 0) g_cmask[(h * 128 + i) * 4 + jw] = word;
    }
}

// ---------------- attention-only kernel: one CTA per (b,h), 256 threads ------
__global__ void __launch_bounds__(256)
k_attn()
{
    extern __shared__ char sm[];
    u32 smB = (u32)__cvta_generic_to_shared(sm);
    bf16* planes = (bf16*)sm;                // 6 x [128*40]
    u32 sQhiB = smB, sQloB = smB + 10240;
    u32 sKhiB = smB + 20480, sKloB = smB + 30720;
    u32 sVhiB = smB + 40960, sVloB = smB + 51200;

    int bid = blockIdx.x;
    int b = bid >> 3, h = bid & 7;
    int t = threadIdx.x;
    int warp = t >> 5, lane = t & 31;
    int g = lane >> 3, r = lane & 7;

    // stage Q/K/V planes
    {
        int gbase = bid * 4096;
        #pragma unroll
        for (int u = 0; u < 12; u++) {
            int c = t + u * 256;
            int plane = c >> 9;
            int i = c & 511;
            int row = i >> 2, seg = i & 3;
            int op = plane >> 1;
            const bf16* src = (plane & 1) ? (g_qkvlo + op * 1048576)
                                          : (g_qkvhi + op * 1048576);
            int pidx = op * 2 + (plane & 1);
            *(uint4*)&planes[pidx * 5120 + row * 40 + seg * 8] =
                *(const uint4*)&src[gbase + row * 32 + seg * 8];
        }
    }

    // mask words straight from gmem (produced by connJob)
    int rA = warp * 16 + (lane >> 2);
    int rB = rA + 8;
    u32 mA[4], mB[4];
    {
        const u32* cm = g_cmask + h * 512;
        #pragma unroll
        for (int w2 = 0; w2 < 4; w2++) {
            mA[w2] = cm[rA * 4 + w2];
            mB[w2] = cm[rB * 4 + w2];
        }
    }
    __syncthreads();

    u32 aQh[2][4], aQl[2][4];
    #pragma unroll
    for (int kt = 0; kt < 2; kt++) {
        int rowA = warp * 16 + r + ((g & 1) << 3);
        int kcol = kt * 16 + ((g >> 1) << 3);
        u32 off = (u32)(rowA * 40 + kcol) * 2;
        LDSM4(aQh[kt], sQhiB + off);
        LDSM4(aQl[kt], sQloB + off);
    }

    float accS[16][4];
    #pragma unroll
    for (int nt = 0; nt < 16; nt++)
        #pragma unroll
        for (int i = 0; i < 4; i++) accS[nt][i] = 0.0f;

    #pragma unroll
    for (int kt = 0; kt < 2; kt++) {
        #pragma unroll
        for (int ng = 0; ng < 8; ng++) {
            u32 kbh[4], kbl[4];
            int nrow = ng * 16 + r + ((g & 1) << 3);
            int kcol = kt * 16 + ((g >> 1) << 3);
            u32 off = (u32)(nrow * 40 + kcol) * 2;
            LDSM4(kbh, sKhiB + off);
            LDSM4(kbl, sKloB + off);
            u32 b0h[2] = {kbh[0], kbh[2]}, b1h[2] = {kbh[1], kbh[3]};
            u32 b0l[2] = {kbl[0], kbl[2]}, b1l[2] = {kbl[1], kbl[3]};
            MMA16816(accS[ng * 2], aQh[kt], b0h);
            MMA16816(accS[ng * 2], aQh[kt], b0l);
            MMA16816(accS[ng * 2], aQl[kt], b0h);
            MMA16816(accS[ng * 2 + 1], aQh[kt], b1h);
            MMA16816(accS[ng * 2 + 1], aQh[kt], b1l);
            MMA16816(accS[ng * 2 + 1], aQl[kt], b1h);
        }
    }

    #pragma unroll
    for (int nt = 0; nt < 16; nt++) {
        int c0 = nt * 8 + (lane & 3) * 2;
        int w2 = c0 >> 5, bit = c0 & 31;
        if (!((mA[w2] >> bit) & 1u))       accS[nt][0] = -INFINITY;
        if (!((mA[w2] >> (bit + 1)) & 1u)) accS[nt][1] = -INFINITY;
        if (!((mB[w2] >> bit) & 1u))       accS[nt][2] = -INFINITY;
        if (!((mB[w2] >> (bit + 1)) & 1u)) accS[nt][3] = -INFINITY;
    }

    float mxA = -INFINITY, mxB = -INFINITY;
    #pragma unroll
    for (int nt = 0; nt < 16; nt++) {
        mxA = fmaxf(mxA, fmaxf(accS[nt][0], accS[nt][1]));
        mxB = fmaxf(mxB, fmaxf(accS[nt][2], accS[nt][3]));
    }
    mxA = fmaxf(mxA, __shfl_xor_sync(0xffffffffu, mxA, 1));
    mxA = fmaxf(mxA, __shfl_xor_sync(0xffffffffu, mxA, 2));
    mxB = fmaxf(mxB, __shfl_xor_sync(0xffffffffu, mxB, 1));
    mxB = fmaxf(mxB, __shfl_xor_sync(0xffffffffu, mxB, 2));

    float sA = 0.0f, sB = 0.0f;
    #pragma unroll
    for (int nt = 0; nt < 16; nt++) {
        accS[nt][0] = expf(accS[nt][0] - mxA);
        accS[nt][1] = expf(accS[nt][1] - mxA);
        accS[nt][2] = expf(accS[nt][2] - mxB);
        accS[nt][3] = expf(accS[nt][3] - mxB);
        sA += accS[nt][0] + accS[nt][1];
        sB += accS[nt][2] + accS[nt][3];
    }
    sA += __shfl_xor_sync(0xffffffffu, sA, 1);
    sA += __shfl_xor_sync(0xffffffffu, sA, 2);
    sB += __shfl_xor_sync(0xffffffffu, sB, 1);
    sB += __shfl_xor_sync(0xffffffffu, sB, 2);
    float invA = 1.0f / sA, invB = 1.0f / sB;

    float accO[4][4];
    #pragma unroll
    for (int nt = 0; nt < 4; nt++)
        #pragma unroll
        for (int i = 0; i < 4; i++) accO[nt][i] = 0.0f;

    #pragma unroll
    for (int kt = 0; kt < 8; kt++) {
        u32 ph[4], plo[4];
        packP(accS[2 * kt][0],     accS[2 * kt][1],     ph[0], plo[0]);
        packP(accS[2 * kt][2],     accS[2 * kt][3],     ph[1], plo[1]);
        packP(accS[2 * kt + 1][0], accS[2 * kt + 1][1], ph[2], plo[2]);
        packP(accS[2 * kt + 1][2], accS[2 * kt + 1][3], ph[3], plo[3]);
        #pragma unroll
        for (int n16 = 0; n16 < 2; n16++) {
            u32 vbh[4], vbl[4];
            int krow = kt * 16 + r + ((g & 1) << 3);
            int ncol = n16 * 16 + ((g >> 1) << 3);
            u32 off = (u32)(krow * 40 + ncol) * 2;
            LDSM4T(vbh, sVhiB + off);
            LDSM4T(vbl, sVloB + off);
            MMA16816(accO[n16 * 2], ph, (&vbh[0]));
            MMA16816(accO[n16 * 2], ph, (&vbl[0]));
            MMA16816(accO[n16 * 2], plo, (&vbh[0]));
            MMA16816(accO[n16 * 2 + 1], ph, (&vbh[2]));
            MMA16816(accO[n16 * 2 + 1], ph, (&vbl[2]));
            MMA16816(accO[n16 * 2 + 1], plo, (&vbh[2]));
        }
    }

    #pragma unroll
    for (int nt = 0; nt < 4; nt++) {
        int c0 = nt * 8 + (lane & 3) * 2;
        int oA = (b * 128 + rA) * 256 + h * 32 + c0;
        int oB = (b * 128 + rB) * 256 + h * 32 + c0;
        u32 hi, lo;
        packP(accO[nt][0] * invA, accO[nt][1] * invA, hi, lo);
        *(u32*)&g_aohi[oA] = hi; *(u32*)&g_aolo[oA] = lo;
        packP(accO[nt][2] * invB, accO[nt][3] * invB, hi, lo);
        *(u32*)&g_aohi[oB] = hi; *(u32*)&g_aolo[oB] = lo;
    }
}

// ---------------- launch ------------------------------------------------------
extern "C" void kernel_launch(void* const* d_in, const int* in_sizes, int n_in,
                              void* d_out, int out_size)
{
    const float* x        = (const float*)d_in[0];
    const float* gumbel_u = (const float*)d_in[1];
    const float* memory_w = (const float*)d_in[2];
    const float* fc_out_w = (const float*)d_in[3];
    const float* fc_out_b = (const float*)d_in[4];
    const float* fc_cat_w = (const float*)d_in[5];
    const float* fc_cat_b = (const float*)d_in[6];
    const float* wq       = (const float*)d_in[7];
    const float* bq       = (const float*)d_in[8];
    const float* wk       = (const float*)d_in[9];
    const float* bk       = (const float*)d_in[10];
    const float* wv       = (const float*)d_in[11];
    const float* bv       = (const float*)d_in[12];
    const float* out_w    = (const float*)d_in[13];
    const float* out_b    = (const float*)d_in[14];
    const float* mlp_w1   = (const float*)d_in[15];
    const float* mlp_b1   = (const float*)d_in[16];
    const float* mlp_w2   = (const float*)d_in[17];
    const float* mlp_b2   = (const float*)d_in[18];

    float *fA, *fB, *cb;
    cudaGetSymbolAddress((void**)&fA, g_fA);
    cudaGetSymbolAddress((void**)&fB, g_fB);
    cudaGetSymbolAddress((void**)&cb, g_cb);
    bf16 *cwhi, *cwlo, *h1hi, *h1lo, *qkvhi, *qkvlo, *aohi, *aolo;
    cudaGetSymbolAddress((void**)&cwhi, g_cwhi);
    cudaGetSymbolAddress((void**)&cwlo, g_cwlo);
    cudaGetSymbolAddress((void**)&h1hi, g_h1hi);
    cudaGetSymbolAddress((void**)&h1lo, g_h1lo);
    cudaGetSymbolAddress((void**)&qkvhi, g_qkvhi);
    cudaGetSymbolAddress((void**)&qkvlo, g_qkvlo);
    cudaGetSymbolAddress((void**)&aohi, g_aohi);
    cudaGetSymbolAddress((void**)&aolo, g_aolo);

    static bool attrSet = false;
    if (!attrSet) {
        cudaFuncSetAttribute(k_attn, cudaFuncAttributeMaxDynamicSharedMemorySize, ATTN_SMEM);
        cudaFuncSetAttribute(k_gemm_ff, cudaFuncAttributeMaxDynamicSharedMemorySize, GEMM_SMEM);
        cudaFuncSetAttribute(k_gemm_pf, cudaFuncAttributeMaxDynamicSharedMemorySize, GEMM_SMEM);
        cudaFuncSetAttribute(k_gemm64, cudaFuncAttributeMaxDynamicSharedMemorySize, GEMM64_SMEM);
        attrSet = true;
    }

    ConnArgs CA = { fc_out_b, fc_cat_w, fc_cat_b, gumbel_u,
                    mlp_b2, wq, wk, wv, bq, bk, bv };

    // L1: fA(128) + fB(128) + mlp1(512) + compose(3x32) + bias(3) = 867
    {
        Job6 J = {};
        J.Af[0] = memory_w; J.Wf[0] = fc_out_w;
        J.Cf[0] = fA; J.scale[0] = 1.0f; J.gather[0] = 1; J.end[0] = 128;
        J.Af[1] = memory_w; J.Wf[1] = fc_out_w + 65536;
        J.Cf[1] = fB; J.scale[1] = 1.0f; J.gather[1] = 1; J.end[1] = 256;
        J.Af[2] = x; J.Wf[2] = mlp_w1; J.bias[2] = mlp_b1;
        J.Chi[2] = h1hi; J.Clo[2] = h1lo;
        J.scale[2] = 1.0f; J.act[2] = 1; J.storeMode[2] = 1; J.end[2] = 768;
        const float* wz[3] = { wq, wk, wv };
        for (int z = 0; z < 3; z++) {
            int ji = 3 + z;
            J.Af[ji] = mlp_w2; J.Wf[ji] = wz[z];
            J.Chi[ji] = cwhi + z * 65536; J.Clo[ji] = cwlo + z * 65536;
            J.scale[ji] = 1.0f; J.storeMode[ji] = 1; J.end[ji] = 768 + (z + 1) * 32;
        }
        J.totTiles = 864; J.nconn = 0;
        k_gemm_ff<<<867, 256, GEMM_SMEM>>>(J, CA);
    }

    // L2: QKV (3 x 256 BM64 tiles) + conn(128) = 896 blocks
    {
        Job6 J = {};
        const float scale = 0.17677669529663687f;  // 1/sqrt(32)
        for (int z = 0; z < 3; z++) {
            J.Ahi[z] = h1hi; J.Alo[z] = h1lo;
            J.Whi[z] = cwhi + z * 65536; J.Wlo[z] = cwlo + z * 65536;
            J.bias[z] = cb + z * 256;
            J.Chi[z] = qkvhi + z * 1048576; J.Clo[z] = qkvlo + z * 1048576;
            J.scale[z] = (z == 0) ? scale : 1.0f;
            J.storeMode[z] = 2;
            J.end[z] = (z + 1) * 256;
        }
        J.end[3] = J.end[4] = J.end[5] = 768;
        J.totTiles = 768; J.nconn = 128;
        k_gemm64<<<896, 256, GEMM64_SMEM>>>(J, CA);
    }

    // L3: attention (256 CTAs, one per (b,h))
    k_attn<<<256, 256, ATTN_SMEM>>>();

    // L4: output projection -> d_out (512; A = ao planes, W = out_w fp32)
    {
        Job6 J = {};
        J.Ahi[0] = aohi; J.Alo[0] = aolo; J.Wf[0] = out_w;
        J.bias[0] = out_b; J.Cf[0] = (float*)d_out;
        J.scale[0] = 1.0f; J.end[0] = 512;
        J.end[1] = J.end[2] = J.end[3] = J.end[4] = J.end[5] = 512;
        J.totTiles = 512; J.nconn = 0;
        k_gemm_pf<<<512, 256, GEMM_SMEM>>>(J, CA);
    }
}

// round 14
// speedup vs baseline: 1.2673x; 1.0230x over previous
#include <cuda_runtime.h>
#include <cuda_bf16.h>
#include <math.h>

// Problem constants: B=32, N=128, D=256, H=8, DK=32
typedef unsigned int u32;
typedef __nv_bfloat16 bf16;

// ---------------- scratch (static device globals; no allocation) -------------
__device__ __align__(16) float g_fA[1024 * 256];
__device__ __align__(16) float g_fB[1024 * 256];
__device__ __align__(16) u32 g_cmask[8 * 128 * 4];       // conn bitmask [h][i][4 words]
__device__ __align__(16) float g_cb[3 * 256];            // composed QKV biases
__device__ __align__(16) bf16 g_cwhi[3 * 65536];         // composed W2@W{q,k,v}
__device__ __align__(16) bf16 g_cwlo[3 * 65536];
__device__ __align__(16) bf16 g_h1hi[4096 * 256];
__device__ __align__(16) bf16 g_h1lo[4096 * 256];
__device__ __align__(16) bf16 g_qkvhi[3 * 1048576];      // [op][B,H,N,DK] planes
__device__ __align__(16) bf16 g_qkvlo[3 * 1048576];
__device__ __align__(16) bf16 g_aohi[4096 * 256];
__device__ __align__(16) bf16 g_aolo[4096 * 256];

#define GEMM64_SMEM 73728   // 4 arrays x 2buf x 4608 bf16
#define ATTN_SMEM 61440

__device__ __forceinline__ float gelu_tanh(float x) {
    float x3 = x * x * x;
    float t = tanhf(0.7978845608028654f * (x + 0.044715f * x3));
    return 0.5f * x * (1.0f + t);
}

__device__ __forceinline__ void split_bf16(float v, bf16& h, bf16& l) {
    h = __float2bfloat16_rn(v);
    l = __float2bfloat16_rn(v - __bfloat162float(h));
}

__device__ __forceinline__ void cvt4(float4 v, uint2& hi, uint2& lo) {
    bf16 h0, l0, h1, l1, h2, l2, h3, l3;
    split_bf16(v.x, h0, l0); split_bf16(v.y, h1, l1);
    split_bf16(v.z, h2, l2); split_bf16(v.w, h3, l3);
    __nv_bfloat162 a, b, c, d;
    a.x = h0; a.y = h1; b.x = h2; b.y = h3;
    c.x = l0; c.y = l1; d.x = l2; d.y = l3;
    hi.x = *(u32*)&a; hi.y = *(u32*)&b;
    lo.x = *(u32*)&c; lo.y = *(u32*)&d;
}

__device__ __forceinline__ void packP(float x, float y, u32& hi, u32& lo) {
    bf16 hx, lx, hy, ly;
    split_bf16(x, hx, lx);
    split_bf16(y, hy, ly);
    __nv_bfloat162 H; H.x = hx; H.y = hy;
    __nv_bfloat162 L; L.x = lx; L.y = ly;
    hi = *(u32*)&H; lo = *(u32*)&L;
}

#define LDSM4(r, addr)                                                        \
    asm volatile("ldmatrix.sync.aligned.m8n8.x4.shared.b16 {%0,%1,%2,%3}, [%4];" \
                 : "=r"(r[0]), "=r"(r[1]), "=r"(r[2]), "=r"(r[3]) : "r"(addr))

#define LDSM4T(r, addr)                                                       \
    asm volatile("ldmatrix.sync.aligned.m8n8.x4.trans.shared.b16 {%0,%1,%2,%3}, [%4];" \
                 : "=r"(r[0]), "=r"(r[1]), "=r"(r[2]), "=r"(r[3]) : "r"(addr))

#define MMA16816(d, a, b)                                                     \
    asm volatile("mma.sync.aligned.m16n8k16.row.col.f32.bf16.bf16.f32 "       \
                 "{%0,%1,%2,%3}, {%4,%5,%6,%7}, {%8,%9}, {%0,%1,%2,%3};"      \
                 : "+f"(d[0]), "+f"(d[1]), "+f"(d[2]), "+f"(d[3])             \
                 : "r"(a[0]), "r"(a[1]), "r"(a[2]), "r"(a[3]),                \
                   "r"(b[0]), "r"(b[1]))

// ---------------- job table --------------------------------------------------
struct Job6 {
    const float* Af[6];
    const bf16 *Ahi[6], *Alo[6];
    const float* Wf[6];
    const bf16 *Whi[6], *Wlo[6];
    const float* bias[6];
    float* Cf[6];
    bf16 *Chi[6], *Clo[6];
    float scale[6];
    int gather[6], act[6], storeMode[6];   // storeMode: 0 fp32, 1 planes, 2 QKV
    int end[6];
    int totTiles, nconn;
};

struct ConnArgs {
    const float *fcb, *fccw, *fccb, *gu;
    const float *b2, *wq, *wk, *wv, *bq, *bk, *bv;
};

__device__ void connJob(int cid, ConnArgs CA, char* smemRaw);

__device__ void biasJob(int z, ConnArgs CA) {
    int c = threadIdx.x;
    const float* wz = (z == 0) ? CA.wq : (z == 1) ? CA.wk : CA.wv;
    const float* bz = (z == 0) ? CA.bq : (z == 1) ? CA.bk : CA.bv;
    float acc = bz[c];
    for (int d = 0; d < 256; d++)
        acc = fmaf(CA.b2[d], wz[d * 256 + c], acc);
    g_cb[z * 256 + c] = acc;
}

// ---------------- GEMM-64: BM=64, BN=64, BK=64, templated operand types ------
// 8 warps as 4(m) x 2(n); warp tile 16x32; 4 k-iterations; double-buffered.
template <bool AFP32, bool WFP32>
__device__ __forceinline__ void gemm64Body(const Job6& J, const ConnArgs& CA, char* smemRaw)
{
    int jid = blockIdx.x;
    if (jid >= J.totTiles) {
        int e = jid - J.totTiles;
        if (e < J.nconn) connJob(e, CA, smemRaw);
        else biasJob(e - J.nconn, CA);
        return;
    }
    int ji = 0;
    #pragma unroll
    for (int k = 0; k < 5; k++) if (jid >= J.end[k]) ji = k + 1;
    int tile = jid - (ji ? J.end[ji - 1] : 0);

    bf16* sAhi = (bf16*)smemRaw;             // [2][4608] each
    bf16* sAlo = sAhi + 2 * 4608;
    bf16* sWhi = sAlo + 2 * 4608;
    bf16* sWlo = sWhi + 2 * 4608;

    int rowBase = (tile >> 2) * 64;
    int colBase = (tile & 3) * 64;

    int t = threadIdx.x;
    int warp = t >> 5, lane = t & 31;
    int wm = warp >> 1, wn = warp & 1;
    int g = lane >> 3, r = lane & 7;

    u32 sAhiB = (u32)__cvta_generic_to_shared(sAhi);
    u32 sAloB = (u32)__cvta_generic_to_shared(sAlo);
    u32 sWhiB = (u32)__cvta_generic_to_shared(sWhi);
    u32 sWloB = (u32)__cvta_generic_to_shared(sWlo);

    int pl = t >> 7, ps = t & 127;

    uint4 pa[4], pw[4];
    float4 fa[4], fw[4];

    auto loadTile = [&](int kt) {
        if (AFP32) {
            #pragma unroll
            for (int u = 0; u < 4; u++) {
                int c = t + 256 * u;          // 0..1023
                int row = c >> 4, seg = c & 15;
                int rr = rowBase + row;
                const float* src = J.gather[ji]
                    ? J.Af[ji] + (rr & 127) * 2048 + (rr >> 7) * 256
                    : J.Af[ji] + rr * 256;
                fa[u] = *(const float4*)&src[kt + seg * 4];
            }
        } else {
            const bf16* asrc = pl ? J.Alo[ji] : J.Ahi[ji];
            #pragma unroll
            for (int u = 0; u < 4; u++) {
                int c = ps + 128 * u;         // 0..511
                pa[u] = *(const uint4*)&asrc[(rowBase + (c >> 3)) * 256 + kt + (c & 7) * 8];
            }
        }
        if (WFP32) {
            #pragma unroll
            for (int u = 0; u < 4; u++) {
                int c = t + 256 * u;
                fw[u] = *(const float4*)&J.Wf[ji][(kt + (c >> 4)) * 256 + colBase + (c & 15) * 4];
            }
        } else {
            const bf16* wsrc = pl ? J.Wlo[ji] : J.Whi[ji];
            #pragma unroll
            for (int u = 0; u < 4; u++) {
                int c = ps + 128 * u;
                pw[u] = *(const uint4*)&wsrc[(kt + (c >> 3)) * 256 + colBase + (c & 7) * 8];
            }
        }
    };

    auto storeTile = [&](int bb) {
        if (AFP32) {
            #pragma unroll
            for (int u = 0; u < 4; u++) {
                uint2 hi, lo;
                cvt4(fa[u], hi, lo);
                int c = t + 256 * u;
                int off = bb * 4608 + (c >> 4) * 72 + (c & 15) * 4;
                *(uint2*)&sAhi[off] = hi; *(uint2*)&sAlo[off] = lo;
            }
        } else {
            bf16* ad = pl ? sAlo : sAhi;
            #pragma unroll
            for (int u = 0; u < 4; u++) {
                int c = ps + 128 * u;
                *(uint4*)&ad[bb * 4608 + (c >> 3) * 72 + (c & 7) * 8] = pa[u];
            }
        }
        if (WFP32) {
            #pragma unroll
            for (int u = 0; u < 4; u++) {
                uint2 hi, lo;
                cvt4(fw[u], hi, lo);
                int c = t + 256 * u;
                int off = bb * 4608 + (c >> 4) * 72 + (c & 15) * 4;
                *(uint2*)&sWhi[off] = hi; *(uint2*)&sWlo[off] = lo;
            }
        } else {
            bf16* wd = pl ? sWlo : sWhi;
            #pragma unroll
            for (int u = 0; u < 4; u++) {
                int c = ps + 128 * u;
                *(uint4*)&wd[bb * 4608 + (c >> 3) * 72 + (c & 7) * 8] = pw[u];
            }
        }
    };

    float accH[4][4], accM[4][4];
    #pragma unroll
    for (int nt = 0; nt < 4; nt++)
        #pragma unroll
        for (int i = 0; i < 4; i++) { accH[nt][i] = 0.0f; accM[nt][i] = 0.0f; }

    loadTile(0);
    storeTile(0);
    __syncthreads();

    #pragma unroll
    for (int it = 0; it < 4; it++) {
        int bb = it & 1;
        if (it < 3) loadTile((it + 1) * 64);

        #pragma unroll
        for (int ks = 0; ks < 64; ks += 16) {
            u32 ah[4], al[4];
            {
                int rowA = wm * 16 + r + ((g & 1) << 3);
                int kcol = ks + ((g >> 1) << 3);
                u32 off = (u32)(bb * 4608 + rowA * 72 + kcol) * 2;
                LDSM4(ah, sAhiB + off);
                LDSM4(al, sAloB + off);
            }
            #pragma unroll
            for (int n16 = 0; n16 < 2; n16++) {
                u32 bh[4], bl[4];
                int krow = ks + r + ((g & 1) << 3);
                int ncol = wn * 32 + n16 * 16 + ((g >> 1) << 3);
                u32 off = (u32)(bb * 4608 + krow * 72 + ncol) * 2;
                LDSM4T(bh, sWhiB + off);
                LDSM4T(bl, sWloB + off);
                MMA16816(accH[n16 * 2], ah, (&bh[0]));
                MMA16816(accM[n16 * 2], ah, (&bl[0]));
                MMA16816(accM[n16 * 2], al, (&bh[0]));
                MMA16816(accH[n16 * 2 + 1], ah, (&bh[2]));
                MMA16816(accM[n16 * 2 + 1], ah, (&bl[2]));
                MMA16816(accM[n16 * 2 + 1], al, (&bh[2]));
            }
        }
        if (it < 3) {
            storeTile(1 - bb);
            __syncthreads();
        }
    }

    const float* bias = J.bias[ji];
    float scl = J.scale[ji];
    int sMode = J.storeMode[ji], act = J.act[ji];

    #pragma unroll
    for (int nt = 0; nt < 4; nt++) {
        int row0 = rowBase + wm * 16 + (lane >> 2);
        int col0 = colBase + wn * 32 + nt * 8 + (lane & 3) * 2;
        float bv0 = bias ? bias[col0] : 0.0f;
        float bv1 = bias ? bias[col0 + 1] : 0.0f;
        #pragma unroll
        for (int half = 0; half < 2; half++) {
            int row = row0 + half * 8;
            float v0 = (accH[nt][half * 2 + 0] + accM[nt][half * 2 + 0] + bv0) * scl;
            float v1 = (accH[nt][half * 2 + 1] + accM[nt][half * 2 + 1] + bv1) * scl;
            if (act) { v0 = gelu_tanh(v0); v1 = gelu_tanh(v1); }
            if (sMode == 0) {
                *(float2*)&J.Cf[ji][row * 256 + col0] = make_float2(v0, v1);
            } else if (sMode == 1) {
                u32 hi, lo;
                packP(v0, v1, hi, lo);
                *(u32*)&J.Chi[ji][row * 256 + col0] = hi;
                *(u32*)&J.Clo[ji][row * 256 + col0] = lo;
            } else {
                int b = row >> 7, n = row & 127;
                int h = col0 >> 5, dk = col0 & 31;
                int idx = (((b * 8 + h) * 128 + n) * 32) + dk;
                u32 hi, lo;
                packP(v0, v1, hi, lo);
                *(u32*)&J.Chi[ji][idx] = hi;
                *(u32*)&J.Clo[ji][idx] = lo;
            }
        }
    }
}

__global__ void __launch_bounds__(256) k_g64_ff(Job6 J, ConnArgs CA) {
    extern __shared__ char smemRaw[];
    gemm64Body<true, true>(J, CA, smemRaw);
}
__global__ void __launch_bounds__(256) k_g64_pp(Job6 J, ConnArgs CA) {
    extern __shared__ char smemRaw[];
    gemm64Body<false, false>(J, CA, smemRaw);
}
__global__ void __launch_bounds__(256) k_g64_pf(Job6 J, ConnArgs CA) {
    extern __shared__ char smemRaw[];
    gemm64Body<false, true>(J, CA, smemRaw);
}

// ---------------- conn job: 32i x 32j, 256 threads; emits bitmask ------------
__device__ void connJob(int cid, ConnArgs CA, char* smemRaw)
{
    float (*Aj)[33] = (float(*)[33])smemRaw;
    float (*Bi)[33] = (float(*)[33])(smemRaw + 32 * 33 * 4);
    float* Cs0 = (float*)(smemRaw + 2 * 32 * 33 * 4);
    float* Cs1 = Cs0 + 256;

    int h = cid >> 4;
    int ibase = ((cid >> 2) & 3) * 32;
    int jbase = (cid & 3) * 32;
    int t = threadIdx.x;
    int tx = t & 15, ty = t >> 4;

    Cs0[t] = CA.fccw[2 * t];
    Cs1[t] = CA.fccw[2 * t + 1];

    float l0[2][2] = {{0.f, 0.f}, {0.f, 0.f}};
    float l1[2][2] = {{0.f, 0.f}, {0.f, 0.f}};

    for (int d0 = 0; d0 < 256; d0 += 32) {
        if (d0) __syncthreads();
        int jr = t >> 3, c = (t & 7) * 4;
        float4 va = *(const float4*)&g_fA[(h * 128 + jbase + jr) * 256 + d0 + c];
        Aj[jr][c] = va.x; Aj[jr][c + 1] = va.y; Aj[jr][c + 2] = va.z; Aj[jr][c + 3] = va.w;
        float4 vb = *(const float4*)&g_fB[(h * 128 + ibase + jr) * 256 + d0 + c];
        float4 o = *(const float4*)&CA.fcb[d0 + c];
        Bi[jr][c] = vb.x + o.x; Bi[jr][c + 1] = vb.y + o.y;
        Bi[jr][c + 2] = vb.z + o.z; Bi[jr][c + 3] = vb.w + o.w;
        __syncthreads();

        #pragma unroll
        for (int dd = 0; dd < 32; dd++) {
            float a0 = Aj[tx * 2][dd], a1 = Aj[tx * 2 + 1][dd];
            float b0 = Bi[ty * 2][dd], b1 = Bi[ty * 2 + 1][dd];
            float c0v = Cs0[d0 + dd], c1v = Cs1[d0 + dd];
            float r00 = fmaxf(a0 + b0, 0.f), r10 = fmaxf(a1 + b0, 0.f);
            float r01 = fmaxf(a0 + b1, 0.f), r11 = fmaxf(a1 + b1, 0.f);
            l0[0][0] = fmaf(r00, c0v, l0[0][0]); l1[0][0] = fmaf(r00, c1v, l1[0][0]);
            l0[0][1] = fmaf(r10, c0v, l0[0][1]); l1[0][1] = fmaf(r10, c1v, l1[0][1]);
            l0[1][0] = fmaf(r01, c0v, l0[1][0]); l1[1][0] = fmaf(r01, c1v, l1[1][0]);
            l0[1][1] = fmaf(r11, c0v, l0[1][1]); l1[1][1] = fmaf(r11, c1v, l1[1][1]);
        }
    }

    float cb0 = CA.fccb[0], cb1 = CA.fccb[1];
    int lane = t & 31;
    u32 hmask = (lane < 16) ? 0x0000FFFFu : 0xFFFF0000u;
    int jw = jbase >> 5;
    #pragma unroll
    for (int ii = 0; ii < 2; ii++) {
        int i = ibase + ty * 2 + ii;
        u32 v = 0;
        #pragma unroll
        for (int jj = 0; jj < 2; jj++) {
            int j = jbase + tx * 2 + jj;
            int idx = (h * 128 + i) * 128 + j;
            float2 u2 = *(const float2*)&CA.gu[idx * 2];
            float gg0 = -logf(-logf(u2.x + 1e-10f) + 1e-10f);
            float gg1 = -logf(-logf(u2.y + 1e-10f) + 1e-10f);
            if ((l1[ii][jj] + cb1 + gg1) > (l0[ii][jj] + cb0 + gg0))
                v |= (1u << (tx * 2 + jj));
        }
        u32 word = __reduce_or_sync(hmask, v);
        if (tx == 0) g_cmask[(h * 128 + i) * 4 + jw] = word;
    }
}

// ---------------- attention-only kernel: one CTA per (b,h), 256 threads ------
__global__ void __launch_bounds__(256)
k_attn()
{
    extern __shared__ char sm[];
    u32 smB = (u32)__cvta_generic_to_shared(sm);
    bf16* planes = (bf16*)sm;                // 6 x [128*40]
    u32 sQhiB = smB, sQloB = smB + 10240;
    u32 sKhiB = smB + 20480, sKloB = smB + 30720;
    u32 sVhiB = smB + 40960, sVloB = smB + 51200;

    int bid = blockIdx.x;
    int b = bid >> 3, h = bid & 7;
    int t = threadIdx.x;
    int warp = t >> 5, lane = t & 31;
    int g = lane >> 3, r = lane & 7;

    // stage Q/K/V planes
    {
        int gbase = bid * 4096;
        #pragma unroll
        for (int u = 0; u < 12; u++) {
            int c = t + u * 256;
            int plane = c >> 9;
            int i = c & 511;
            int row = i >> 2, seg = i & 3;
            int op = plane >> 1;
            const bf16* src = (plane & 1) ? (g_qkvlo + op * 1048576)
                                          : (g_qkvhi + op * 1048576);
            int pidx = op * 2 + (plane & 1);
            *(uint4*)&planes[pidx * 5120 + row * 40 + seg * 8] =
                *(const uint4*)&src[gbase + row * 32 + seg * 8];
        }
    }

    // mask words straight from gmem
    int rA = warp * 16 + (lane >> 2);
    int rB = rA + 8;
    u32 mA[4], mB[4];
    {
        const u32* cm = g_cmask + h * 512;
        #pragma unroll
        for (int w2 = 0; w2 < 4; w2++) {
            mA[w2] = cm[rA * 4 + w2];
            mB[w2] = cm[rB * 4 + w2];
        }
    }
    __syncthreads();

    u32 aQh[2][4], aQl[2][4];
    #pragma unroll
    for (int kt = 0; kt < 2; kt++) {
        int rowA = warp * 16 + r + ((g & 1) << 3);
        int kcol = kt * 16 + ((g >> 1) << 3);
        u32 off = (u32)(rowA * 40 + kcol) * 2;
        LDSM4(aQh[kt], sQhiB + off);
        LDSM4(aQl[kt], sQloB + off);
    }

    float accS[16][4];
    #pragma unroll
    for (int nt = 0; nt < 16; nt++)
        #pragma unroll
        for (int i = 0; i < 4; i++) accS[nt][i] = 0.0f;

    #pragma unroll
    for (int kt = 0; kt < 2; kt++) {
        #pragma unroll
        for (int ng = 0; ng < 8; ng++) {
            u32 kbh[4], kbl[4];
            int nrow = ng * 16 + r + ((g & 1) << 3);
            int kcol = kt * 16 + ((g >> 1) << 3);
            u32 off = (u32)(nrow * 40 + kcol) * 2;
            LDSM4(kbh, sKhiB + off);
            LDSM4(kbl, sKloB + off);
            u32 b0h[2] = {kbh[0], kbh[2]}, b1h[2] = {kbh[1], kbh[3]};
            u32 b0l[2] = {kbl[0], kbl[2]}, b1l[2] = {kbl[1], kbl[3]};
            MMA16816(accS[ng * 2], aQh[kt], b0h);
            MMA16816(accS[ng * 2], aQh[kt], b0l);
            MMA16816(accS[ng * 2], aQl[kt], b0h);
            MMA16816(accS[ng * 2 + 1], aQh[kt], b1h);
            MMA16816(accS[ng * 2 + 1], aQh[kt], b1l);
            MMA16816(accS[ng * 2 + 1], aQl[kt], b1h);
        }
    }

    #pragma unroll
    for (int nt = 0; nt < 16; nt++) {
        int c0 = nt * 8 + (lane & 3) * 2;
        int w2 = c0 >> 5, bit = c0 & 31;
        if (!((mA[w2] >> bit) & 1u))       accS[nt][0] = -INFINITY;
        if (!((mA[w2] >> (bit + 1)) & 1u)) accS[nt][1] = -INFINITY;
        if (!((mB[w2] >> bit) & 1u))       accS[nt][2] = -INFINITY;
        if (!((mB[w2] >> (bit + 1)) & 1u)) accS[nt][3] = -INFINITY;
    }

    float mxA = -INFINITY, mxB = -INFINITY;
    #pragma unroll
    for (int nt = 0; nt < 16; nt++) {
        mxA = fmaxf(mxA, fmaxf(accS[nt][0], accS[nt][1]));
        mxB = fmaxf(mxB, fmaxf(accS[nt][2], accS[nt][3]));
    }
    mxA = fmaxf(mxA, __shfl_xor_sync(0xffffffffu, mxA, 1));
    mxA = fmaxf(mxA, __shfl_xor_sync(0xffffffffu, mxA, 2));
    mxB = fmaxf(mxB, __shfl_xor_sync(0xffffffffu, mxB, 1));
    mxB = fmaxf(mxB, __shfl_xor_sync(0xffffffffu, mxB, 2));

    float sA = 0.0f, sB = 0.0f;
    #pragma unroll
    for (int nt = 0; nt < 16; nt++) {
        accS[nt][0] = expf(accS[nt][0] - mxA);
        accS[nt][1] = expf(accS[nt][1] - mxA);
        accS[nt][2] = expf(accS[nt][2] - mxB);
        accS[nt][3] = expf(accS[nt][3] - mxB);
        sA += accS[nt][0] + accS[nt][1];
        sB += accS[nt][2] + accS[nt][3];
    }
    sA += __shfl_xor_sync(0xffffffffu, sA, 1);
    sA += __shfl_xor_sync(0xffffffffu, sA, 2);
    sB += __shfl_xor_sync(0xffffffffu, sB, 1);
    sB += __shfl_xor_sync(0xffffffffu, sB, 2);
    float invA = 1.0f / sA, invB = 1.0f / sB;

    float accO[4][4];
    #pragma unroll
    for (int nt = 0; nt < 4; nt++)
        #pragma unroll
        for (int i = 0; i < 4; i++) accO[nt][i] = 0.0f;

    #pragma unroll
    for (int kt = 0; kt < 8; kt++) {
        u32 ph[4], plo[4];
        packP(accS[2 * kt][0],     accS[2 * kt][1],     ph[0], plo[0]);
        packP(accS[2 * kt][2],     accS[2 * kt][3],     ph[1], plo[1]);
        packP(accS[2 * kt + 1][0], accS[2 * kt + 1][1], ph[2], plo[2]);
        packP(accS[2 * kt + 1][2], accS[2 * kt + 1][3], ph[3], plo[3]);
        #pragma unroll
        for (int n16 = 0; n16 < 2; n16++) {
            u32 vbh[4], vbl[4];
            int krow = kt * 16 + r + ((g & 1) << 3);
            int ncol = n16 * 16 + ((g >> 1) << 3);
            u32 off = (u32)(krow * 40 + ncol) * 2;
            LDSM4T(vbh, sVhiB + off);
            LDSM4T(vbl, sVloB + off);
            MMA16816(accO[n16 * 2], ph, (&vbh[0]));
            MMA16816(accO[n16 * 2], ph, (&vbl[0]));
            MMA16816(accO[n16 * 2], plo, (&vbh[0]));
            MMA16816(accO[n16 * 2 + 1], ph, (&vbh[2]));
            MMA16816(accO[n16 * 2 + 1], ph, (&vbl[2]));
            MMA16816(accO[n16 * 2 + 1], plo, (&vbh[2]));
        }
    }

    #pragma unroll
    for (int nt = 0; nt < 4; nt++) {
        int c0 = nt * 8 + (lane & 3) * 2;
        int oA = (b * 128 + rA) * 256 + h * 32 + c0;
        int oB = (b * 128 + rB) * 256 + h * 32 + c0;
        u32 hi, lo;
        packP(accO[nt][0] * invA, accO[nt][1] * invA, hi, lo);
        *(u32*)&g_aohi[oA] = hi; *(u32*)&g_aolo[oA] = lo;
        packP(accO[nt][2] * invB, accO[nt][3] * invB, hi, lo);
        *(u32*)&g_aohi[oB] = hi; *(u32*)&g_aolo[oB] = lo;
    }
}

// ---------------- launch ------------------------------------------------------
extern "C" void kernel_launch(void* const* d_in, const int* in_sizes, int n_in,
                              void* d_out, int out_size)
{
    const float* x        = (const float*)d_in[0];
    const float* gumbel_u = (const float*)d_in[1];
    const float* memory_w = (const float*)d_in[2];
    const float* fc_out_w = (const float*)d_in[3];
    const float* fc_out_b = (const float*)d_in[4];
    const float* fc_cat_w = (const float*)d_in[5];
    const float* fc_cat_b = (const float*)d_in[6];
    const float* wq       = (const float*)d_in[7];
    const float* bq       = (const float*)d_in[8];
    const float* wk       = (const float*)d_in[9];
    const float* bk       = (const float*)d_in[10];
    const float* wv       = (const float*)d_in[11];
    const float* bv       = (const float*)d_in[12];
    const float* out_w    = (const float*)d_in[13];
    const float* out_b    = (const float*)d_in[14];
    const float* mlp_w1   = (const float*)d_in[15];
    const float* mlp_b1   = (const float*)d_in[16];
    const float* mlp_w2   = (const float*)d_in[17];
    const float* mlp_b2   = (const float*)d_in[18];

    float *fA, *fB, *cb;
    cudaGetSymbolAddress((void**)&fA, g_fA);
    cudaGetSymbolAddress((void**)&fB, g_fB);
    cudaGetSymbolAddress((void**)&cb, g_cb);
    bf16 *cwhi, *cwlo, *h1hi, *h1lo, *qkvhi, *qkvlo, *aohi, *aolo;
    cudaGetSymbolAddress((void**)&cwhi, g_cwhi);
    cudaGetSymbolAddress((void**)&cwlo, g_cwlo);
    cudaGetSymbolAddress((void**)&h1hi, g_h1hi);
    cudaGetSymbolAddress((void**)&h1lo, g_h1lo);
    cudaGetSymbolAddress((void**)&qkvhi, g_qkvhi);
    cudaGetSymbolAddress((void**)&qkvlo, g_qkvlo);
    cudaGetSymbolAddress((void**)&aohi, g_aohi);
    cudaGetSymbolAddress((void**)&aolo, g_aolo);

    static bool attrSet = false;
    if (!attrSet) {
        cudaFuncSetAttribute(k_attn, cudaFuncAttributeMaxDynamicSharedMemorySize, ATTN_SMEM);
        cudaFuncSetAttribute(k_g64_ff, cudaFuncAttributeMaxDynamicSharedMemorySize, GEMM64_SMEM);
        cudaFuncSetAttribute(k_g64_pp, cudaFuncAttributeMaxDynamicSharedMemorySize, GEMM64_SMEM);
        cudaFuncSetAttribute(k_g64_pf, cudaFuncAttributeMaxDynamicSharedMemorySize, GEMM64_SMEM);
        attrSet = true;
    }

    ConnArgs CA = { fc_out_b, fc_cat_w, fc_cat_b, gumbel_u,
                    mlp_b2, wq, wk, wv, bq, bk, bv };

    // L1: fA(64) + fB(64) + mlp1(256) + compose(3x16) + bias(3) = 435 blocks
    {
        Job6 J = {};
        J.Af[0] = memory_w; J.Wf[0] = fc_out_w;
        J.Cf[0] = fA; J.scale[0] = 1.0f; J.gather[0] = 1; J.end[0] = 64;
        J.Af[1] = memory_w; J.Wf[1] = fc_out_w + 65536;
        J.Cf[1] = fB; J.scale[1] = 1.0f; J.gather[1] = 1; J.end[1] = 128;
        J.Af[2] = x; J.Wf[2] = mlp_w1; J.bias[2] = mlp_b1;
        J.Chi[2] = h1hi; J.Clo[2] = h1lo;
        J.scale[2] = 1.0f; J.act[2] = 1; J.storeMode[2] = 1; J.end[2] = 384;
        const float* wz[3] = { wq, wk, wv };
        for (int z = 0; z < 3; z++) {
            int ji = 3 + z;
            J.Af[ji] = mlp_w2; J.Wf[ji] = wz[z];
            J.Chi[ji] = cwhi + z * 65536; J.Clo[ji] = cwlo + z * 65536;
            J.scale[ji] = 1.0f; J.storeMode[ji] = 1; J.end[ji] = 384 + (z + 1) * 16;
        }
        J.totTiles = 432; J.nconn = 0;
        k_g64_ff<<<435, 256, GEMM64_SMEM>>>(J, CA);
    }

    // L2: QKV (3 x 256 tiles) + conn(128) = 896 blocks
    {
        Job6 J = {};
        const float scale = 0.17677669529663687f;  // 1/sqrt(32)
        for (int z = 0; z < 3; z++) {
            J.Ahi[z] = h1hi; J.Alo[z] = h1lo;
            J.Whi[z] = cwhi + z * 65536; J.Wlo[z] = cwlo + z * 65536;
            J.bias[z] = cb + z * 256;
            J.Chi[z] = qkvhi + z * 1048576; J.Clo[z] = qkvlo + z * 1048576;
            J.scale[z] = (z == 0) ? scale : 1.0f;
            J.storeMode[z] = 2;
            J.end[z] = (z + 1) * 256;
        }
        J.end[3] = J.end[4] = J.end[5] = 768;
        J.totTiles = 768; J.nconn = 128;
        k_g64_pp<<<896, 256, GEMM64_SMEM>>>(J, CA);
    }

    // L3: attention (256 CTAs, one per (b,h))
    k_attn<<<256, 256, ATTN_SMEM>>>();

    // L4: output projection -> d_out (256 tiles; A = ao planes, W = out_w fp32)
    {
        Job6 J = {};
        J.Ahi[0] = aohi; J.Alo[0] = aolo; J.Wf[0] = out_w;
        J.bias[0] = out_b; J.Cf[0] = (float*)d_out;
        J.scale[0] = 1.0f; J.end[0] = 256;
        J.end[1] = J.end[2] = J.end[3] = J.end[4] = J.end[5] = 256;
        J.totTiles = 256; J.nconn = 0;
        k_g64_pf<<<256, 256, GEMM64_SMEM>>>(J, CA);
    }
}

// round 15
// speedup vs baseline: 1.3431x; 1.0598x over previous
#include <cuda_runtime.h>
#include <cuda_bf16.h>
#include <math.h>

// Problem constants: B=32, N=128, D=256, H=8, DK=32
typedef unsigned int u32;
typedef __nv_bfloat16 bf16;

// ---------------- scratch (static device globals; no allocation) -------------
__device__ __align__(16) float g_fA[1024 * 256];
__device__ __align__(16) float g_fB[1024 * 256];
__device__ __align__(16) u32 g_cmask[8 * 128 * 4];       // conn bitmask [h][i][4 words]
__device__ __align__(16) float g_cb[3 * 256];            // composed QKV biases
__device__ __align__(16) bf16 g_cwhi[3 * 65536];         // composed W2@W{q,k,v}
__device__ __align__(16) bf16 g_cwlo[3 * 65536];
__device__ __align__(16) bf16 g_h1hi[4096 * 256];
__device__ __align__(16) bf16 g_h1lo[4096 * 256];
__device__ __align__(16) bf16 g_qkvhi[3 * 1048576];      // [op][B,H,N,DK] planes
__device__ __align__(16) bf16 g_qkvlo[3 * 1048576];
__device__ __align__(16) bf16 g_aohi[4096 * 256];
__device__ __align__(16) bf16 g_aolo[4096 * 256];

#define GEMM64_SMEM 73728   // 4 arrays x 2buf x 4608 bf16
#define ATTN_SMEM 61440

__device__ __forceinline__ float gelu_tanh(float x) {
    float x3 = x * x * x;
    float t = tanhf(0.7978845608028654f * (x + 0.044715f * x3));
    return 0.5f * x * (1.0f + t);
}

__device__ __forceinline__ void split_bf16(float v, bf16& h, bf16& l) {
    h = __float2bfloat16_rn(v);
    l = __float2bfloat16_rn(v - __bfloat162float(h));
}

__device__ __forceinline__ void cvt4(float4 v, uint2& hi, uint2& lo) {
    bf16 h0, l0, h1, l1, h2, l2, h3, l3;
    split_bf16(v.x, h0, l0); split_bf16(v.y, h1, l1);
    split_bf16(v.z, h2, l2); split_bf16(v.w, h3, l3);
    __nv_bfloat162 a, b, c, d;
    a.x = h0; a.y = h1; b.x = h2; b.y = h3;
    c.x = l0; c.y = l1; d.x = l2; d.y = l3;
    hi.x = *(u32*)&a; hi.y = *(u32*)&b;
    lo.x = *(u32*)&c; lo.y = *(u32*)&d;
}

__device__ __forceinline__ void packP(float x, float y, u32& hi, u32& lo) {
    bf16 hx, lx, hy, ly;
    split_bf16(x, hx, lx);
    split_bf16(y, hy, ly);
    __nv_bfloat162 H; H.x = hx; H.y = hy;
    __nv_bfloat162 L; L.x = lx; L.y = ly;
    hi = *(u32*)&H; lo = *(u32*)&L;
}

#define LDSM4(r, addr)                                                        \
    asm volatile("ldmatrix.sync.aligned.m8n8.x4.shared.b16 {%0,%1,%2,%3}, [%4];" \
                 : "=r"(r[0]), "=r"(r[1]), "=r"(r[2]), "=r"(r[3]) : "r"(addr))

#define LDSM4T(r, addr)                                                       \
    asm volatile("ldmatrix.sync.aligned.m8n8.x4.trans.shared.b16 {%0,%1,%2,%3}, [%4];" \
                 : "=r"(r[0]), "=r"(r[1]), "=r"(r[2]), "=r"(r[3]) : "r"(addr))

#define MMA16816(d, a, b)                                                     \
    asm volatile("mma.sync.aligned.m16n8k16.row.col.f32.bf16.bf16.f32 "       \
                 "{%0,%1,%2,%3}, {%4,%5,%6,%7}, {%8,%9}, {%0,%1,%2,%3};"      \
                 : "+f"(d[0]), "+f"(d[1]), "+f"(d[2]), "+f"(d[3])             \
                 : "r"(a[0]), "r"(a[1]), "r"(a[2]), "r"(a[3]),                \
                   "r"(b[0]), "r"(b[1]))

// ---------------- job table --------------------------------------------------
struct Job6 {
    const float* Af[6];
    const bf16 *Ahi[6], *Alo[6];
    const float* Wf[6];
    const bf16 *Whi[6], *Wlo[6];
    const float* bias[6];
    float* Cf[6];
    bf16 *Chi[6], *Clo[6];
    float scale[6];
    int gather[6], act[6], storeMode[6];   // storeMode: 0 fp32, 1 planes, 2 QKV
    int end[6];
    int totTiles, nconn;
};

struct ConnArgs {
    const float *fcb, *fccw, *fccb, *gu;
    const float *b2, *wq, *wk, *wv, *bq, *bk, *bv;
};

__device__ void connJob(int cid, ConnArgs CA, char* smemRaw);

__device__ void biasJob(int z, ConnArgs CA) {
    int c = threadIdx.x;
    const float* wz = (z == 0) ? CA.wq : (z == 1) ? CA.wk : CA.wv;
    const float* bz = (z == 0) ? CA.bq : (z == 1) ? CA.bk : CA.bv;
    float acc = bz[c];
    for (int d = 0; d < 256; d++)
        acc = fmaf(CA.b2[d], wz[d * 256 + c], acc);
    g_cb[z * 256 + c] = acc;
}

// ---------------- GEMM-64: BM=64, BN=64, BK=64, templated operand types ------
template <bool AFP32, bool WFP32>
__device__ __forceinline__ void gemm64Body(const Job6& J, const ConnArgs& CA, char* smemRaw)
{
    int jid = blockIdx.x;
    if (jid >= J.totTiles) {
        int e = jid - J.totTiles;
        if (e < J.nconn) connJob(e, CA, smemRaw);
        else biasJob(e - J.nconn, CA);
        return;
    }
    int ji = 0;
    #pragma unroll
    for (int k = 0; k < 5; k++) if (jid >= J.end[k]) ji = k + 1;
    int tile = jid - (ji ? J.end[ji - 1] : 0);

    bf16* sAhi = (bf16*)smemRaw;             // [2][4608] each
    bf16* sAlo = sAhi + 2 * 4608;
    bf16* sWhi = sAlo + 2 * 4608;
    bf16* sWlo = sWhi + 2 * 4608;

    int rowBase = (tile >> 2) * 64;
    int colBase = (tile & 3) * 64;

    int t = threadIdx.x;
    int warp = t >> 5, lane = t & 31;
    int wm = warp >> 1, wn = warp & 1;
    int g = lane >> 3, r = lane & 7;

    u32 sAhiB = (u32)__cvta_generic_to_shared(sAhi);
    u32 sAloB = (u32)__cvta_generic_to_shared(sAlo);
    u32 sWhiB = (u32)__cvta_generic_to_shared(sWhi);
    u32 sWloB = (u32)__cvta_generic_to_shared(sWlo);

    int pl = t >> 7, ps = t & 127;

    uint4 pa[4], pw[4];
    float4 fa[4], fw[4];

    auto loadTile = [&](int kt) {
        if (AFP32) {
            #pragma unroll
            for (int u = 0; u < 4; u++) {
                int c = t + 256 * u;          // 0..1023
                int row = c >> 4, seg = c & 15;
                int rr = rowBase + row;
                const float* src = J.gather[ji]
                    ? J.Af[ji] + (rr & 127) * 2048 + (rr >> 7) * 256
                    : J.Af[ji] + rr * 256;
                fa[u] = *(const float4*)&src[kt + seg * 4];
            }
        } else {
            const bf16* asrc = pl ? J.Alo[ji] : J.Ahi[ji];
            #pragma unroll
            for (int u = 0; u < 4; u++) {
                int c = ps + 128 * u;         // 0..511
                pa[u] = *(const uint4*)&asrc[(rowBase + (c >> 3)) * 256 + kt + (c & 7) * 8];
            }
        }
        if (WFP32) {
            #pragma unroll
            for (int u = 0; u < 4; u++) {
                int c = t + 256 * u;
                fw[u] = *(const float4*)&J.Wf[ji][(kt + (c >> 4)) * 256 + colBase + (c & 15) * 4];
            }
        } else {
            const bf16* wsrc = pl ? J.Wlo[ji] : J.Whi[ji];
            #pragma unroll
            for (int u = 0; u < 4; u++) {
                int c = ps + 128 * u;
                pw[u] = *(const uint4*)&wsrc[(kt + (c >> 3)) * 256 + colBase + (c & 7) * 8];
            }
        }
    };

    auto storeTile = [&](int bb) {
        if (AFP32) {
            #pragma unroll
            for (int u = 0; u < 4; u++) {
                uint2 hi, lo;
                cvt4(fa[u], hi, lo);
                int c = t + 256 * u;
                int off = bb * 4608 + (c >> 4) * 72 + (c & 15) * 4;
                *(uint2*)&sAhi[off] = hi; *(uint2*)&sAlo[off] = lo;
            }
        } else {
            bf16* ad = pl ? sAlo : sAhi;
            #pragma unroll
            for (int u = 0; u < 4; u++) {
                int c = ps + 128 * u;
                *(uint4*)&ad[bb * 4608 + (c >> 3) * 72 + (c & 7) * 8] = pa[u];
            }
        }
        if (WFP32) {
            #pragma unroll
            for (int u = 0; u < 4; u++) {
                uint2 hi, lo;
                cvt4(fw[u], hi, lo);
                int c = t + 256 * u;
                int off = bb * 4608 + (c >> 4) * 72 + (c & 15) * 4;
                *(uint2*)&sWhi[off] = hi; *(uint2*)&sWlo[off] = lo;
            }
        } else {
            bf16* wd = pl ? sWlo : sWhi;
            #pragma unroll
            for (int u = 0; u < 4; u++) {
                int c = ps + 128 * u;
                *(uint4*)&wd[bb * 4608 + (c >> 3) * 72 + (c & 7) * 8] = pw[u];
            }
        }
    };

    float accH[4][4], accM[4][4];
    #pragma unroll
    for (int nt = 0; nt < 4; nt++)
        #pragma unroll
        for (int i = 0; i < 4; i++) { accH[nt][i] = 0.0f; accM[nt][i] = 0.0f; }

    loadTile(0);
    storeTile(0);
    __syncthreads();

    #pragma unroll
    for (int it = 0; it < 4; it++) {
        int bb = it & 1;
        if (it < 3) loadTile((it + 1) * 64);

        #pragma unroll
        for (int ks = 0; ks < 64; ks += 16) {
            u32 ah[4], al[4];
            {
                int rowA = wm * 16 + r + ((g & 1) << 3);
                int kcol = ks + ((g >> 1) << 3);
                u32 off = (u32)(bb * 4608 + rowA * 72 + kcol) * 2;
                LDSM4(ah, sAhiB + off);
                LDSM4(al, sAloB + off);
            }
            #pragma unroll
            for (int n16 = 0; n16 < 2; n16++) {
                u32 bh[4], bl[4];
                int krow = ks + r + ((g & 1) << 3);
                int ncol = wn * 32 + n16 * 16 + ((g >> 1) << 3);
                u32 off = (u32)(bb * 4608 + krow * 72 + ncol) * 2;
                LDSM4T(bh, sWhiB + off);
                LDSM4T(bl, sWloB + off);
                MMA16816(accH[n16 * 2], ah, (&bh[0]));
                MMA16816(accM[n16 * 2], ah, (&bl[0]));
                MMA16816(accM[n16 * 2], al, (&bh[0]));
                MMA16816(accH[n16 * 2 + 1], ah, (&bh[2]));
                MMA16816(accM[n16 * 2 + 1], ah, (&bl[2]));
                MMA16816(accM[n16 * 2 + 1], al, (&bh[2]));
            }
        }
        if (it < 3) {
            storeTile(1 - bb);
            __syncthreads();
        }
    }

    const float* bias = J.bias[ji];
    float scl = J.scale[ji];
    int sMode = J.storeMode[ji], act = J.act[ji];

    #pragma unroll
    for (int nt = 0; nt < 4; nt++) {
        int row0 = rowBase + wm * 16 + (lane >> 2);
        int col0 = colBase + wn * 32 + nt * 8 + (lane & 3) * 2;
        float bv0 = bias ? bias[col0] : 0.0f;
        float bv1 = bias ? bias[col0 + 1] : 0.0f;
        #pragma unroll
        for (int half = 0; half < 2; half++) {
            int row = row0 + half * 8;
            float v0 = (accH[nt][half * 2 + 0] + accM[nt][half * 2 + 0] + bv0) * scl;
            float v1 = (accH[nt][half * 2 + 1] + accM[nt][half * 2 + 1] + bv1) * scl;
            if (act) { v0 = gelu_tanh(v0); v1 = gelu_tanh(v1); }
            if (sMode == 0) {
                *(float2*)&J.Cf[ji][row * 256 + col0] = make_float2(v0, v1);
            } else if (sMode == 1) {
                u32 hi, lo;
                packP(v0, v1, hi, lo);
                *(u32*)&J.Chi[ji][row * 256 + col0] = hi;
                *(u32*)&J.Clo[ji][row * 256 + col0] = lo;
            } else {
                int b = row >> 7, n = row & 127;
                int h = col0 >> 5, dk = col0 & 31;
                int idx = (((b * 8 + h) * 128 + n) * 32) + dk;
                u32 hi, lo;
                packP(v0, v1, hi, lo);
                *(u32*)&J.Chi[ji][idx] = hi;
                *(u32*)&J.Clo[ji][idx] = lo;
            }
        }
    }
}

__global__ void __launch_bounds__(256) k_g64_ff(Job6 J, ConnArgs CA) {
    extern __shared__ char smemRaw[];
    gemm64Body<true, true>(J, CA, smemRaw);
}
__global__ void __launch_bounds__(256) k_g64_pp(Job6 J, ConnArgs CA) {
    extern __shared__ char smemRaw[];
#if __CUDA_ARCH__ >= 900
    cudaGridDependencySynchronize();
#endif
    gemm64Body<false, false>(J, CA, smemRaw);
}
__global__ void __launch_bounds__(256) k_g64_pf(Job6 J, ConnArgs CA) {
    extern __shared__ char smemRaw[];
#if __CUDA_ARCH__ >= 900
    cudaGridDependencySynchronize();
#endif
    gemm64Body<false, true>(J, CA, smemRaw);
}

// ---------------- conn job: 32i x 32j, 256 threads; emits bitmask ------------
__device__ void connJob(int cid, ConnArgs CA, char* smemRaw)
{
    float (*Aj)[33] = (float(*)[33])smemRaw;
    float (*Bi)[33] = (float(*)[33])(smemRaw + 32 * 33 * 4);
    float* Cs0 = (float*)(smemRaw + 2 * 32 * 33 * 4);
    float* Cs1 = Cs0 + 256;

    int h = cid >> 4;
    int ibase = ((cid >> 2) & 3) * 32;
    int jbase = (cid & 3) * 32;
    int t = threadIdx.x;
    int tx = t & 15, ty = t >> 4;

    Cs0[t] = CA.fccw[2 * t];
    Cs1[t] = CA.fccw[2 * t + 1];

    float l0[2][2] = {{0.f, 0.f}, {0.f, 0.f}};
    float l1[2][2] = {{0.f, 0.f}, {0.f, 0.f}};

    for (int d0 = 0; d0 < 256; d0 += 32) {
        if (d0) __syncthreads();
        int jr = t >> 3, c = (t & 7) * 4;
        float4 va = *(const float4*)&g_fA[(h * 128 + jbase + jr) * 256 + d0 + c];
        Aj[jr][c] = va.x; Aj[jr][c + 1] = va.y; Aj[jr][c + 2] = va.z; Aj[jr][c + 3] = va.w;
        float4 vb = *(const float4*)&g_fB[(h * 128 + ibase + jr) * 256 + d0 + c];
        float4 o = *(const float4*)&CA.fcb[d0 + c];
        Bi[jr][c] = vb.x + o.x; Bi[jr][c + 1] = vb.y + o.y;
        Bi[jr][c + 2] = vb.z + o.z; Bi[jr][c + 3] = vb.w + o.w;
        __syncthreads();

        #pragma unroll
        for (int dd = 0; dd < 32; dd++) {
            float a0 = Aj[tx * 2][dd], a1 = Aj[tx * 2 + 1][dd];
            float b0 = Bi[ty * 2][dd], b1 = Bi[ty * 2 + 1][dd];
            float c0v = Cs0[d0 + dd], c1v = Cs1[d0 + dd];
            float r00 = fmaxf(a0 + b0, 0.f), r10 = fmaxf(a1 + b0, 0.f);
            float r01 = fmaxf(a0 + b1, 0.f), r11 = fmaxf(a1 + b1, 0.f);
            l0[0][0] = fmaf(r00, c0v, l0[0][0]); l1[0][0] = fmaf(r00, c1v, l1[0][0]);
            l0[0][1] = fmaf(r10, c0v, l0[0][1]); l1[0][1] = fmaf(r10, c1v, l1[0][1]);
            l0[1][0] = fmaf(r01, c0v, l0[1][0]); l1[1][0] = fmaf(r01, c1v, l1[1][0]);
            l0[1][1] = fmaf(r11, c0v, l0[1][1]); l1[1][1] = fmaf(r11, c1v, l1[1][1]);
        }
    }

    float cb0 = CA.fccb[0], cb1 = CA.fccb[1];
    int lane = t & 31;
    u32 hmask = (lane < 16) ? 0x0000FFFFu : 0xFFFF0000u;
    int jw = jbase >> 5;
    #pragma unroll
    for (int ii = 0; ii < 2; ii++) {
        int i = ibase + ty * 2 + ii;
        u32 v = 0;
        #pragma unroll
        for (int jj = 0; jj < 2; jj++) {
            int j = jbase + tx * 2 + jj;
            int idx = (h * 128 + i) * 128 + j;
            float2 u2 = *(const float2*)&CA.gu[idx * 2];
            float gg0 = -logf(-logf(u2.x + 1e-10f) + 1e-10f);
            float gg1 = -logf(-logf(u2.y + 1e-10f) + 1e-10f);
            if ((l1[ii][jj] + cb1 + gg1) > (l0[ii][jj] + cb0 + gg0))
                v |= (1u << (tx * 2 + jj));
        }
        u32 word = __reduce_or_sync(hmask, v);
        if (tx == 0) g_cmask[(h * 128 + i) * 4 + jw] = word;
    }
}

// ---------------- attention-only kernel: one CTA per (b,h), 256 threads ------
// S is computed in log2 domain (log2e folded into Q scale) -> exp2f softmax.
__global__ void __launch_bounds__(256)
k_attn()
{
    extern __shared__ char sm[];
#if __CUDA_ARCH__ >= 900
    cudaGridDependencySynchronize();
#endif
    u32 smB = (u32)__cvta_generic_to_shared(sm);
    bf16* planes = (bf16*)sm;                // 6 x [128*40]
    u32 sQhiB = smB, sQloB = smB + 10240;
    u32 sKhiB = smB + 20480, sKloB = smB + 30720;
    u32 sVhiB = smB + 40960, sVloB = smB + 51200;

    int bid = blockIdx.x;
    int b = bid >> 3, h = bid & 7;
    int t = threadIdx.x;
    int warp = t >> 5, lane = t & 31;
    int g = lane >> 3, r = lane & 7;

    // stage Q/K/V planes
    {
        int gbase = bid * 4096;
        #pragma unroll
        for (int u = 0; u < 12; u++) {
            int c = t + u * 256;
            int plane = c >> 9;
            int i = c & 511;
            int row = i >> 2, seg = i & 3;
            int op = plane >> 1;
            const bf16* src = (plane & 1) ? (g_qkvlo + op * 1048576)
                                          : (g_qkvhi + op * 1048576);
            int pidx = op * 2 + (plane & 1);
            *(uint4*)&planes[pidx * 5120 + row * 40 + seg * 8] =
                *(const uint4*)&src[gbase + row * 32 + seg * 8];
        }
    }

    // mask words straight from gmem
    int rA = warp * 16 + (lane >> 2);
    int rB = rA + 8;
    u32 mA[4], mB[4];
    {
        const u32* cm = g_cmask + h * 512;
        #pragma unroll
        for (int w2 = 0; w2 < 4; w2++) {
            mA[w2] = cm[rA * 4 + w2];
            mB[w2] = cm[rB * 4 + w2];
        }
    }
    __syncthreads();

    u32 aQh[2][4], aQl[2][4];
    #pragma unroll
    for (int kt = 0; kt < 2; kt++) {
        int rowA = warp * 16 + r + ((g & 1) << 3);
        int kcol = kt * 16 + ((g >> 1) << 3);
        u32 off = (u32)(rowA * 40 + kcol) * 2;
        LDSM4(aQh[kt], sQhiB + off);
        LDSM4(aQl[kt], sQloB + off);
    }

    float accS[16][4];
    #pragma unroll
    for (int nt = 0; nt < 16; nt++)
        #pragma unroll
        for (int i = 0; i < 4; i++) accS[nt][i] = 0.0f;

    #pragma unroll
    for (int kt = 0; kt < 2; kt++) {
        #pragma unroll
        for (int ng = 0; ng < 8; ng++) {
            u32 kbh[4], kbl[4];
            int nrow = ng * 16 + r + ((g & 1) << 3);
            int kcol = kt * 16 + ((g >> 1) << 3);
            u32 off = (u32)(nrow * 40 + kcol) * 2;
            LDSM4(kbh, sKhiB + off);
            LDSM4(kbl, sKloB + off);
            u32 b0h[2] = {kbh[0], kbh[2]}, b1h[2] = {kbh[1], kbh[3]};
            u32 b0l[2] = {kbl[0], kbl[2]}, b1l[2] = {kbl[1], kbl[3]};
            MMA16816(accS[ng * 2], aQh[kt], b0h);
            MMA16816(accS[ng * 2], aQh[kt], b0l);
            MMA16816(accS[ng * 2], aQl[kt], b0h);
            MMA16816(accS[ng * 2 + 1], aQh[kt], b1h);
            MMA16816(accS[ng * 2 + 1], aQh[kt], b1l);
            MMA16816(accS[ng * 2 + 1], aQl[kt], b1h);
        }
    }

    #pragma unroll
    for (int nt = 0; nt < 16; nt++) {
        int c0 = nt * 8 + (lane & 3) * 2;
        int w2 = c0 >> 5, bit = c0 & 31;
        if (!((mA[w2] >> bit) & 1u))       accS[nt][0] = -INFINITY;
        if (!((mA[w2] >> (bit + 1)) & 1u)) accS[nt][1] = -INFINITY;
        if (!((mB[w2] >> bit) & 1u))       accS[nt][2] = -INFINITY;
        if (!((mB[w2] >> (bit + 1)) & 1u)) accS[nt][3] = -INFINITY;
    }

    float mxA = -INFINITY, mxB = -INFINITY;
    #pragma unroll
    for (int nt = 0; nt < 16; nt++) {
        mxA = fmaxf(mxA, fmaxf(accS[nt][0], accS[nt][1]));
        mxB = fmaxf(mxB, fmaxf(accS[nt][2], accS[nt][3]));
    }
    mxA = fmaxf(mxA, __shfl_xor_sync(0xffffffffu, mxA, 1));
    mxA = fmaxf(mxA, __shfl_xor_sync(0xffffffffu, mxA, 2));
    mxB = fmaxf(mxB, __shfl_xor_sync(0xffffffffu, mxB, 1));
    mxB = fmaxf(mxB, __shfl_xor_sync(0xffffffffu, mxB, 2));

    float sA = 0.0f, sB = 0.0f;
    #pragma unroll
    for (int nt = 0; nt < 16; nt++) {
        accS[nt][0] = exp2f(accS[nt][0] - mxA);
        accS[nt][1] = exp2f(accS[nt][1] - mxA);
        accS[nt][2] = exp2f(accS[nt][2] - mxB);
        accS[nt][3] = exp2f(accS[nt][3] - mxB);
        sA += accS[nt][0] + accS[nt][1];
        sB += accS[nt][2] + accS[nt][3];
    }
    sA += __shfl_xor_sync(0xffffffffu, sA, 1);
    sA += __shfl_xor_sync(0xffffffffu, sA, 2);
    sB += __shfl_xor_sync(0xffffffffu, sB, 1);
    sB += __shfl_xor_sync(0xffffffffu, sB, 2);
    float invA = 1.0f / sA, invB = 1.0f / sB;

    float accO[4][4];
    #pragma unroll
    for (int nt = 0; nt < 4; nt++)
        #pragma unroll
        for (int i = 0; i < 4; i++) accO[nt][i] = 0.0f;

    #pragma unroll
    for (int kt = 0; kt < 8; kt++) {
        u32 ph[4], plo[4];
        packP(accS[2 * kt][0],     accS[2 * kt][1],     ph[0], plo[0]);
        packP(accS[2 * kt][2],     accS[2 * kt][3],     ph[1], plo[1]);
        packP(accS[2 * kt + 1][0], accS[2 * kt + 1][1], ph[2], plo[2]);
        packP(accS[2 * kt + 1][2], accS[2 * kt + 1][3], ph[3], plo[3]);
        #pragma unroll
        for (int n16 = 0; n16 < 2; n16++) {
            u32 vbh[4], vbl[4];
            int krow = kt * 16 + r + ((g & 1) << 3);
            int ncol = n16 * 16 + ((g >> 1) << 3);
            u32 off = (u32)(krow * 40 + ncol) * 2;
            LDSM4T(vbh, sVhiB + off);
            LDSM4T(vbl, sVloB + off);
            MMA16816(accO[n16 * 2], ph, (&vbh[0]));
            MMA16816(accO[n16 * 2], ph, (&vbl[0]));
            MMA16816(accO[n16 * 2], plo, (&vbh[0]));
            MMA16816(accO[n16 * 2 + 1], ph, (&vbh[2]));
            MMA16816(accO[n16 * 2 + 1], ph, (&vbl[2]));
            MMA16816(accO[n16 * 2 + 1], plo, (&vbh[2]));
        }
    }

    #pragma unroll
    for (int nt = 0; nt < 4; nt++) {
        int c0 = nt * 8 + (lane & 3) * 2;
        int oA = (b * 128 + rA) * 256 + h * 32 + c0;
        int oB = (b * 128 + rB) * 256 + h * 32 + c0;
        u32 hi, lo;
        packP(accO[nt][0] * invA, accO[nt][1] * invA, hi, lo);
        *(u32*)&g_aohi[oA] = hi; *(u32*)&g_aolo[oA] = lo;
        packP(accO[nt][2] * invB, accO[nt][3] * invB, hi, lo);
        *(u32*)&g_aohi[oB] = hi; *(u32*)&g_aolo[oB] = lo;
    }
}

// ---------------- launch helpers ----------------------------------------------
template <typename K, typename... Args>
static void launchPDL(K kernel, int grid, int smem, Args... args)
{
    cudaLaunchConfig_t cfg = {};
    cfg.gridDim = dim3(grid, 1, 1);
    cfg.blockDim = dim3(256, 1, 1);
    cfg.dynamicSmemBytes = (size_t)smem;
    cfg.stream = 0;
    cudaLaunchAttribute at[1];
    at[0].id = cudaLaunchAttributeProgrammaticStreamSerialization;
    at[0].val.programmaticStreamSerializationAllowed = 1;
    cfg.attrs = at;
    cfg.numAttrs = 1;
    cudaLaunchKernelEx(&cfg, kernel, args...);
}

// ---------------- launch ------------------------------------------------------
extern "C" void kernel_launch(void* const* d_in, const int* in_sizes, int n_in,
                              void* d_out, int out_size)
{
    const float* x        = (const float*)d_in[0];
    const float* gumbel_u = (const float*)d_in[1];
    const float* memory_w = (const float*)d_in[2];
    const float* fc_out_w = (const float*)d_in[3];
    const float* fc_out_b = (const float*)d_in[4];
    const float* fc_cat_w = (const float*)d_in[5];
    const float* fc_cat_b = (const float*)d_in[6];
    const float* wq       = (const float*)d_in[7];
    const float* bq       = (const float*)d_in[8];
    const float* wk       = (const float*)d_in[9];
    const float* bk       = (const float*)d_in[10];
    const float* wv       = (const float*)d_in[11];
    const float* bv       = (const float*)d_in[12];
    const float* out_w    = (const float*)d_in[13];
    const float* out_b    = (const float*)d_in[14];
    const float* mlp_w1   = (const float*)d_in[15];
    const float* mlp_b1   = (const float*)d_in[16];
    const float* mlp_w2   = (const float*)d_in[17];
    const float* mlp_b2   = (const float*)d_in[18];

    float *fA, *fB, *cb;
    cudaGetSymbolAddress((void**)&fA, g_fA);
    cudaGetSymbolAddress((void**)&fB, g_fB);
    cudaGetSymbolAddress((void**)&cb, g_cb);
    bf16 *cwhi, *cwlo, *h1hi, *h1lo, *qkvhi, *qkvlo, *aohi, *aolo;
    cudaGetSymbolAddress((void**)&cwhi, g_cwhi);
    cudaGetSymbolAddress((void**)&cwlo, g_cwlo);
    cudaGetSymbolAddress((void**)&h1hi, g_h1hi);
    cudaGetSymbolAddress((void**)&h1lo, g_h1lo);
    cudaGetSymbolAddress((void**)&qkvhi, g_qkvhi);
    cudaGetSymbolAddress((void**)&qkvlo, g_qkvlo);
    cudaGetSymbolAddress((void**)&aohi, g_aohi);
    cudaGetSymbolAddress((void**)&aolo, g_aolo);

    static bool attrSet = false;
    if (!attrSet) {
        cudaFuncSetAttribute(k_attn, cudaFuncAttributeMaxDynamicSharedMemorySize, ATTN_SMEM);
        cudaFuncSetAttribute(k_g64_ff, cudaFuncAttributeMaxDynamicSharedMemorySize, GEMM64_SMEM);
        cudaFuncSetAttribute(k_g64_pp, cudaFuncAttributeMaxDynamicSharedMemorySize, GEMM64_SMEM);
        cudaFuncSetAttribute(k_g64_pf, cudaFuncAttributeMaxDynamicSharedMemorySize, GEMM64_SMEM);
        attrSet = true;
    }

    ConnArgs CA = { fc_out_b, fc_cat_w, fc_cat_b, gumbel_u,
                    mlp_b2, wq, wk, wv, bq, bk, bv };

    // L1: fA(64) + fB(64) + mlp1(256) + compose(3x16) + bias(3) = 435 blocks
    {
        Job6 J = {};
        J.Af[0] = memory_w; J.Wf[0] = fc_out_w;
        J.Cf[0] = fA; J.scale[0] = 1.0f; J.gather[0] = 1; J.end[0] = 64;
        J.Af[1] = memory_w; J.Wf[1] = fc_out_w + 65536;
        J.Cf[1] = fB; J.scale[1] = 1.0f; J.gather[1] = 1; J.end[1] = 128;
        J.Af[2] = x; J.Wf[2] = mlp_w1; J.bias[2] = mlp_b1;
        J.Chi[2] = h1hi; J.Clo[2] = h1lo;
        J.scale[2] = 1.0f; J.act[2] = 1; J.storeMode[2] = 1; J.end[2] = 384;
        const float* wz[3] = { wq, wk, wv };
        for (int z = 0; z < 3; z++) {
            int ji = 3 + z;
            J.Af[ji] = mlp_w2; J.Wf[ji] = wz[z];
            J.Chi[ji] = cwhi + z * 65536; J.Clo[ji] = cwlo + z * 65536;
            J.scale[ji] = 1.0f; J.storeMode[ji] = 1; J.end[ji] = 384 + (z + 1) * 16;
        }
        J.totTiles = 432; J.nconn = 0;
        k_g64_ff<<<435, 256, GEMM64_SMEM>>>(J, CA);
    }

    // L2: QKV (3 x 256 tiles) + conn(128) = 896 blocks  [PDL]
    {
        Job6 J = {};
        // fold log2(e) into Q scale so softmax uses exp2f
        const float scaleQ = 0.17677669529663687f * 1.4426950408889634f;
        for (int z = 0; z < 3; z++) {
            J.Ahi[z] = h1hi; J.Alo[z] = h1lo;
            J.Whi[z] = cwhi + z * 65536; J.Wlo[z] = cwlo + z * 65536;
            J.bias[z] = cb + z * 256;
            J.Chi[z] = qkvhi + z * 1048576; J.Clo[z] = qkvlo + z * 1048576;
            J.scale[z] = (z == 0) ? scaleQ : 1.0f;
            J.storeMode[z] = 2;
            J.end[z] = (z + 1) * 256;
        }
        J.end[3] = J.end[4] = J.end[5] = 768;
        J.totTiles = 768; J.nconn = 128;
        launchPDL(k_g64_pp, 896, GEMM64_SMEM, J, CA);
    }

    // L3: attention (256 CTAs)  [PDL]
    launchPDL(k_attn, 256, ATTN_SMEM);

    // L4: output projection -> d_out (256 tiles)  [PDL]
    {
        Job6 J = {};
        J.Ahi[0] = aohi; J.Alo[0] = aolo; J.Wf[0] = out_w;
        J.bias[0] = out_b; J.Cf[0] = (float*)d_out;
        J.scale[0] = 1.0f; J.end[0] = 256;
        J.end[1] = J.end[2] = J.end[3] = J.end[4] = J.end[5] = 256;
        J.totTiles = 256; J.nconn = 0;
        launchPDL(k_g64_pf, 256, GEMM64_SMEM, J, CA);
    }
}

// round 16
// speedup vs baseline: 1.4252x; 1.0611x over previous
#include <cuda_runtime.h>
#include <cuda_bf16.h>
#include <math.h>

// Problem constants: B=32, N=128, D=256, H=8, DK=32
typedef unsigned int u32;
typedef __nv_bfloat16 bf16;

// ---------------- scratch (static device globals; no allocation) -------------
__device__ __align__(16) float g_fA[1024 * 256];
__device__ __align__(16) float g_fB[1024 * 256];
__device__ __align__(16) u32 g_cmask[8 * 128 * 4];       // conn bitmask [h][i][4 words]
__device__ __align__(16) float g_cb[3 * 256];            // composed QKV biases
__device__ __align__(16) bf16 g_cwhi[3 * 65536];         // composed W2@W{q,k,v}
__device__ __align__(16) bf16 g_cwlo[3 * 65536];
__device__ __align__(16) bf16 g_h1hi[4096 * 256];
__device__ __align__(16) bf16 g_h1lo[4096 * 256];
__device__ __align__(16) bf16 g_qkvhi[3 * 1048576];      // [op][B,H,N,DK] planes
__device__ __align__(16) bf16 g_qkvlo[3 * 1048576];
__device__ __align__(16) bf16 g_aohi[4096 * 256];
__device__ __align__(16) bf16 g_aolo[4096 * 256];

#define GEMM64_SMEM 73728   // 4 arrays x 2buf x 4608 bf16
#define ATTN_SMEM 61440

__device__ __forceinline__ float gelu_tanh(float x) {
    float x3 = x * x * x;
    float t = tanhf(0.7978845608028654f * (x + 0.044715f * x3));
    return 0.5f * x * (1.0f + t);
}

__device__ __forceinline__ void split_bf16(float v, bf16& h, bf16& l) {
    h = __float2bfloat16_rn(v);
    l = __float2bfloat16_rn(v - __bfloat162float(h));
}

__device__ __forceinline__ void cvt4(float4 v, uint2& hi, uint2& lo) {
    bf16 h0, l0, h1, l1, h2, l2, h3, l3;
    split_bf16(v.x, h0, l0); split_bf16(v.y, h1, l1);
    split_bf16(v.z, h2, l2); split_bf16(v.w, h3, l3);
    __nv_bfloat162 a, b, c, d;
    a.x = h0; a.y = h1; b.x = h2; b.y = h3;
    c.x = l0; c.y = l1; d.x = l2; d.y = l3;
    hi.x = *(u32*)&a; hi.y = *(u32*)&b;
    lo.x = *(u32*)&c; lo.y = *(u32*)&d;
}

__device__ __forceinline__ void packP(float x, float y, u32& hi, u32& lo) {
    bf16 hx, lx, hy, ly;
    split_bf16(x, hx, lx);
    split_bf16(y, hy, ly);
    __nv_bfloat162 H; H.x = hx; H.y = hy;
    __nv_bfloat162 L; L.x = lx; L.y = ly;
    hi = *(u32*)&H; lo = *(u32*)&L;
}

#define LDSM4(r, addr)                                                        \
    asm volatile("ldmatrix.sync.aligned.m8n8.x4.shared.b16 {%0,%1,%2,%3}, [%4];" \
                 : "=r"(r[0]), "=r"(r[1]), "=r"(r[2]), "=r"(r[3]) : "r"(addr))

#define LDSM4T(r, addr)                                                       \
    asm volatile("ldmatrix.sync.aligned.m8n8.x4.trans.shared.b16 {%0,%1,%2,%3}, [%4];" \
                 : "=r"(r[0]), "=r"(r[1]), "=r"(r[2]), "=r"(r[3]) : "r"(addr))

#define MMA16816(d, a, b)                                                     \
    asm volatile("mma.sync.aligned.m16n8k16.row.col.f32.bf16.bf16.f32 "       \
                 "{%0,%1,%2,%3}, {%4,%5,%6,%7}, {%8,%9}, {%0,%1,%2,%3};"      \
                 : "+f"(d[0]), "+f"(d[1]), "+f"(d[2]), "+f"(d[3])             \
                 : "r"(a[0]), "r"(a[1]), "r"(a[2]), "r"(a[3]),                \
                   "r"(b[0]), "r"(b[1]))

#define CPASYNC16(dst, src)                                                   \
    asm volatile("cp.async.cg.shared.global [%0], [%1], 16;"                  \
                 :: "r"(dst), "l"(src))
#define CPCOMMIT() asm volatile("cp.async.commit_group;" ::: "memory")
#define CPWAIT0()  asm volatile("cp.async.wait_group 0;" ::: "memory")

// ---------------- job table --------------------------------------------------
struct Job6 {
    const float* Af[6];
    const bf16 *Ahi[6], *Alo[6];
    const float* Wf[6];
    const bf16 *Whi[6], *Wlo[6];
    const float* bias[6];
    float* Cf[6];
    bf16 *Chi[6], *Clo[6];
    float scale[6];
    int gather[6], act[6], storeMode[6];   // storeMode: 0 fp32, 1 planes, 2 QKV
    int end[6];
    int totTiles, nconn;
};

struct ConnArgs {
    const float *fcb, *fccw, *fccb, *gu;
    const float *b2, *wq, *wk, *wv, *bq, *bk, *bv;
};

__device__ void connJob(int cid, ConnArgs CA, char* smemRaw);

__device__ void biasJob(int z, ConnArgs CA) {
    int c = threadIdx.x;
    const float* wz = (z == 0) ? CA.wq : (z == 1) ? CA.wk : CA.wv;
    const float* bz = (z == 0) ? CA.bq : (z == 1) ? CA.bk : CA.bv;
    float acc = bz[c];
    for (int d = 0; d < 256; d++)
        acc = fmaf(CA.b2[d], wz[d * 256 + c], acc);
    g_cb[z * 256 + c] = acc;
}

// ---------------- shared epilogue for GEMM-64 --------------------------------
__device__ __forceinline__ void gemm64Epilogue(
    const Job6& J, int ji, int rowBase, int colBase,
    float accH[4][4], float accM[4][4])
{
    int lane = threadIdx.x & 31;
    int warp = threadIdx.x >> 5;
    int wm = warp >> 1, wn = warp & 1;

    const float* bias = J.bias[ji];
    float scl = J.scale[ji];
    int sMode = J.storeMode[ji], act = J.act[ji];

    #pragma unroll
    for (int nt = 0; nt < 4; nt++) {
        int row0 = rowBase + wm * 16 + (lane >> 2);
        int col0 = colBase + wn * 32 + nt * 8 + (lane & 3) * 2;
        float bv0 = bias ? bias[col0] : 0.0f;
        float bv1 = bias ? bias[col0 + 1] : 0.0f;
        #pragma unroll
        for (int half = 0; half < 2; half++) {
            int row = row0 + half * 8;
            float v0 = (accH[nt][half * 2 + 0] + accM[nt][half * 2 + 0] + bv0) * scl;
            float v1 = (accH[nt][half * 2 + 1] + accM[nt][half * 2 + 1] + bv1) * scl;
            if (act) { v0 = gelu_tanh(v0); v1 = gelu_tanh(v1); }
            if (sMode == 0) {
                *(float2*)&J.Cf[ji][row * 256 + col0] = make_float2(v0, v1);
            } else if (sMode == 1) {
                u32 hi, lo;
                packP(v0, v1, hi, lo);
                *(u32*)&J.Chi[ji][row * 256 + col0] = hi;
                *(u32*)&J.Clo[ji][row * 256 + col0] = lo;
            } else {
                int b = row >> 7, n = row & 127;
                int h = col0 >> 5, dk = col0 & 31;
                int idx = (((b * 8 + h) * 128 + n) * 32) + dk;
                u32 hi, lo;
                packP(v0, v1, hi, lo);
                *(u32*)&J.Chi[ji][idx] = hi;
                *(u32*)&J.Clo[ji][idx] = lo;
            }
        }
    }
}

// ---------------- GEMM-64 mainloop compute (one k-iter) ----------------------
__device__ __forceinline__ void gemm64Compute(
    int bb, u32 sAhiB, u32 sAloB, u32 sWhiB, u32 sWloB,
    float accH[4][4], float accM[4][4])
{
    int lane = threadIdx.x & 31;
    int warp = threadIdx.x >> 5;
    int wm = warp >> 1, wn = warp & 1;
    int g = lane >> 3, r = lane & 7;

    #pragma unroll
    for (int ks = 0; ks < 64; ks += 16) {
        u32 ah[4], al[4];
        {
            int rowA = wm * 16 + r + ((g & 1) << 3);
            int kcol = ks + ((g >> 1) << 3);
            u32 off = (u32)(bb * 4608 + rowA * 72 + kcol) * 2;
            LDSM4(ah, sAhiB + off);
            LDSM4(al, sAloB + off);
        }
        #pragma unroll
        for (int n16 = 0; n16 < 2; n16++) {
            u32 bh[4], bl[4];
            int krow = ks + r + ((g & 1) << 3);
            int ncol = wn * 32 + n16 * 16 + ((g >> 1) << 3);
            u32 off = (u32)(bb * 4608 + krow * 72 + ncol) * 2;
            LDSM4T(bh, sWhiB + off);
            LDSM4T(bl, sWloB + off);
            MMA16816(accH[n16 * 2], ah, (&bh[0]));
            MMA16816(accM[n16 * 2], ah, (&bl[0]));
            MMA16816(accM[n16 * 2], al, (&bh[0]));
            MMA16816(accH[n16 * 2 + 1], ah, (&bh[2]));
            MMA16816(accM[n16 * 2 + 1], ah, (&bl[2]));
            MMA16816(accM[n16 * 2 + 1], al, (&bh[2]));
        }
    }
}

// ---------------- GEMM-64: fp32/plane reg-staged variants --------------------
template <bool AFP32, bool WFP32>
__device__ __forceinline__ void gemm64Body(const Job6& J, const ConnArgs& CA, char* smemRaw)
{
    int jid = blockIdx.x;
    if (jid >= J.totTiles) {
        int e = jid - J.totTiles;
        if (e < J.nconn) connJob(e, CA, smemRaw);
        else biasJob(e - J.nconn, CA);
        return;
    }
    int ji = 0;
    #pragma unroll
    for (int k = 0; k < 5; k++) if (jid >= J.end[k]) ji = k + 1;
    int tile = jid - (ji ? J.end[ji - 1] : 0);

    bf16* sAhi = (bf16*)smemRaw;
    bf16* sAlo = sAhi + 2 * 4608;
    bf16* sWhi = sAlo + 2 * 4608;
    bf16* sWlo = sWhi + 2 * 4608;

    int rowBase = (tile >> 2) * 64;
    int colBase = (tile & 3) * 64;

    int t = threadIdx.x;
    u32 sAhiB = (u32)__cvta_generic_to_shared(sAhi);
    u32 sAloB = (u32)__cvta_generic_to_shared(sAlo);
    u32 sWhiB = (u32)__cvta_generic_to_shared(sWhi);
    u32 sWloB = (u32)__cvta_generic_to_shared(sWlo);

    int pl = t >> 7, ps = t & 127;

    uint4 pa[4], pw[4];
    float4 fa[4], fw[4];

    auto loadTile = [&](int kt) {
        if (AFP32) {
            #pragma unroll
            for (int u = 0; u < 4; u++) {
                int c = t + 256 * u;
                int row = c >> 4, seg = c & 15;
                int rr = rowBase + row;
                const float* src = J.gather[ji]
                    ? J.Af[ji] + (rr & 127) * 2048 + (rr >> 7) * 256
                    : J.Af[ji] + rr * 256;
                fa[u] = *(const float4*)&src[kt + seg * 4];
            }
        } else {
            const bf16* asrc = pl ? J.Alo[ji] : J.Ahi[ji];
            #pragma unroll
            for (int u = 0; u < 4; u++) {
                int c = ps + 128 * u;
                pa[u] = *(const uint4*)&asrc[(rowBase + (c >> 3)) * 256 + kt + (c & 7) * 8];
            }
        }
        if (WFP32) {
            #pragma unroll
            for (int u = 0; u < 4; u++) {
                int c = t + 256 * u;
                fw[u] = *(const float4*)&J.Wf[ji][(kt + (c >> 4)) * 256 + colBase + (c & 15) * 4];
            }
        } else {
            const bf16* wsrc = pl ? J.Wlo[ji] : J.Whi[ji];
            #pragma unroll
            for (int u = 0; u < 4; u++) {
                int c = ps + 128 * u;
                pw[u] = *(const uint4*)&wsrc[(kt + (c >> 3)) * 256 + colBase + (c & 7) * 8];
            }
        }
    };

    auto storeTile = [&](int bb) {
        if (AFP32) {
            #pragma unroll
            for (int u = 0; u < 4; u++) {
                uint2 hi, lo;
                cvt4(fa[u], hi, lo);
                int c = t + 256 * u;
                int off = bb * 4608 + (c >> 4) * 72 + (c & 15) * 4;
                *(uint2*)&sAhi[off] = hi; *(uint2*)&sAlo[off] = lo;
            }
        } else {
            bf16* ad = pl ? sAlo : sAhi;
            #pragma unroll
            for (int u = 0; u < 4; u++) {
                int c = ps + 128 * u;
                *(uint4*)&ad[bb * 4608 + (c >> 3) * 72 + (c & 7) * 8] = pa[u];
            }
        }
        if (WFP32) {
            #pragma unroll
            for (int u = 0; u < 4; u++) {
                uint2 hi, lo;
                cvt4(fw[u], hi, lo);
                int c = t + 256 * u;
                int off = bb * 4608 + (c >> 4) * 72 + (c & 15) * 4;
                *(uint2*)&sWhi[off] = hi; *(uint2*)&sWlo[off] = lo;
            }
        } else {
            bf16* wd = pl ? sWlo : sWhi;
            #pragma unroll
            for (int u = 0; u < 4; u++) {
                int c = ps + 128 * u;
                *(uint4*)&wd[bb * 4608 + (c >> 3) * 72 + (c & 7) * 8] = pw[u];
            }
        }
    };

    float accH[4][4], accM[4][4];
    #pragma unroll
    for (int nt = 0; nt < 4; nt++)
        #pragma unroll
        for (int i = 0; i < 4; i++) { accH[nt][i] = 0.0f; accM[nt][i] = 0.0f; }

    loadTile(0);
    storeTile(0);
    __syncthreads();

    #pragma unroll
    for (int it = 0; it < 4; it++) {
        int bb = it & 1;
        if (it < 3) loadTile((it + 1) * 64);
        gemm64Compute(bb, sAhiB, sAloB, sWhiB, sWloB, accH, accM);
        if (it < 3) {
            storeTile(1 - bb);
            __syncthreads();
        }
    }

    gemm64Epilogue(J, ji, rowBase, colBase, accH, accM);
}

__global__ void __launch_bounds__(256) k_g64_ff(Job6 J, ConnArgs CA) {
    extern __shared__ char smemRaw[];
    gemm64Body<true, true>(J, CA, smemRaw);
}
__global__ void __launch_bounds__(256) k_g64_pf(Job6 J, ConnArgs CA) {
    extern __shared__ char smemRaw[];
#if __CUDA_ARCH__ >= 900
    cudaGridDependencySynchronize();
#endif
    gemm64Body<false, true>(J, CA, smemRaw);
}

// ---------------- GEMM-64 planes x planes with cp.async ----------------------
__global__ void __launch_bounds__(256)
k_g64_pp_ca(Job6 J, ConnArgs CA)
{
    extern __shared__ char smemRaw[];
#if __CUDA_ARCH__ >= 900
    cudaGridDependencySynchronize();
#endif
    int jid = blockIdx.x;
    if (jid >= J.totTiles) {
        int e = jid - J.totTiles;
        if (e < J.nconn) connJob(e, CA, smemRaw);
        else biasJob(e - J.nconn, CA);
        return;
    }
    int ji = 0;
    #pragma unroll
    for (int k = 0; k < 5; k++) if (jid >= J.end[k]) ji = k + 1;
    int tile = jid - (ji ? J.end[ji - 1] : 0);

    bf16* sAhi = (bf16*)smemRaw;
    u32 sAhiB = (u32)__cvta_generic_to_shared(sAhi);
    u32 sAloB = sAhiB + 2 * 4608 * 2;
    u32 sWhiB = sAloB + 2 * 4608 * 2;
    u32 sWloB = sWhiB + 2 * 4608 * 2;

    int rowBase = (tile >> 2) * 64;
    int colBase = (tile & 3) * 64;

    int t = threadIdx.x;
    int pl = t >> 7, ps = t & 127;

    const bf16* asrc = pl ? J.Alo[ji] : J.Ahi[ji];
    const bf16* wsrc = pl ? J.Wlo[ji] : J.Whi[ji];
    u32 adB = pl ? sAloB : sAhiB;
    u32 wdB = pl ? sWloB : sWhiB;

    auto cpTile = [&](int kt, int bb) {
        #pragma unroll
        for (int u = 0; u < 4; u++) {
            int c = ps + 128 * u;
            u32 off = (u32)(bb * 4608 + (c >> 3) * 72 + (c & 7) * 8) * 2;
            CPASYNC16(adB + off, &asrc[(rowBase + (c >> 3)) * 256 + kt + (c & 7) * 8]);
            CPASYNC16(wdB + off, &wsrc[(kt + (c >> 3)) * 256 + colBase + (c & 7) * 8]);
        }
        CPCOMMIT();
    };

    float accH[4][4], accM[4][4];
    #pragma unroll
    for (int nt = 0; nt < 4; nt++)
        #pragma unroll
        for (int i = 0; i < 4; i++) { accH[nt][i] = 0.0f; accM[nt][i] = 0.0f; }

    cpTile(0, 0);

    #pragma unroll
    for (int it = 0; it < 4; it++) {
        int bb = it & 1;
        CPWAIT0();
        __syncthreads();   // buffer bb complete & all threads past previous compute
        if (it < 3) cpTile((it + 1) * 64, 1 - bb);
        gemm64Compute(bb, sAhiB, sAloB, sWhiB, sWloB, accH, accM);
    }

    gemm64Epilogue(J, ji, rowBase, colBase, accH, accM);
}

// ---------------- conn job: 32i x 32j, 256 threads; emits bitmask ------------
__device__ void connJob(int cid, ConnArgs CA, char* smemRaw)
{
    float (*Aj)[33] = (float(*)[33])smemRaw;
    float (*Bi)[33] = (float(*)[33])(smemRaw + 32 * 33 * 4);
    float* Cs0 = (float*)(smemRaw + 2 * 32 * 33 * 4);
    float* Cs1 = Cs0 + 256;

    int h = cid >> 4;
    int ibase = ((cid >> 2) & 3) * 32;
    int jbase = (cid & 3) * 32;
    int t = threadIdx.x;
    int tx = t & 15, ty = t >> 4;

    Cs0[t] = CA.fccw[2 * t];
    Cs1[t] = CA.fccw[2 * t + 1];

    float l0[2][2] = {{0.f, 0.f}, {0.f, 0.f}};
    float l1[2][2] = {{0.f, 0.f}, {0.f, 0.f}};

    for (int d0 = 0; d0 < 256; d0 += 32) {
        if (d0) __syncthreads();
        int jr = t >> 3, c = (t & 7) * 4;
        float4 va = *(const float4*)&g_fA[(h * 128 + jbase + jr) * 256 + d0 + c];
        Aj[jr][c] = va.x; Aj[jr][c + 1] = va.y; Aj[jr][c + 2] = va.z; Aj[jr][c + 3] = va.w;
        float4 vb = *(const float4*)&g_fB[(h * 128 + ibase + jr) * 256 + d0 + c];
        float4 o = *(const float4*)&CA.fcb[d0 + c];
        Bi[jr][c] = vb.x + o.x; Bi[jr][c + 1] = vb.y + o.y;
        Bi[jr][c + 2] = vb.z + o.z; Bi[jr][c + 3] = vb.w + o.w;
        __syncthreads();

        #pragma unroll
        for (int dd = 0; dd < 32; dd++) {
            float a0 = Aj[tx * 2][dd], a1 = Aj[tx * 2 + 1][dd];
            float b0 = Bi[ty * 2][dd], b1 = Bi[ty * 2 + 1][dd];
            float c0v = Cs0[d0 + dd], c1v = Cs1[d0 + dd];
            float r00 = fmaxf(a0 + b0, 0.f), r10 = fmaxf(a1 + b0, 0.f);
            float r01 = fmaxf(a0 + b1, 0.f), r11 = fmaxf(a1 + b1, 0.f);
            l0[0][0] = fmaf(r00, c0v, l0[0][0]); l1[0][0] = fmaf(r00, c1v, l1[0][0]);
            l0[0][1] = fmaf(r10, c0v, l0[0][1]); l1[0][1] = fmaf(r10, c1v, l1[0][1]);
            l0[1][0] = fmaf(r01, c0v, l0[1][0]); l1[1][0] = fmaf(r01, c1v, l1[1][0]);
            l0[1][1] = fmaf(r11, c0v, l0[1][1]); l1[1][1] = fmaf(r11, c1v, l1[1][1]);
        }
    }

    float cb0 = CA.fccb[0], cb1 = CA.fccb[1];
    int lane = t & 31;
    u32 hmask = (lane < 16) ? 0x0000FFFFu : 0xFFFF0000u;
    int jw = jbase >> 5;
    #pragma unroll
    for (int ii = 0; ii < 2; ii++) {
        int i = ibase + ty * 2 + ii;
        u32 v = 0;
        #pragma unroll
        for (int jj = 0; jj < 2; jj++) {
            int j = jbase + tx * 2 + jj;
            int idx = (h * 128 + i) * 128 + j;
            float2 u2 = *(const float2*)&CA.gu[idx * 2];
            float gg0 = -logf(-logf(u2.x + 1e-10f) + 1e-10f);
            float gg1 = -logf(-logf(u2.y + 1e-10f) + 1e-10f);
            if ((l1[ii][jj] + cb1 + gg1) > (l0[ii][jj] + cb0 + gg0))
                v |= (1u << (tx * 2 + jj));
        }
        u32 word = __reduce_or_sync(hmask, v);
        if (tx == 0) g_cmask[(h * 128 + i) * 4 + jw] = word;
    }
}

// ---------------- attention-only kernel: one CTA per (b,h), 256 threads ------
// S in log2 domain (log2e folded into Q) -> exp2f softmax. cp.async staging.
__global__ void __launch_bounds__(256)
k_attn()
{
    extern __shared__ char sm[];
#if __CUDA_ARCH__ >= 900
    cudaGridDependencySynchronize();
#endif
    u32 smB = (u32)__cvta_generic_to_shared(sm);
    u32 sQhiB = smB, sQloB = smB + 10240;
    u32 sKhiB = smB + 20480, sKloB = smB + 30720;
    u32 sVhiB = smB + 40960, sVloB = smB + 51200;

    int bid = blockIdx.x;
    int b = bid >> 3, h = bid & 7;
    int t = threadIdx.x;
    int warp = t >> 5, lane = t & 31;
    int g = lane >> 3, r = lane & 7;

    // stage Q/K/V planes via cp.async (overlaps the mask LDGs below)
    {
        int gbase = bid * 4096;
        #pragma unroll
        for (int u = 0; u < 12; u++) {
            int c = t + u * 256;
            int plane = c >> 9;
            int i = c & 511;
            int row = i >> 2, seg = i & 3;
            int op = plane >> 1;
            const bf16* src = (plane & 1) ? (g_qkvlo + op * 1048576)
                                          : (g_qkvhi + op * 1048576);
            int pidx = op * 2 + (plane & 1);
            u32 dst = smB + (u32)(pidx * 5120 + row * 40 + seg * 8) * 2;
            CPASYNC16(dst, &src[gbase + row * 32 + seg * 8]);
        }
        CPCOMMIT();
    }

    // mask words from gmem (LDGs overlap bulk copies)
    int rA = warp * 16 + (lane >> 2);
    int rB = rA + 8;
    u32 mA[4], mB[4];
    {
        const u32* cm = g_cmask + h * 512;
        #pragma unroll
        for (int w2 = 0; w2 < 4; w2++) {
            mA[w2] = cm[rA * 4 + w2];
            mB[w2] = cm[rB * 4 + w2];
        }
    }
    CPWAIT0();
    __syncthreads();

    u32 aQh[2][4], aQl[2][4];
    #pragma unroll
    for (int kt = 0; kt < 2; kt++) {
        int rowA = warp * 16 + r + ((g & 1) << 3);
        int kcol = kt * 16 + ((g >> 1) << 3);
        u32 off = (u32)(rowA * 40 + kcol) * 2;
        LDSM4(aQh[kt], sQhiB + off);
        LDSM4(aQl[kt], sQloB + off);
    }

    float accS[16][4];
    #pragma unroll
    for (int nt = 0; nt < 16; nt++)
        #pragma unroll
        for (int i = 0; i < 4; i++) accS[nt][i] = 0.0f;

    #pragma unroll
    for (int kt = 0; kt < 2; kt++) {
        #pragma unroll
        for (int ng = 0; ng < 8; ng++) {
            u32 kbh[4], kbl[4];
            int nrow = ng * 16 + r + ((g & 1) << 3);
            int kcol = kt * 16 + ((g >> 1) << 3);
            u32 off = (u32)(nrow * 40 + kcol) * 2;
            LDSM4(kbh, sKhiB + off);
            LDSM4(kbl, sKloB + off);
            u32 b0h[2] = {kbh[0], kbh[2]}, b1h[2] = {kbh[1], kbh[3]};
            u32 b0l[2] = {kbl[0], kbl[2]}, b1l[2] = {kbl[1], kbl[3]};
            MMA16816(accS[ng * 2], aQh[kt], b0h);
            MMA16816(accS[ng * 2], aQh[kt], b0l);
            MMA16816(accS[ng * 2], aQl[kt], b0h);
            MMA16816(accS[ng * 2 + 1], aQh[kt], b1h);
            MMA16816(accS[ng * 2 + 1], aQh[kt], b1l);
            MMA16816(accS[ng * 2 + 1], aQl[kt], b1h);
        }
    }

    #pragma unroll
    for (int nt = 0; nt < 16; nt++) {
        int c0 = nt * 8 + (lane & 3) * 2;
        int w2 = c0 >> 5, bit = c0 & 31;
        if (!((mA[w2] >> bit) & 1u))       accS[nt][0] = -INFINITY;
        if (!((mA[w2] >> (bit + 1)) & 1u)) accS[nt][1] = -INFINITY;
        if (!((mB[w2] >> bit) & 1u))       accS[nt][2] = -INFINITY;
        if (!((mB[w2] >> (bit + 1)) & 1u)) accS[nt][3] = -INFINITY;
    }

    float mxA = -INFINITY, mxB = -INFINITY;
    #pragma unroll
    for (int nt = 0; nt < 16; nt++) {
        mxA = fmaxf(mxA, fmaxf(accS[nt][0], accS[nt][1]));
        mxB = fmaxf(mxB, fmaxf(accS[nt][2], accS[nt][3]));
    }
    mxA = fmaxf(mxA, __shfl_xor_sync(0xffffffffu, mxA, 1));
    mxA = fmaxf(mxA, __shfl_xor_sync(0xffffffffu, mxA, 2));
    mxB = fmaxf(mxB, __shfl_xor_sync(0xffffffffu, mxB, 1));
    mxB = fmaxf(mxB, __shfl_xor_sync(0xffffffffu, mxB, 2));

    float sA = 0.0f, sB = 0.0f;
    #pragma unroll
    for (int nt = 0; nt < 16; nt++) {
        accS[nt][0] = exp2f(accS[nt][0] - mxA);
        accS[nt][1] = exp2f(accS[nt][1] - mxA);
        accS[nt][2] = exp2f(accS[nt][2] - mxB);
        accS[nt][3] = exp2f(accS[nt][3] - mxB);
        sA += accS[nt][0] + accS[nt][1];
        sB += accS[nt][2] + accS[nt][3];
    }
    sA += __shfl_xor_sync(0xffffffffu, sA, 1);
    sA += __shfl_xor_sync(0xffffffffu, sA, 2);
    sB += __shfl_xor_sync(0xffffffffu, sB, 1);
    sB += __shfl_xor_sync(0xffffffffu, sB, 2);
    float invA = 1.0f / sA, invB = 1.0f / sB;

    float accO[4][4];
    #pragma unroll
    for (int nt = 0; nt < 4; nt++)
        #pragma unroll
        for (int i = 0; i < 4; i++) accO[nt][i] = 0.0f;

    #pragma unroll
    for (int kt = 0; kt < 8; kt++) {
        u32 ph[4], plo[4];
        packP(accS[2 * kt][0],     accS[2 * kt][1],     ph[0], plo[0]);
        packP(accS[2 * kt][2],     accS[2 * kt][3],     ph[1], plo[1]);
        packP(accS[2 * kt + 1][0], accS[2 * kt + 1][1], ph[2], plo[2]);
        packP(accS[2 * kt + 1][2], accS[2 * kt + 1][3], ph[3], plo[3]);
        #pragma unroll
        for (int n16 = 0; n16 < 2; n16++) {
            u32 vbh[4], vbl[4];
            int krow = kt * 16 + r + ((g & 1) << 3);
            int ncol = n16 * 16 + ((g >> 1) << 3);
            u32 off = (u32)(krow * 40 + ncol) * 2;
            LDSM4T(vbh, sVhiB + off);
            LDSM4T(vbl, sVloB + off);
            MMA16816(accO[n16 * 2], ph, (&vbh[0]));
            MMA16816(accO[n16 * 2], ph, (&vbl[0]));
            MMA16816(accO[n16 * 2], plo, (&vbh[0]));
            MMA16816(accO[n16 * 2 + 1], ph, (&vbh[2]));
            MMA16816(accO[n16 * 2 + 1], ph, (&vbl[2]));
            MMA16816(accO[n16 * 2 + 1], plo, (&vbh[2]));
        }
    }

    #pragma unroll
    for (int nt = 0; nt < 4; nt++) {
        int c0 = nt * 8 + (lane & 3) * 2;
        int oA = (b * 128 + rA) * 256 + h * 32 + c0;
        int oB = (b * 128 + rB) * 256 + h * 32 + c0;
        u32 hi, lo;
        packP(accO[nt][0] * invA, accO[nt][1] * invA, hi, lo);
        *(u32*)&g_aohi[oA] = hi; *(u32*)&g_aolo[oA] = lo;
        packP(accO[nt][2] * invB, accO[nt][3] * invB, hi, lo);
        *(u32*)&g_aohi[oB] = hi; *(u32*)&g_aolo[oB] = lo;
    }
}

// ---------------- launch helpers ----------------------------------------------
template <typename K, typename... Args>
static void launchPDL(K kernel, int grid, int smem, Args... args)
{
    cudaLaunchConfig_t cfg = {};
    cfg.gridDim = dim3(grid, 1, 1);
    cfg.blockDim = dim3(256, 1, 1);
    cfg.dynamicSmemBytes = (size_t)smem;
    cfg.stream = 0;
    cudaLaunchAttribute at[1];
    at[0].id = cudaLaunchAttributeProgrammaticStreamSerialization;
    at[0].val.programmaticStreamSerializationAllowed = 1;
    cfg.attrs = at;
    cfg.numAttrs = 1;
    cudaLaunchKernelEx(&cfg, kernel, args...);
}

// ---------------- launch ------------------------------------------------------
extern "C" void kernel_launch(void* const* d_in, const int* in_sizes, int n_in,
                              void* d_out, int out_size)
{
    const float* x        = (const float*)d_in[0];
    const float* gumbel_u = (const float*)d_in[1];
    const float* memory_w = (const float*)d_in[2];
    const float* fc_out_w = (const float*)d_in[3];
    const float* fc_out_b = (const float*)d_in[4];
    const float* fc_cat_w = (const float*)d_in[5];
    const float* fc_cat_b = (const float*)d_in[6];
    const float* wq       = (const float*)d_in[7];
    const float* bq       = (const float*)d_in[8];
    const float* wk       = (const float*)d_in[9];
    const float* bk       = (const float*)d_in[10];
    const float* wv       = (const float*)d_in[11];
    const float* bv       = (const float*)d_in[12];
    const float* out_w    = (const float*)d_in[13];
    const float* out_b    = (const float*)d_in[14];
    const float* mlp_w1   = (const float*)d_in[15];
    const float* mlp_b1   = (const float*)d_in[16];
    const float* mlp_w2   = (const float*)d_in[17];
    const float* mlp_b2   = (const float*)d_in[18];

    float *fA, *fB, *cb;
    cudaGetSymbolAddress((void**)&fA, g_fA);
    cudaGetSymbolAddress((void**)&fB, g_fB);
    cudaGetSymbolAddress((void**)&cb, g_cb);
    bf16 *cwhi, *cwlo, *h1hi, *h1lo, *qkvhi, *qkvlo, *aohi, *aolo;
    cudaGetSymbolAddress((void**)&cwhi, g_cwhi);
    cudaGetSymbolAddress((void**)&cwlo, g_cwlo);
    cudaGetSymbolAddress((void**)&h1hi, g_h1hi);
    cudaGetSymbolAddress((void**)&h1lo, g_h1lo);
    cudaGetSymbolAddress((void**)&qkvhi, g_qkvhi);
    cudaGetSymbolAddress((void**)&qkvlo, g_qkvlo);
    cudaGetSymbolAddress((void**)&aohi, g_aohi);
    cudaGetSymbolAddress((void**)&aolo, g_aolo);

    static bool attrSet = false;
    if (!attrSet) {
        cudaFuncSetAttribute(k_attn, cudaFuncAttributeMaxDynamicSharedMemorySize, ATTN_SMEM);
        cudaFuncSetAttribute(k_g64_ff, cudaFuncAttributeMaxDynamicSharedMemorySize, GEMM64_SMEM);
        cudaFuncSetAttribute(k_g64_pp_ca, cudaFuncAttributeMaxDynamicSharedMemorySize, GEMM64_SMEM);
        cudaFuncSetAttribute(k_g64_pf, cudaFuncAttributeMaxDynamicSharedMemorySize, GEMM64_SMEM);
        attrSet = true;
    }

    ConnArgs CA = { fc_out_b, fc_cat_w, fc_cat_b, gumbel_u,
                    mlp_b2, wq, wk, wv, bq, bk, bv };

    // L1: fA(64) + fB(64) + mlp1(256) + compose(3x16) + bias(3) = 435 blocks
    {
        Job6 J = {};
        J.Af[0] = memory_w; J.Wf[0] = fc_out_w;
        J.Cf[0] = fA; J.scale[0] = 1.0f; J.gather[0] = 1; J.end[0] = 64;
        J.Af[1] = memory_w; J.Wf[1] = fc_out_w + 65536;
        J.Cf[1] = fB; J.scale[1] = 1.0f; J.gather[1] = 1; J.end[1] = 128;
        J.Af[2] = x; J.Wf[2] = mlp_w1; J.bias[2] = mlp_b1;
        J.Chi[2] = h1hi; J.Clo[2] = h1lo;
        J.scale[2] = 1.0f; J.act[2] = 1; J.storeMode[2] = 1; J.end[2] = 384;
        const float* wz[3] = { wq, wk, wv };
        for (int z = 0; z < 3; z++) {
            int ji = 3 + z;
            J.Af[ji] = mlp_w2; J.Wf[ji] = wz[z];
            J.Chi[ji] = cwhi + z * 65536; J.Clo[ji] = cwlo + z * 65536;
            J.scale[ji] = 1.0f; J.storeMode[ji] = 1; J.end[ji] = 384 + (z + 1) * 16;
        }
        J.totTiles = 432; J.nconn = 0;
        k_g64_ff<<<435, 256, GEMM64_SMEM>>>(J, CA);
    }

    // L2: QKV (3 x 256 tiles, cp.async) + conn(128) = 896 blocks  [PDL]
    {
        Job6 J = {};
        // fold log2(e) into Q scale so softmax uses exp2f
        const float scaleQ = 0.17677669529663687f * 1.4426950408889634f;
        for (int z = 0; z < 3; z++) {
            J.Ahi[z] = h1hi; J.Alo[z] = h1lo;
            J.Whi[z] = cwhi + z * 65536; J.Wlo[z] = cwlo + z * 65536;
            J.bias[z] = cb + z * 256;
            J.Chi[z] = qkvhi + z * 1048576; J.Clo[z] = qkvlo + z * 1048576;
            J.scale[z] = (z == 0) ? scaleQ : 1.0f;
            J.storeMode[z] = 2;
            J.end[z] = (z + 1) * 256;
        }
        J.end[3] = J.end[4] = J.end[5] = 768;
        J.totTiles = 768; J.nconn = 128;
        launchPDL(k_g64_pp_ca, 896, GEMM64_SMEM, J, CA);
    }

    // L3: attention (256 CTAs)  [PDL]
    launchPDL(k_attn, 256, ATTN_SMEM);

    // L4: output projection -> d_out (256 tiles)  [PDL]
    {
        Job6 J = {};
        J.Ahi[0] = aohi; J.Alo[0] = aolo; J.Wf[0] = out_w;
        J.bias[0] = out_b; J.Cf[0] = (float*)d_out;
        J.scale[0] = 1.0f; J.end[0] = 256;
        J.end[1] = J.end[2] = J.end[3] = J.end[4] = J.end[5] = 256;
        J.totTiles = 256; J.nconn = 0;
        launchPDL(k_g64_pf, 256, GEMM64_SMEM, J, CA);
    }
}

// round 17
// speedup vs baseline: 1.4631x; 1.0266x over previous
#include <cuda_runtime.h>
#include <cuda_bf16.h>
#include <math.h>

// Problem constants: B=32, N=128, D=256, H=8, DK=32
typedef unsigned int u32;
typedef __nv_bfloat16 bf16;

// ---------------- scratch (static device globals; no allocation) -------------
__device__ __align__(16) float g_fA[1024 * 256];
__device__ __align__(16) float g_fB[1024 * 256];
__device__ __align__(16) u32 g_cmask[8 * 128 * 4];       // conn bitmask [h][i][4 words]
__device__ __align__(16) float g_cb[3 * 256];            // composed QKV biases
__device__ __align__(16) bf16 g_cwhi[3 * 65536];         // composed W2@W{q,k,v}
__device__ __align__(16) bf16 g_cwlo[3 * 65536];
__device__ __align__(16) bf16 g_h1hi[4096 * 256];
__device__ __align__(16) bf16 g_h1lo[4096 * 256];
__device__ __align__(16) bf16 g_qkvhi[3 * 1048576];      // [op][B,H,N,DK] planes
__device__ __align__(16) bf16 g_qkvlo[3 * 1048576];
__device__ __align__(16) bf16 g_aohi[4096 * 256];
__device__ __align__(16) bf16 g_aolo[4096 * 256];

#define GEMM64_SMEM 73728   // 4 arrays x 2buf x 4608 bf16
#define ATTN_SMEM 61440

__device__ __forceinline__ float gelu_tanh(float x) {
    float x3 = x * x * x;
    float t = tanhf(0.7978845608028654f * (x + 0.044715f * x3));
    return 0.5f * x * (1.0f + t);
}

__device__ __forceinline__ void split_bf16(float v, bf16& h, bf16& l) {
    h = __float2bfloat16_rn(v);
    l = __float2bfloat16_rn(v - __bfloat162float(h));
}

__device__ __forceinline__ void cvt4(float4 v, uint2& hi, uint2& lo) {
    bf16 h0, l0, h1, l1, h2, l2, h3, l3;
    split_bf16(v.x, h0, l0); split_bf16(v.y, h1, l1);
    split_bf16(v.z, h2, l2); split_bf16(v.w, h3, l3);
    __nv_bfloat162 a, b, c, d;
    a.x = h0; a.y = h1; b.x = h2; b.y = h3;
    c.x = l0; c.y = l1; d.x = l2; d.y = l3;
    hi.x = *(u32*)&a; hi.y = *(u32*)&b;
    lo.x = *(u32*)&c; lo.y = *(u32*)&d;
}

__device__ __forceinline__ void packP(float x, float y, u32& hi, u32& lo) {
    bf16 hx, lx, hy, ly;
    split_bf16(x, hx, lx);
    split_bf16(y, hy, ly);
    __nv_bfloat162 H; H.x = hx; H.y = hy;
    __nv_bfloat162 L; L.x = lx; L.y = ly;
    hi = *(u32*)&H; lo = *(u32*)&L;
}

#define LDSM4(r, addr)                                                        \
    asm volatile("ldmatrix.sync.aligned.m8n8.x4.shared.b16 {%0,%1,%2,%3}, [%4];" \
                 : "=r"(r[0]), "=r"(r[1]), "=r"(r[2]), "=r"(r[3]) : "r"(addr))

#define LDSM4T(r, addr)                                                       \
    asm volatile("ldmatrix.sync.aligned.m8n8.x4.trans.shared.b16 {%0,%1,%2,%3}, [%4];" \
                 : "=r"(r[0]), "=r"(r[1]), "=r"(r[2]), "=r"(r[3]) : "r"(addr))

#define MMA16816(d, a, b)                                                     \
    asm volatile("mma.sync.aligned.m16n8k16.row.col.f32.bf16.bf16.f32 "       \
                 "{%0,%1,%2,%3}, {%4,%5,%6,%7}, {%8,%9}, {%0,%1,%2,%3};"      \
                 : "+f"(d[0]), "+f"(d[1]), "+f"(d[2]), "+f"(d[3])             \
                 : "r"(a[0]), "r"(a[1]), "r"(a[2]), "r"(a[3]),                \
                   "r"(b[0]), "r"(b[1]))

#define CPASYNC16(dst, src)                                                   \
    asm volatile("cp.async.cg.shared.global [%0], [%1], 16;"                  \
                 :: "r"(dst), "l"(src))
#define CPCOMMIT() asm volatile("cp.async.commit_group;" ::: "memory")
#define CPWAIT0()  asm volatile("cp.async.wait_group 0;" ::: "memory")

// ---------------- job table --------------------------------------------------
struct Job6 {
    const float* Af[6];
    const bf16 *Ahi[6], *Alo[6];
    const float* Wf[6];
    const bf16 *Whi[6], *Wlo[6];
    const float* bias[6];
    float* Cf[6];
    bf16 *Chi[6], *Clo[6];
    float scale[6];
    int gather[6], act[6], storeMode[6];   // storeMode: 0 fp32, 1 planes, 2 QKV
    int end[6];
    int totTiles, nconn;
};

struct ConnArgs {
    const float *fcb, *fccw, *fccb, *gu;
    const float *b2, *wq, *wk, *wv, *bq, *bk, *bv;
};

__device__ void connJob(int cid, ConnArgs CA, char* smemRaw);

__device__ void biasJob(int z, ConnArgs CA) {
    int c = threadIdx.x;
    const float* wz = (z == 0) ? CA.wq : (z == 1) ? CA.wk : CA.wv;
    const float* bz = (z == 0) ? CA.bq : (z == 1) ? CA.bk : CA.bv;
    float acc = bz[c];
    for (int d = 0; d < 256; d++)
        acc = fmaf(CA.b2[d], wz[d * 256 + c], acc);
    g_cb[z * 256 + c] = acc;
}

// ---------------- shared epilogue for GEMM-64 --------------------------------
__device__ __forceinline__ void gemm64Epilogue(
    const Job6& J, int ji, int rowBase, int colBase,
    float accH[4][4], float accM[4][4])
{
    int lane = threadIdx.x & 31;
    int warp = threadIdx.x >> 5;
    int wm = warp >> 1, wn = warp & 1;

    const float* bias = J.bias[ji];
    float scl = J.scale[ji];
    int sMode = J.storeMode[ji], act = J.act[ji];

    #pragma unroll
    for (int nt = 0; nt < 4; nt++) {
        int row0 = rowBase + wm * 16 + (lane >> 2);
        int col0 = colBase + wn * 32 + nt * 8 + (lane & 3) * 2;
        float bv0 = bias ? bias[col0] : 0.0f;
        float bv1 = bias ? bias[col0 + 1] : 0.0f;
        #pragma unroll
        for (int half = 0; half < 2; half++) {
            int row = row0 + half * 8;
            float v0 = (accH[nt][half * 2 + 0] + accM[nt][half * 2 + 0] + bv0) * scl;
            float v1 = (accH[nt][half * 2 + 1] + accM[nt][half * 2 + 1] + bv1) * scl;
            if (act) { v0 = gelu_tanh(v0); v1 = gelu_tanh(v1); }
            if (sMode == 0) {
                *(float2*)&J.Cf[ji][row * 256 + col0] = make_float2(v0, v1);
            } else if (sMode == 1) {
                u32 hi, lo;
                packP(v0, v1, hi, lo);
                *(u32*)&J.Chi[ji][row * 256 + col0] = hi;
                *(u32*)&J.Clo[ji][row * 256 + col0] = lo;
            } else {
                int b = row >> 7, n = row & 127;
                int h = col0 >> 5, dk = col0 & 31;
                int idx = (((b * 8 + h) * 128 + n) * 32) + dk;
                u32 hi, lo;
                packP(v0, v1, hi, lo);
                *(u32*)&J.Chi[ji][idx] = hi;
                *(u32*)&J.Clo[ji][idx] = lo;
            }
        }
    }
}

// ---------------- GEMM-64 mainloop compute (one k-iter) ----------------------
__device__ __forceinline__ void gemm64Compute(
    int bb, u32 sAhiB, u32 sAloB, u32 sWhiB, u32 sWloB,
    float accH[4][4], float accM[4][4])
{
    int lane = threadIdx.x & 31;
    int warp = threadIdx.x >> 5;
    int wm = warp >> 1, wn = warp & 1;
    int g = lane >> 3, r = lane & 7;

    #pragma unroll
    for (int ks = 0; ks < 64; ks += 16) {
        u32 ah[4], al[4];
        {
            int rowA = wm * 16 + r + ((g & 1) << 3);
            int kcol = ks + ((g >> 1) << 3);
            u32 off = (u32)(bb * 4608 + rowA * 72 + kcol) * 2;
            LDSM4(ah, sAhiB + off);
            LDSM4(al, sAloB + off);
        }
        #pragma unroll
        for (int n16 = 0; n16 < 2; n16++) {
            u32 bh[4], bl[4];
            int krow = ks + r + ((g & 1) << 3);
            int ncol = wn * 32 + n16 * 16 + ((g >> 1) << 3);
            u32 off = (u32)(bb * 4608 + krow * 72 + ncol) * 2;
            LDSM4T(bh, sWhiB + off);
            LDSM4T(bl, sWloB + off);
            MMA16816(accH[n16 * 2], ah, (&bh[0]));
            MMA16816(accM[n16 * 2], ah, (&bl[0]));
            MMA16816(accM[n16 * 2], al, (&bh[0]));
            MMA16816(accH[n16 * 2 + 1], ah, (&bh[2]));
            MMA16816(accM[n16 * 2 + 1], ah, (&bl[2]));
            MMA16816(accM[n16 * 2 + 1], al, (&bh[2]));
        }
    }
}

// ---------------- GEMM-64: fp32 x fp32, register-staged (L1) -----------------
__global__ void __launch_bounds__(256)
k_g64_ff(Job6 J, ConnArgs CA)
{
    extern __shared__ char smemRaw[];
    int jid = blockIdx.x;
    if (jid >= J.totTiles) {
        int e = jid - J.totTiles;
        if (e < J.nconn) connJob(e, CA, smemRaw);
        else biasJob(e - J.nconn, CA);
        return;
    }
    int ji = 0;
    #pragma unroll
    for (int k = 0; k < 5; k++) if (jid >= J.end[k]) ji = k + 1;
    int tile = jid - (ji ? J.end[ji - 1] : 0);

    bf16* sAhi = (bf16*)smemRaw;
    bf16* sAlo = sAhi + 2 * 4608;
    bf16* sWhi = sAlo + 2 * 4608;
    bf16* sWlo = sWhi + 2 * 4608;

    int rowBase = (tile >> 2) * 64;
    int colBase = (tile & 3) * 64;

    int t = threadIdx.x;
    u32 sAhiB = (u32)__cvta_generic_to_shared(sAhi);
    u32 sAloB = (u32)__cvta_generic_to_shared(sAlo);
    u32 sWhiB = (u32)__cvta_generic_to_shared(sWhi);
    u32 sWloB = (u32)__cvta_generic_to_shared(sWlo);

    float4 fa[4], fw[4];

    auto loadTile = [&](int kt) {
        #pragma unroll
        for (int u = 0; u < 4; u++) {
            int c = t + 256 * u;
            int row = c >> 4, seg = c & 15;
            int rr = rowBase + row;
            const float* src = J.gather[ji]
                ? J.Af[ji] + (rr & 127) * 2048 + (rr >> 7) * 256
                : J.Af[ji] + rr * 256;
            fa[u] = *(const float4*)&src[kt + seg * 4];
            fw[u] = *(const float4*)&J.Wf[ji][(kt + row) * 256 + colBase + seg * 4];
        }
    };

    auto storeTile = [&](int bb) {
        #pragma unroll
        for (int u = 0; u < 4; u++) {
            uint2 hi, lo;
            int c = t + 256 * u;
            int off = bb * 4608 + (c >> 4) * 72 + (c & 15) * 4;
            cvt4(fa[u], hi, lo);
            *(uint2*)&sAhi[off] = hi; *(uint2*)&sAlo[off] = lo;
            cvt4(fw[u], hi, lo);
            *(uint2*)&sWhi[off] = hi; *(uint2*)&sWlo[off] = lo;
        }
    };

    float accH[4][4], accM[4][4];
    #pragma unroll
    for (int nt = 0; nt < 4; nt++)
        #pragma unroll
        for (int i = 0; i < 4; i++) { accH[nt][i] = 0.0f; accM[nt][i] = 0.0f; }

    loadTile(0);
    storeTile(0);
    __syncthreads();

    #pragma unroll
    for (int it = 0; it < 4; it++) {
        int bb = it & 1;
        if (it < 3) loadTile((it + 1) * 64);
        gemm64Compute(bb, sAhiB, sAloB, sWhiB, sWloB, accH, accM);
        if (it < 3) {
            storeTile(1 - bb);
            __syncthreads();
        }
    }

    gemm64Epilogue(J, ji, rowBase, colBase, accH, accM);
}

// ---------------- GEMM-64 planes x planes with cp.async (L2) -----------------
__global__ void __launch_bounds__(256)
k_g64_pp_ca(Job6 J, ConnArgs CA)
{
    extern __shared__ char smemRaw[];
#if __CUDA_ARCH__ >= 900
    cudaGridDependencySynchronize();
#endif
    int jid = blockIdx.x;
    if (jid >= J.totTiles) {
        int e = jid - J.totTiles;
        if (e < J.nconn) connJob(e, CA, smemRaw);
        else biasJob(e - J.nconn, CA);
        return;
    }
    int ji = 0;
    #pragma unroll
    for (int k = 0; k < 5; k++) if (jid >= J.end[k]) ji = k + 1;
    int tile = jid - (ji ? J.end[ji - 1] : 0);

    u32 sAhiB = (u32)__cvta_generic_to_shared(smemRaw);
    u32 sAloB = sAhiB + 2 * 4608 * 2;
    u32 sWhiB = sAloB + 2 * 4608 * 2;
    u32 sWloB = sWhiB + 2 * 4608 * 2;

    int rowBase = (tile >> 2) * 64;
    int colBase = (tile & 3) * 64;

    int t = threadIdx.x;
    int pl = t >> 7, ps = t & 127;

    const bf16* asrc = pl ? J.Alo[ji] : J.Ahi[ji];
    const bf16* wsrc = pl ? J.Wlo[ji] : J.Whi[ji];
    u32 adB = pl ? sAloB : sAhiB;
    u32 wdB = pl ? sWloB : sWhiB;

    auto cpTile = [&](int kt, int bb) {
        #pragma unroll
        for (int u = 0; u < 4; u++) {
            int c = ps + 128 * u;
            u32 off = (u32)(bb * 4608 + (c >> 3) * 72 + (c & 7) * 8) * 2;
            CPASYNC16(adB + off, &asrc[(rowBase + (c >> 3)) * 256 + kt + (c & 7) * 8]);
            CPASYNC16(wdB + off, &wsrc[(kt + (c >> 3)) * 256 + colBase + (c & 7) * 8]);
        }
        CPCOMMIT();
    };

    float accH[4][4], accM[4][4];
    #pragma unroll
    for (int nt = 0; nt < 4; nt++)
        #pragma unroll
        for (int i = 0; i < 4; i++) { accH[nt][i] = 0.0f; accM[nt][i] = 0.0f; }

    cpTile(0, 0);

    #pragma unroll
    for (int it = 0; it < 4; it++) {
        int bb = it & 1;
        CPWAIT0();
        __syncthreads();
        if (it < 3) cpTile((it + 1) * 64, 1 - bb);
        gemm64Compute(bb, sAhiB, sAloB, sWhiB, sWloB, accH, accM);
    }

    gemm64Epilogue(J, ji, rowBase, colBase, accH, accM);
}

// ---------------- GEMM-64 hybrid: A planes via cp.async, W fp32 reg (L4) -----
__global__ void __launch_bounds__(256)
k_g64_pf_ca(Job6 J, ConnArgs CA)
{
    extern __shared__ char smemRaw[];
#if __CUDA_ARCH__ >= 900
    cudaGridDependencySynchronize();
#endif
    int jid = blockIdx.x;
    if (jid >= J.totTiles) {
        int e = jid - J.totTiles;
        if (e < J.nconn) connJob(e, CA, smemRaw);
        else biasJob(e - J.nconn, CA);
        return;
    }
    int ji = 0;
    #pragma unroll
    for (int k = 0; k < 5; k++) if (jid >= J.end[k]) ji = k + 1;
    int tile = jid - (ji ? J.end[ji - 1] : 0);

    bf16* sWhi = (bf16*)smemRaw + 2 * 4608 * 2;   // W arrays after the 2 A arrays
    bf16* sWlo = sWhi + 2 * 4608;

    u32 sAhiB = (u32)__cvta_generic_to_shared(smemRaw);
    u32 sAloB = sAhiB + 2 * 4608 * 2;
    u32 sWhiB = (u32)__cvta_generic_to_shared(sWhi);
    u32 sWloB = (u32)__cvta_generic_to_shared(sWlo);

    int rowBase = (tile >> 2) * 64;
    int colBase = (tile & 3) * 64;

    int t = threadIdx.x;
    int pl = t >> 7, ps = t & 127;

    const bf16* asrc = pl ? J.Alo[ji] : J.Ahi[ji];
    u32 adB = pl ? sAloB : sAhiB;

    float4 fw[4];

    auto cpA = [&](int kt, int bb) {
        #pragma unroll
        for (int u = 0; u < 4; u++) {
            int c = ps + 128 * u;
            u32 off = (u32)(bb * 4608 + (c >> 3) * 72 + (c & 7) * 8) * 2;
            CPASYNC16(adB + off, &asrc[(rowBase + (c >> 3)) * 256 + kt + (c & 7) * 8]);
        }
        CPCOMMIT();
    };

    auto loadW = [&](int kt) {
        #pragma unroll
        for (int u = 0; u < 4; u++) {
            int c = t + 256 * u;
            fw[u] = *(const float4*)&J.Wf[ji][(kt + (c >> 4)) * 256 + colBase + (c & 15) * 4];
        }
    };

    auto storeW = [&](int bb) {
        #pragma unroll
        for (int u = 0; u < 4; u++) {
            uint2 hi, lo;
            cvt4(fw[u], hi, lo);
            int c = t + 256 * u;
            int off = bb * 4608 + (c >> 4) * 72 + (c & 15) * 4;
            *(uint2*)&sWhi[off] = hi; *(uint2*)&sWlo[off] = lo;
        }
    };

    float accH[4][4], accM[4][4];
    #pragma unroll
    for (int nt = 0; nt < 4; nt++)
        #pragma unroll
        for (int i = 0; i < 4; i++) { accH[nt][i] = 0.0f; accM[nt][i] = 0.0f; }

    cpA(0, 0);
    loadW(0);
    storeW(0);

    #pragma unroll
    for (int it = 0; it < 4; it++) {
        int bb = it & 1;
        CPWAIT0();
        __syncthreads();            // A buffer bb complete, W buffer bb stored
        if (it < 3) {
            cpA((it + 1) * 64, 1 - bb);
            loadW((it + 1) * 64);   // W LDGs overlap compute below
        }
        gemm64Compute(bb, sAhiB, sAloB, sWhiB, sWloB, accH, accM);
        if (it < 3) storeW(1 - bb); // after compute: writes other buffer (safe; sync at loop top)
    }

    gemm64Epilogue(J, ji, rowBase, colBase, accH, accM);
}

// ---------------- conn job: 32i x 32j, 256 threads; emits bitmask ------------
__device__ void connJob(int cid, ConnArgs CA, char* smemRaw)
{
    float (*Aj)[33] = (float(*)[33])smemRaw;
    float (*Bi)[33] = (float(*)[33])(smemRaw + 32 * 33 * 4);
    float* Cs0 = (float*)(smemRaw + 2 * 32 * 33 * 4);
    float* Cs1 = Cs0 + 256;

    int h = cid >> 4;
    int ibase = ((cid >> 2) & 3) * 32;
    int jbase = (cid & 3) * 32;
    int t = threadIdx.x;
    int tx = t & 15, ty = t >> 4;

    Cs0[t] = CA.fccw[2 * t];
    Cs1[t] = CA.fccw[2 * t + 1];

    float l0[2][2] = {{0.f, 0.f}, {0.f, 0.f}};
    float l1[2][2] = {{0.f, 0.f}, {0.f, 0.f}};

    for (int d0 = 0; d0 < 256; d0 += 32) {
        if (d0) __syncthreads();
        int jr = t >> 3, c = (t & 7) * 4;
        float4 va = *(const float4*)&g_fA[(h * 128 + jbase + jr) * 256 + d0 + c];
        Aj[jr][c] = va.x; Aj[jr][c + 1] = va.y; Aj[jr][c + 2] = va.z; Aj[jr][c + 3] = va.w;
        float4 vb = *(const float4*)&g_fB[(h * 128 + ibase + jr) * 256 + d0 + c];
        float4 o = *(const float4*)&CA.fcb[d0 + c];
        Bi[jr][c] = vb.x + o.x; Bi[jr][c + 1] = vb.y + o.y;
        Bi[jr][c + 2] = vb.z + o.z; Bi[jr][c + 3] = vb.w + o.w;
        __syncthreads();

        #pragma unroll
        for (int dd = 0; dd < 32; dd++) {
            float a0 = Aj[tx * 2][dd], a1 = Aj[tx * 2 + 1][dd];
            float b0 = Bi[ty * 2][dd], b1 = Bi[ty * 2 + 1][dd];
            float c0v = Cs0[d0 + dd], c1v = Cs1[d0 + dd];
            float r00 = fmaxf(a0 + b0, 0.f), r10 = fmaxf(a1 + b0, 0.f);
            float r01 = fmaxf(a0 + b1, 0.f), r11 = fmaxf(a1 + b1, 0.f);
            l0[0][0] = fmaf(r00, c0v, l0[0][0]); l1[0][0] = fmaf(r00, c1v, l1[0][0]);
            l0[0][1] = fmaf(r10, c0v, l0[0][1]); l1[0][1] = fmaf(r10, c1v, l1[0][1]);
            l0[1][0] = fmaf(r01, c0v, l0[1][0]); l1[1][0] = fmaf(r01, c1v, l1[1][0]);
            l0[1][1] = fmaf(r11, c0v, l0[1][1]); l1[1][1] = fmaf(r11, c1v, l1[1][1]);
        }
    }

    float cb0 = CA.fccb[0], cb1 = CA.fccb[1];
    int lane = t & 31;
    u32 hmask = (lane < 16) ? 0x0000FFFFu : 0xFFFF0000u;
    int jw = jbase >> 5;
    #pragma unroll
    for (int ii = 0; ii < 2; ii++) {
        int i = ibase + ty * 2 + ii;
        u32 v = 0;
        #pragma unroll
        for (int jj = 0; jj < 2; jj++) {
            int j = jbase + tx * 2 + jj;
            int idx = (h * 128 + i) * 128 + j;
            float2 u2 = *(const float2*)&CA.gu[idx * 2];
            float gg0 = -logf(-logf(u2.x + 1e-10f) + 1e-10f);
            float gg1 = -logf(-logf(u2.y + 1e-10f) + 1e-10f);
            if ((l1[ii][jj] + cb1 + gg1) > (l0[ii][jj] + cb0 + gg0))
                v |= (1u << (tx * 2 + jj));
        }
        u32 word = __reduce_or_sync(hmask, v);
        if (tx == 0) g_cmask[(h * 128 + i) * 4 + jw] = word;
    }
}

// ---------------- attention-only kernel: one CTA per (b,h), 256 threads ------
// S in log2 domain (log2e folded into Q) -> exp2f softmax. cp.async staging.
__global__ void __launch_bounds__(256)
k_attn()
{
    extern __shared__ char sm[];
#if __CUDA_ARCH__ >= 900
    cudaGridDependencySynchronize();
#endif
    u32 smB = (u32)__cvta_generic_to_shared(sm);
    u32 sQhiB = smB, sQloB = smB + 10240;
    u32 sKhiB = smB + 20480, sKloB = smB + 30720;
    u32 sVhiB = smB + 40960, sVloB = smB + 51200;

    int bid = blockIdx.x;
    int b = bid >> 3, h = bid & 7;
    int t = threadIdx.x;
    int warp = t >> 5, lane = t & 31;
    int g = lane >> 3, r = lane & 7;

    // stage Q/K/V planes via cp.async (overlaps the mask LDGs below)
    {
        int gbase = bid * 4096;
        #pragma unroll
        for (int u = 0; u < 12; u++) {
            int c = t + u * 256;
            int plane = c >> 9;
            int i = c & 511;
            int row = i >> 2, seg = i & 3;
            int op = plane >> 1;
            const bf16* src = (plane & 1) ? (g_qkvlo + op * 1048576)
                                          : (g_qkvhi + op * 1048576);
            int pidx = op * 2 + (plane & 1);
            u32 dst = smB + (u32)(pidx * 5120 + row * 40 + seg * 8) * 2;
            CPASYNC16(dst, &src[gbase + row * 32 + seg * 8]);
        }
        CPCOMMIT();
    }

    // mask words from gmem (LDGs overlap bulk copies)
    int rA = warp * 16 + (lane >> 2);
    int rB = rA + 8;
    u32 mA[4], mB[4];
    {
        const u32* cm = g_cmask + h * 512;
        #pragma unroll
        for (int w2 = 0; w2 < 4; w2++) {
            mA[w2] = cm[rA * 4 + w2];
            mB[w2] = cm[rB * 4 + w2];
        }
    }
    CPWAIT0();
    __syncthreads();

    u32 aQh[2][4], aQl[2][4];
    #pragma unroll
    for (int kt = 0; kt < 2; kt++) {
        int rowA = warp * 16 + r + ((g & 1) << 3);
        int kcol = kt * 16 + ((g >> 1) << 3);
        u32 off = (u32)(rowA * 40 + kcol) * 2;
        LDSM4(aQh[kt], sQhiB + off);
        LDSM4(aQl[kt], sQloB + off);
    }

    float accS[16][4];
    #pragma unroll
    for (int nt = 0; nt < 16; nt++)
        #pragma unroll
        for (int i = 0; i < 4; i++) accS[nt][i] = 0.0f;

    #pragma unroll
    for (int kt = 0; kt < 2; kt++) {
        #pragma unroll
        for (int ng = 0; ng < 8; ng++) {
            u32 kbh[4], kbl[4];
            int nrow = ng * 16 + r + ((g & 1) << 3);
            int kcol = kt * 16 + ((g >> 1) << 3);
            u32 off = (u32)(nrow * 40 + kcol) * 2;
            LDSM4(kbh, sKhiB + off);
            LDSM4(kbl, sKloB + off);
            u32 b0h[2] = {kbh[0], kbh[2]}, b1h[2] = {kbh[1], kbh[3]};
            u32 b0l[2] = {kbl[0], kbl[2]}, b1l[2] = {kbl[1], kbl[3]};
            MMA16816(accS[ng * 2], aQh[kt], b0h);
            MMA16816(accS[ng * 2], aQh[kt], b0l);
            MMA16816(accS[ng * 2], aQl[kt], b0h);
            MMA16816(accS[ng * 2 + 1], aQh[kt], b1h);
            MMA16816(accS[ng * 2 + 1], aQh[kt], b1l);
            MMA16816(accS[ng * 2 + 1], aQl[kt], b1h);
        }
    }

    #pragma unroll
    for (int nt = 0; nt < 16; nt++) {
        int c0 = nt * 8 + (lane & 3) * 2;
        int w2 = c0 >> 5, bit = c0 & 31;
        if (!((mA[w2] >> bit) & 1u))       accS[nt][0] = -INFINITY;
        if (!((mA[w2] >> (bit + 1)) & 1u)) accS[nt][1] = -INFINITY;
        if (!((mB[w2] >> bit) & 1u))       accS[nt][2] = -INFINITY;
        if (!((mB[w2] >> (bit + 1)) & 1u)) accS[nt][3] = -INFINITY;
    }

    float mxA = -INFINITY, mxB = -INFINITY;
    #pragma unroll
    for (int nt = 0; nt < 16; nt++) {
        mxA = fmaxf(mxA, fmaxf(accS[nt][0], accS[nt][1]));
        mxB = fmaxf(mxB, fmaxf(accS[nt][2], accS[nt][3]));
    }
    mxA = fmaxf(mxA, __shfl_xor_sync(0xffffffffu, mxA, 1));
    mxA = fmaxf(mxA, __shfl_xor_sync(0xffffffffu, mxA, 2));
    mxB = fmaxf(mxB, __shfl_xor_sync(0xffffffffu, mxB, 1));
    mxB = fmaxf(mxB, __shfl_xor_sync(0xffffffffu, mxB, 2));

    float sA = 0.0f, sB = 0.0f;
    #pragma unroll
    for (int nt = 0; nt < 16; nt++) {
        accS[nt][0] = exp2f(accS[nt][0] - mxA);
        accS[nt][1] = exp2f(accS[nt][1] - mxA);
        accS[nt][2] = exp2f(accS[nt][2] - mxB);
        accS[nt][3] = exp2f(accS[nt][3] - mxB);
        sA += accS[nt][0] + accS[nt][1];
        sB += accS[nt][2] + accS[nt][3];
    }
    sA += __shfl_xor_sync(0xffffffffu, sA, 1);
    sA += __shfl_xor_sync(0xffffffffu, sA, 2);
    sB += __shfl_xor_sync(0xffffffffu, sB, 1);
    sB += __shfl_xor_sync(0xffffffffu, sB, 2);
    float invA = 1.0f / sA, invB = 1.0f / sB;

    float accO[4][4];
    #pragma unroll
    for (int nt = 0; nt < 4; nt++)
        #pragma unroll
        for (int i = 0; i < 4; i++) accO[nt][i] = 0.0f;

    #pragma unroll
    for (int kt = 0; kt < 8; kt++) {
        u32 ph[4], plo[4];
        packP(accS[2 * kt][0],     accS[2 * kt][1],     ph[0], plo[0]);
        packP(accS[2 * kt][2],     accS[2 * kt][3],     ph[1], plo[1]);
        packP(accS[2 * kt + 1][0], accS[2 * kt + 1][1], ph[2], plo[2]);
        packP(accS[2 * kt + 1][2], accS[2 * kt + 1][3], ph[3], plo[3]);
        #pragma unroll
        for (int n16 = 0; n16 < 2; n16++) {
            u32 vbh[4], vbl[4];
            int krow = kt * 16 + r + ((g & 1) << 3);
            int ncol = n16 * 16 + ((g >> 1) << 3);
            u32 off = (u32)(krow * 40 + ncol) * 2;
            LDSM4T(vbh, sVhiB + off);
            LDSM4T(vbl, sVloB + off);
            MMA16816(accO[n16 * 2], ph, (&vbh[0]));
            MMA16816(accO[n16 * 2], ph, (&vbl[0]));
            MMA16816(accO[n16 * 2], plo, (&vbh[0]));
            MMA16816(accO[n16 * 2 + 1], ph, (&vbh[2]));
            MMA16816(accO[n16 * 2 + 1], ph, (&vbl[2]));
            MMA16816(accO[n16 * 2 + 1], plo, (&vbh[2]));
        }
    }

    #pragma unroll
    for (int nt = 0; nt < 4; nt++) {
        int c0 = nt * 8 + (lane & 3) * 2;
        int oA = (b * 128 + rA) * 256 + h * 32 + c0;
        int oB = (b * 128 + rB) * 256 + h * 32 + c0;
        u32 hi, lo;
        packP(accO[nt][0] * invA, accO[nt][1] * invA, hi, lo);
        *(u32*)&g_aohi[oA] = hi; *(u32*)&g_aolo[oA] = lo;
        packP(accO[nt][2] * invB, accO[nt][3] * invB, hi, lo);
        *(u32*)&g_aohi[oB] = hi; *(u32*)&g_aolo[oB] = lo;
    }
}

// ---------------- launch helpers ----------------------------------------------
template <typename K, typename... Args>
static void launchPDL(K kernel, int grid, int smem, Args... args)
{
    cudaLaunchConfig_t cfg = {};
    cfg.gridDim = dim3(grid, 1, 1);
    cfg.blockDim = dim3(256, 1, 1);
    cfg.dynamicSmemBytes = (size_t)smem;
    cfg.stream = 0;
    cudaLaunchAttribute at[1];
    at[0].id = cudaLaunchAttributeProgrammaticStreamSerialization;
    at[0].val.programmaticStreamSerializationAllowed = 1;
    cfg.attrs = at;
    cfg.numAttrs = 1;
    cudaLaunchKernelEx(&cfg, kernel, args...);
}

// ---------------- launch ------------------------------------------------------
extern "C" void kernel_launch(void* const* d_in, const int* in_sizes, int n_in,
                              void* d_out, int out_size)
{
    const float* x        = (const float*)d_in[0];
    const float* gumbel_u = (const float*)d_in[1];
    const float* memory_w = (const float*)d_in[2];
    const float* fc_out_w = (const float*)d_in[3];
    const float* fc_out_b = (const float*)d_in[4];
    const float* fc_cat_w = (const float*)d_in[5];
    const float* fc_cat_b = (const float*)d_in[6];
    const float* wq       = (const float*)d_in[7];
    const float* bq       = (const float*)d_in[8];
    const float* wk       = (const float*)d_in[9];
    const float* bk       = (const float*)d_in[10];
    const float* wv       = (const float*)d_in[11];
    const float* bv       = (const float*)d_in[12];
    const float* out_w    = (const float*)d_in[13];
    const float* out_b    = (const float*)d_in[14];
    const float* mlp_w1   = (const float*)d_in[15];
    const float* mlp_b1   = (const float*)d_in[16];
    const float* mlp_w2   = (const float*)d_in[17];
    const float* mlp_b2   = (const float*)d_in[18];

    float *fA, *fB, *cb;
    cudaGetSymbolAddress((void**)&fA, g_fA);
    cudaGetSymbolAddress((void**)&fB, g_fB);
    cudaGetSymbolAddress((void**)&cb, g_cb);
    bf16 *cwhi, *cwlo, *h1hi, *h1lo, *qkvhi, *qkvlo, *aohi, *aolo;
    cudaGetSymbolAddress((void**)&cwhi, g_cwhi);
    cudaGetSymbolAddress((void**)&cwlo, g_cwlo);
    cudaGetSymbolAddress((void**)&h1hi, g_h1hi);
    cudaGetSymbolAddress((void**)&h1lo, g_h1lo);
    cudaGetSymbolAddress((void**)&qkvhi, g_qkvhi);
    cudaGetSymbolAddress((void**)&qkvlo, g_qkvlo);
    cudaGetSymbolAddress((void**)&aohi, g_aohi);
    cudaGetSymbolAddress((void**)&aolo, g_aolo);

    static bool attrSet = false;
    if (!attrSet) {
        cudaFuncSetAttribute(k_attn, cudaFuncAttributeMaxDynamicSharedMemorySize, ATTN_SMEM);
        cudaFuncSetAttribute(k_g64_ff, cudaFuncAttributeMaxDynamicSharedMemorySize, GEMM64_SMEM);
        cudaFuncSetAttribute(k_g64_pp_ca, cudaFuncAttributeMaxDynamicSharedMemorySize, GEMM64_SMEM);
        cudaFuncSetAttribute(k_g64_pf_ca, cudaFuncAttributeMaxDynamicSharedMemorySize, GEMM64_SMEM);
        attrSet = true;
    }

    ConnArgs CA = { fc_out_b, fc_cat_w, fc_cat_b, gumbel_u,
                    mlp_b2, wq, wk, wv, bq, bk, bv };

    // L1: fA(64) + fB(64) + mlp1(256) + compose(3x16) + bias(3) = 435 blocks
    {
        Job6 J = {};
        J.Af[0] = memory_w; J.Wf[0] = fc_out_w;
        J.Cf[0] = fA; J.scale[0] = 1.0f; J.gather[0] = 1; J.end[0] = 64;
        J.Af[1] = memory_w; J.Wf[1] = fc_out_w + 65536;
        J.Cf[1] = fB; J.scale[1] = 1.0f; J.gather[1] = 1; J.end[1] = 128;
        J.Af[2] = x; J.Wf[2] = mlp_w1; J.bias[2] = mlp_b1;
        J.Chi[2] = h1hi; J.Clo[2] = h1lo;
        J.scale[2] = 1.0f; J.act[2] = 1; J.storeMode[2] = 1; J.end[2] = 384;
        const float* wz[3] = { wq, wk, wv };
        for (int z = 0; z < 3; z++) {
            int ji = 3 + z;
            J.Af[ji] = mlp_w2; J.Wf[ji] = wz[z];
            J.Chi[ji] = cwhi + z * 65536; J.Clo[ji] = cwlo + z * 65536;
            J.scale[ji] = 1.0f; J.storeMode[ji] = 1; J.end[ji] = 384 + (z + 1) * 16;
        }
        J.totTiles = 432; J.nconn = 0;
        k_g64_ff<<<435, 256, GEMM64_SMEM>>>(J, CA);
    }

    // L2: QKV (3 x 256 tiles, cp.async) + conn(128) = 896 blocks  [PDL]
    {
        Job6 J = {};
        // fold log2(e) into Q scale so softmax uses exp2f
        const float scaleQ = 0.17677669529663687f * 1.4426950408889634f;
        for (int z = 0; z < 3; z++) {
            J.Ahi[z] = h1hi; J.Alo[z] = h1lo;
            J.Whi[z] = cwhi + z * 65536; J.Wlo[z] = cwlo + z * 65536;
            J.bias[z] = cb + z * 256;
            J.Chi[z] = qkvhi + z * 1048576; J.Clo[z] = qkvlo + z * 1048576;
            J.scale[z] = (z == 0) ? scaleQ : 1.0f;
            J.storeMode[z] = 2;
            J.end[z] = (z + 1) * 256;
        }
        J.end[3] = J.end[4] = J.end[5] = 768;
        J.totTiles = 768; J.nconn = 128;
        launchPDL(k_g64_pp_ca, 896, GEMM64_SMEM, J, CA);
    }

    // L3: attention (256 CTAs)  [PDL]
    launchPDL(k_attn, 256, ATTN_SMEM);

    // L4: output projection -> d_out (256 tiles, hybrid cp.async)  [PDL]
    {
        Job6 J = {};
        J.Ahi[0] = aohi; J.Alo[0] = aolo; J.Wf[0] = out_w;
        J.bias[0] = out_b; J.Cf[0] = (float*)d_out;
        J.scale[0] = 1.0f; J.end[0] = 256;
        J.end[1] = J.end[2] = J.end[3] = J.end[4] = J.end[5] = 256;
        J.totTiles = 256; J.nconn = 0;
        launchPDL(k_g64_pf_ca, 256, GEMM64_SMEM, J, CA);
    }
}